// round 7
// baseline (speedup 1.0000x reference)
#include <cuda_runtime.h>
#include <cuda_bf16.h>
#include <math.h>
#include <stdint.h>

#define S_TOT 8196
#define L_PAT 8192
#define H_NUM 8
#define HD 64
#define NUM_CLS 4
#define WIN 32
#define WLEN 65
#define CTX 69
#define GK 512

// scratch
__device__ float g_qkv[3ull * H_NUM * S_TOT * HD];
__device__ float g_attn[(size_t)S_TOT * 512];
__device__ float g_clsp[32 * 8 * 66];
__device__ __nv_bfloat16 g_xh[(size_t)S_TOT * GK];
__device__ __nv_bfloat16 g_xl[(size_t)S_TOT * GK];
__device__ __nv_bfloat16 g_wqh[1536 * GK];
__device__ __nv_bfloat16 g_wql[1536 * GK];
__device__ __nv_bfloat16 g_woh[512 * GK];
__device__ __nv_bfloat16 g_wol[512 * GK];
__device__ __nv_bfloat16 g_ah[(size_t)S_TOT * GK];
__device__ __nv_bfloat16 g_al[(size_t)S_TOT * GK];

__constant__ float c_ftbl[16] = {
    1.0f, 0.5623413252f, 0.3162277660f, 0.1778279410f,
    0.1f, 0.05623413252f, 0.03162277660f, 0.01778279410f,
    0.01f, 0.005623413252f, 0.003162277660f, 0.001778279410f,
    0.001f, 0.0005623413252f, 0.0003162277660f, 0.0001778279410f
};

extern __shared__ char dynsm[];

__device__ __forceinline__ uint32_t smem_u32(const void* p) {
    uint32_t a;
    asm("{ .reg .u64 t; cvta.to.shared.u64 t, %1; cvt.u32.u64 %0, t; }" : "=r"(a) : "l"(p));
    return a;
}
__device__ __forceinline__ void ldm_x4(uint32_t* r, uint32_t addr) {
    asm volatile("ldmatrix.sync.aligned.m8n8.x4.shared.b16 {%0,%1,%2,%3}, [%4];"
                 : "=r"(r[0]), "=r"(r[1]), "=r"(r[2]), "=r"(r[3]) : "r"(addr));
}
__device__ __forceinline__ void mma16816(float* c, const uint32_t* a, uint32_t b0, uint32_t b1) {
    asm volatile("mma.sync.aligned.m16n8k16.row.col.f32.bf16.bf16.f32 "
                 "{%0,%1,%2,%3}, {%4,%5,%6,%7}, {%8,%9}, {%0,%1,%2,%3};"
                 : "+f"(c[0]), "+f"(c[1]), "+f"(c[2]), "+f"(c[3])
                 : "r"(a[0]), "r"(a[1]), "r"(a[2]), "r"(a[3]), "r"(b0), "r"(b1));
}
__device__ __forceinline__ void cp16(uint32_t dst, const void* src, int sz) {
    asm volatile("cp.async.cg.shared.global [%0], [%1], 16, %2;"
                 :: "r"(dst), "l"(src), "r"(sz));
}
#define CP_COMMIT() asm volatile("cp.async.commit_group;" ::: "memory")
#define CP_WAIT1()  asm volatile("cp.async.wait_group 1;" ::: "memory")

// fast exp on FMA pipe (x <= 0 domain)
__device__ __forceinline__ float fexp(float x) {
    x = fmaxf(x, -80.0f);
    float z = fmaf(x, 1.442695041f, 12582912.0f);
    float n = z - 12582912.0f;
    float f = fmaf(x, 1.442695041f, -n);
    float r = 1.3333558e-3f;
    r = fmaf(r, f, 9.6181291e-3f);
    r = fmaf(r, f, 5.5504109e-2f);
    r = fmaf(r, f, 2.4022651e-1f);
    r = fmaf(r, f, 6.9314718e-1f);
    r = fmaf(r, f, 1.0f);
    return r * __int_as_float(((int)n + 127) << 23);
}

// ---------------------------------------------------------------------------
// split: fp32 -> (hi, lo) bf16, round-to-nearest
// ---------------------------------------------------------------------------
__global__ void split_kernel(const float* __restrict__ src,
                             __nv_bfloat16* __restrict__ hi,
                             __nv_bfloat16* __restrict__ lo, int n4) {
    int i = blockIdx.x * 256 + threadIdx.x;
    if (i >= n4) return;
    float4 v = *(const float4*)(src + (size_t)i * 4);
    __nv_bfloat16 h0 = __float2bfloat16(v.x), h1 = __float2bfloat16(v.y);
    __nv_bfloat16 h2 = __float2bfloat16(v.z), h3 = __float2bfloat16(v.w);
    __nv_bfloat16 l0 = __float2bfloat16(v.x - __bfloat162float(h0));
    __nv_bfloat16 l1 = __float2bfloat16(v.y - __bfloat162float(h1));
    __nv_bfloat16 l2 = __float2bfloat16(v.z - __bfloat162float(h2));
    __nv_bfloat16 l3 = __float2bfloat16(v.w - __bfloat162float(h3));
    __nv_bfloat162* hp = (__nv_bfloat162*)(hi + (size_t)i * 4);
    __nv_bfloat162* lp = (__nv_bfloat162*)(lo + (size_t)i * 4);
    hp[0] = __nv_bfloat162(h0, h1); hp[1] = __nv_bfloat162(h2, h3);
    lp[0] = __nv_bfloat162(l0, l1); lp[1] = __nv_bfloat162(l2, l3);
}

// ---------------------------------------------------------------------------
// bf16x3 mma.sync GEMM, cp.async 3-stage pipeline.
// 512 threads (16 warps 4x4), CTA tile 128x128, warp tile 32x32, k-chunk 64.
// ---------------------------------------------------------------------------
#define SMS 72
#define TILE_B (128 * SMS * 2)          // 18432 B per operand tile
#define STAGE_B (4 * TILE_B)            // 73728 B
#define GEMM_SMEM (3 * STAGE_B)         // 221184 B

template<int MODE>
__launch_bounds__(512)
__global__ void gemm_bf16x3(const __nv_bfloat16* __restrict__ Ah,
                            const __nv_bfloat16* __restrict__ Al,
                            const __nv_bfloat16* __restrict__ Bh,
                            const __nv_bfloat16* __restrict__ Bl,
                            const float* __restrict__ bias,
                            float* __restrict__ C, int M, int Ntot) {
    const int tid = threadIdx.x;
    const int wid = tid >> 5;
    const int lane = tid & 31;
    const int wm = (wid >> 2) * 32;
    const int wn = (wid & 3) * 32;
    const int bm = blockIdx.y * 128;
    const int bn = blockIdx.x * 128;

    float c[2][4][4];
#pragma unroll
    for (int i = 0; i < 2; i++)
#pragma unroll
        for (int j = 0; j < 4; j++)
#pragma unroll
            for (int r = 0; r < 4; r++) c[i][j][r] = 0.f;

    const uint32_t smb = smem_u32(dynsm);
    const int lrow = lane & 15;
    const int lcol = (lane >> 4) * 8;

    auto cp_chunk = [&](int ch, int st) {
        uint32_t sb = smb + st * STAGE_B;
#pragma unroll
        for (int it = 0; it < 8; it++) {
            int idx = tid + it * 512;
            int tile = idx >> 10;
            int slot = idx & 1023;
            int row = slot >> 3;
            int c16 = slot & 7;
            uint32_t dst = sb + tile * TILE_B + row * (SMS * 2) + c16 * 16;
            if (tile == 0) {
                int gr = bm + row;
                cp16(dst, Ah + (size_t)gr * GK + ch * 64 + c16 * 8, gr < M ? 16 : 0);
            } else if (tile == 1) {
                int gr = bm + row;
                cp16(dst, Al + (size_t)gr * GK + ch * 64 + c16 * 8, gr < M ? 16 : 0);
            } else if (tile == 2) {
                cp16(dst, Bh + (size_t)(bn + row) * GK + ch * 64 + c16 * 8, 16);
            } else {
                cp16(dst, Bl + (size_t)(bn + row) * GK + ch * 64 + c16 * 8, 16);
            }
        }
        CP_COMMIT();
    };

    cp_chunk(0, 0);
    cp_chunk(1, 1);

    for (int ch = 0; ch < GK / 64; ch++) {
        int st = ch % 3;
        CP_WAIT1();
        __syncthreads();
        if (ch + 2 < GK / 64) cp_chunk(ch + 2, (ch + 2) % 3);

        uint32_t a_h = smb + st * STAGE_B;
        uint32_t a_l = a_h + TILE_B;
        uint32_t b_h = a_h + 2 * TILE_B;
        uint32_t b_l = a_h + 3 * TILE_B;

#pragma unroll
        for (int kk = 0; kk < 4; kk++) {
            uint32_t afh[2][4], afl[2][4], bfh[2][4], bfl[2][4];
#pragma unroll
            for (int mt = 0; mt < 2; mt++) {
                uint32_t off = ((wm + mt * 16 + lrow) * SMS + kk * 16 + lcol) * 2;
                ldm_x4(afh[mt], a_h + off);
                ldm_x4(afl[mt], a_l + off);
            }
#pragma unroll
            for (int g = 0; g < 2; g++) {
                uint32_t off = ((wn + g * 16 + lrow) * SMS + kk * 16 + lcol) * 2;
                ldm_x4(bfh[g], b_h + off);
                ldm_x4(bfl[g], b_l + off);
            }
#pragma unroll
            for (int mt = 0; mt < 2; mt++) {
#pragma unroll
                for (int nt = 0; nt < 4; nt++) {
                    int g = nt >> 1, s = nt & 1;
                    mma16816(c[mt][nt], afh[mt], bfh[g][s], bfh[g][s + 2]);
                    mma16816(c[mt][nt], afh[mt], bfl[g][s], bfl[g][s + 2]);
                    mma16816(c[mt][nt], afl[mt], bfh[g][s], bfh[g][s + 2]);
                }
            }
        }
    }

    const int gid = lane >> 2;
    const int tig = lane & 3;
#pragma unroll
    for (int mt = 0; mt < 2; mt++) {
#pragma unroll
        for (int nt = 0; nt < 4; nt++) {
            int n = bn + wn + nt * 8 + tig * 2;
            float bx = bias[n], by = bias[n + 1];
            int m0 = bm + wm + mt * 16 + gid;
#pragma unroll
            for (int half = 0; half < 2; half++) {
                int m = m0 + half * 8;
                if (m >= M) continue;
                float vx = c[mt][nt][half * 2 + 0] + bx;
                float vy = c[mt][nt][half * 2 + 1] + by;
                if (MODE == 0) {
                    *(float2*)&C[(size_t)m * Ntot + n] = make_float2(vx, vy);
                } else {
                    int sel = n >> 9, h = (n >> 6) & 7, d = n & 63;
                    *(float2*)&g_qkv[(((size_t)(sel * 8 + h) * S_TOT) + m) * 64 + d] =
                        make_float2(vx, vy);
                }
            }
        }
    }
}

// ---------------------------------------------------------------------------
// RoPE2D: block = 8 tokens, thread = (token, pair); loops over h.
// ---------------------------------------------------------------------------
__launch_bounds__(256)
__global__ void rope_kernel(const float* __restrict__ coords) {
    int tid = threadIdx.x;
    int t = tid >> 5, p = tid & 31;
    int l = blockIdx.x * 8 + t;
    float cx = coords[2 * l + 0];
    float cy = coords[2 * l + 1];
    float freq = c_ftbl[p & 15];
    float coord = ((p < 16) ? cx : cy) * 1e-5f;
    float s, c;
    __sincosf(coord * freq, &s, &c);

#pragma unroll
    for (int h = 0; h < 8; h++) {
        size_t bq = ((size_t)h * S_TOT + NUM_CLS + l) * 64 + 2 * p;
        size_t bk = ((size_t)(8 + h) * S_TOT + NUM_CLS + l) * 64 + 2 * p;
        float2 q = *(float2*)&g_qkv[bq];
        *(float2*)&g_qkv[bq] = make_float2(q.x * c - q.y * s, q.y * c + q.x * s);
        float2 k = *(float2*)&g_qkv[bk];
        *(float2*)&g_qkv[bk] = make_float2(k.x * c - k.y * s, k.y * c + k.x * s);
    }
}

// ---------------------------------------------------------------------------
// CLS attention split-K
// ---------------------------------------------------------------------------
#define CCHUNK 1025

__launch_bounds__(256)
__global__ void cls_part_kernel() {
    __shared__ float qs[64];
    __shared__ float sc[CCHUNK];
    __shared__ float red[8];
    __shared__ float osum[8][64];

    int hc = blockIdx.x;
    int h = hc >> 2, ci = hc & 3;
    int chunk = blockIdx.y;
    int k0 = chunk * CCHUNK;
    int k1 = min(S_TOT, k0 + CCHUNK);
    int nk = k1 - k0;
    int tid = threadIdx.x;
    int lane = tid & 31, w = tid >> 5;

    const float* Q = &g_qkv[(((size_t)h * S_TOT) + ci) * 64];
    const float* Kb = &g_qkv[(size_t)(8 + h) * S_TOT * 64];
    const float* Vb = &g_qkv[(size_t)(16 + h) * S_TOT * 64];

    if (tid < 64) qs[tid] = Q[tid];
    __syncthreads();

    float lmax = -INFINITY;
    for (int s = tid; s < nk; s += 256) {
        const float4* kr = (const float4*)(Kb + (size_t)(k0 + s) * 64);
        float a = 0.f;
#pragma unroll
        for (int i = 0; i < 16; i++) {
            float4 kv = kr[i];
            float4 qv = *(float4*)&qs[i * 4];
            a += kv.x * qv.x + kv.y * qv.y + kv.z * qv.z + kv.w * qv.w;
        }
        a *= 0.125f;
        sc[s] = a;
        lmax = fmaxf(lmax, a);
    }
#pragma unroll
    for (int o = 16; o > 0; o >>= 1) lmax = fmaxf(lmax, __shfl_xor_sync(0xffffffffu, lmax, o));
    if (lane == 0) red[w] = lmax;
    __syncthreads();
    float gmax = red[0];
#pragma unroll
    for (int i = 1; i < 8; i++) gmax = fmaxf(gmax, red[i]);
    __syncthreads();

    float lsum = 0.f;
    for (int s = tid; s < nk; s += 256) {
        float p = __expf(sc[s] - gmax);
        sc[s] = p;
        lsum += p;
    }
#pragma unroll
    for (int o = 16; o > 0; o >>= 1) lsum += __shfl_xor_sync(0xffffffffu, lsum, o);
    if (lane == 0) red[w] = lsum;
    __syncthreads();
    float gsum = 0.f;
#pragma unroll
    for (int i = 0; i < 8; i++) gsum += red[i];

    float acc[64];
#pragma unroll
    for (int d = 0; d < 64; d++) acc[d] = 0.f;
    for (int s = tid; s < nk; s += 256) {
        float p = sc[s];
        const float4* vr = (const float4*)(Vb + (size_t)(k0 + s) * 64);
#pragma unroll
        for (int i = 0; i < 16; i++) {
            float4 vv = vr[i];
            acc[i * 4 + 0] = fmaf(p, vv.x, acc[i * 4 + 0]);
            acc[i * 4 + 1] = fmaf(p, vv.y, acc[i * 4 + 1]);
            acc[i * 4 + 2] = fmaf(p, vv.z, acc[i * 4 + 2]);
            acc[i * 4 + 3] = fmaf(p, vv.w, acc[i * 4 + 3]);
        }
    }
#pragma unroll
    for (int d = 0; d < 64; d++) {
        float v = acc[d];
#pragma unroll
        for (int o = 16; o > 0; o >>= 1) v += __shfl_down_sync(0xffffffffu, v, o);
        if (lane == 0) osum[w][d] = v;
    }
    __syncthreads();

    float* dst = &g_clsp[((size_t)hc * 8 + chunk) * 66];
    if (tid == 0) { dst[0] = gmax; dst[1] = gsum; }
    if (tid < 64) {
        float v = 0.f;
#pragma unroll
        for (int i = 0; i < 8; i++) v += osum[i][tid];
        dst[2 + tid] = v;
    }
}

__global__ void cls_combine_kernel() {
    int hc = blockIdx.x;
    int h = hc >> 2, ci = hc & 3;
    int d = threadIdx.x;
    const float* base = &g_clsp[(size_t)hc * 8 * 66];
    float M = -INFINITY;
#pragma unroll
    for (int c = 0; c < 8; c++) M = fmaxf(M, base[c * 66]);
    float S = 0.f, A = 0.f;
#pragma unroll
    for (int c = 0; c < 8; c++) {
        float w = __expf(base[c * 66] - M);
        S = fmaf(base[c * 66 + 1], w, S);
        A = fmaf(base[c * 66 + 2 + d], w, A);
    }
    g_attn[(size_t)ci * 512 + h * 64 + d] = A / S;
}

// ---------------------------------------------------------------------------
// Patch attention (register-blocked, FMA-pipe exp)
// ---------------------------------------------------------------------------
#define KSS 68
#define PATCH_SMEM ((128*KSS + 128*KSS + 256 + 256 + 64*72) * 4)

__launch_bounds__(256)
__global__ void patch_attn_kernel() {
    float* sm = (float*)dynsm;
    float* ks = sm;
    float* vs = ks + 128 * KSS;
    float* kc = vs + 128 * KSS;
    float* vc = kc + 256;
    float* sc = vc + 256;

    int h = blockIdx.y;
    int l0 = blockIdx.x * 64;
    int tid = threadIdx.x;

    const float* Qb = &g_qkv[(size_t)h * S_TOT * 64];
    const float* Kb = &g_qkv[(size_t)(8 + h) * S_TOT * 64];
    const float* Vb = &g_qkv[(size_t)(16 + h) * S_TOT * 64];

    for (int i = tid; i < 128 * 16; i += 256) {
        int r = i >> 4, c4 = (i & 15) << 2;
        int kp = l0 - WIN + r;
        float4 kv = make_float4(0.f, 0.f, 0.f, 0.f);
        float4 vv = make_float4(0.f, 0.f, 0.f, 0.f);
        if (kp >= 0 && kp < L_PAT) {
            kv = *(const float4*)&Kb[(size_t)(NUM_CLS + kp) * 64 + c4];
            vv = *(const float4*)&Vb[(size_t)(NUM_CLS + kp) * 64 + c4];
        }
        *(float4*)&ks[r * KSS + c4] = kv;
        *(float4*)&vs[r * KSS + c4] = vv;
    }
    if (tid < 64) {
        int r = tid >> 4, c4 = (tid & 15) << 2;
        *(float4*)&kc[r * 64 + c4] = *(const float4*)&Kb[(size_t)r * 64 + c4];
        *(float4*)&vc[r * 64 + c4] = *(const float4*)&Vb[(size_t)r * 64 + c4];
    }

    const int qg = tid >> 4;
    const int jp = (tid >> 2) & 3;
    const int dc = tid & 3;
    const int qi0 = qg * 4;
    const int dof = dc * 16;

    float qreg[4][16];
#pragma unroll
    for (int qq = 0; qq < 4; qq++)
#pragma unroll
        for (int i = 0; i < 4; i++)
            *(float4*)&qreg[qq][i * 4] =
                *(const float4*)&Qb[(size_t)(NUM_CLS + l0 + qi0 + qq) * 64 + dof + i * 4];
    __syncthreads();

    for (int ri = jp; ri < 72; ri += 4) {
        const float* kr;
        if (ri < 4) kr = &kc[ri * 64 + dof];
        else        kr = &ks[(qi0 + ri - 4) * KSS + dof];
        float kf[16];
#pragma unroll
        for (int i = 0; i < 4; i++) *(float4*)&kf[i * 4] = *(const float4*)&kr[i * 4];
        float acc[4] = {0.f, 0.f, 0.f, 0.f};
#pragma unroll
        for (int dd = 0; dd < 16; dd++) {
            float kv = kf[dd];
            acc[0] = fmaf(qreg[0][dd], kv, acc[0]);
            acc[1] = fmaf(qreg[1][dd], kv, acc[1]);
            acc[2] = fmaf(qreg[2][dd], kv, acc[2]);
            acc[3] = fmaf(qreg[3][dd], kv, acc[3]);
        }
#pragma unroll
        for (int o = 1; o <= 2; o <<= 1) {
            acc[0] += __shfl_xor_sync(0xffffffffu, acc[0], o);
            acc[1] += __shfl_xor_sync(0xffffffffu, acc[1], o);
            acc[2] += __shfl_xor_sync(0xffffffffu, acc[2], o);
            acc[3] += __shfl_xor_sync(0xffffffffu, acc[3], o);
        }
        if (dc == 0) {
            if (ri < 4) {
#pragma unroll
                for (int qq = 0; qq < 4; qq++)
                    sc[(qi0 + qq) * 72 + ri] = acc[qq] * 0.125f;
            } else {
                int rw = ri - 4;
                int pos = l0 + qi0 + rw - WIN;
                bool okpos = (pos >= 0) && (pos < L_PAT);
#pragma unroll
                for (int qq = 0; qq < 4; qq++) {
                    int w = rw - qq;
                    if (w >= 0 && w <= 64)
                        sc[(qi0 + qq) * 72 + 4 + w] = okpos ? acc[qq] * 0.125f : -1e30f;
                }
            }
        }
    }
    __syncthreads();

    {
        int row = tid >> 2, sub = tid & 3;
        float* srow = &sc[row * 72];
        float m = -INFINITY;
        for (int j = sub; j < CTX; j += 4) m = fmaxf(m, srow[j]);
        m = fmaxf(m, __shfl_xor_sync(0xffffffffu, m, 1));
        m = fmaxf(m, __shfl_xor_sync(0xffffffffu, m, 2));
        float sum = 0.f;
        for (int j = sub; j < CTX; j += 4) {
            float p = fexp(srow[j] - m);
            srow[j] = p;
            sum += p;
        }
        sum += __shfl_xor_sync(0xffffffffu, sum, 1);
        sum += __shfl_xor_sync(0xffffffffu, sum, 2);
        float inv = 1.0f / sum;
        for (int j = sub; j < CTX; j += 4) srow[j] *= inv;
    }
    __syncthreads();

    float oacc[4][16];
#pragma unroll
    for (int qq = 0; qq < 4; qq++)
#pragma unroll
        for (int dd = 0; dd < 16; dd++) oacc[qq][dd] = 0.f;

    for (int ri = jp; ri < 72; ri += 4) {
        const float* vr;
        float p[4];
        if (ri < 4) {
            vr = &vc[ri * 64 + dof];
#pragma unroll
            for (int qq = 0; qq < 4; qq++) p[qq] = sc[(qi0 + qq) * 72 + ri];
        } else {
            int rw = ri - 4;
            vr = &vs[(qi0 + rw) * KSS + dof];
#pragma unroll
            for (int qq = 0; qq < 4; qq++) {
                int w = rw - qq;
                p[qq] = (w >= 0 && w <= 64) ? sc[(qi0 + qq) * 72 + 4 + w] : 0.f;
            }
        }
        float vf[16];
#pragma unroll
        for (int i = 0; i < 4; i++) *(float4*)&vf[i * 4] = *(const float4*)&vr[i * 4];
#pragma unroll
        for (int dd = 0; dd < 16; dd++) {
            float vv = vf[dd];
            oacc[0][dd] = fmaf(p[0], vv, oacc[0][dd]);
            oacc[1][dd] = fmaf(p[1], vv, oacc[1][dd]);
            oacc[2][dd] = fmaf(p[2], vv, oacc[2][dd]);
            oacc[3][dd] = fmaf(p[3], vv, oacc[3][dd]);
        }
    }
#pragma unroll
    for (int o = 4; o <= 8; o <<= 1)
#pragma unroll
        for (int qq = 0; qq < 4; qq++)
#pragma unroll
            for (int dd = 0; dd < 16; dd++)
                oacc[qq][dd] += __shfl_xor_sync(0xffffffffu, oacc[qq][dd], o);

    if (jp == 0) {
#pragma unroll
        for (int qq = 0; qq < 4; qq++)
#pragma unroll
            for (int i = 0; i < 4; i++)
                *(float4*)&g_attn[(size_t)(NUM_CLS + l0 + qi0 + qq) * 512 + h * 64 + dof + i * 4] =
                    *(float4*)&oacc[qq][i * 4];
    }
}

// ---------------------------------------------------------------------------
extern "C" void kernel_launch(void* const* d_in, const int* in_sizes, int n_in,
                              void* d_out, int out_size) {
    const float* x      = (const float*)d_in[0];
    const float* coords = (const float*)d_in[1];
    const float* w_qkv  = (const float*)d_in[2];
    const float* b_qkv  = (const float*)d_in[3];
    const float* w_out  = (const float*)d_in[4];
    const float* b_out  = (const float*)d_in[5];
    float* out = (float*)d_out;

    float* attn_ptr = nullptr;
    cudaGetSymbolAddress((void**)&attn_ptr, g_attn);
    __nv_bfloat16 *xh, *xl, *wqh, *wql, *woh, *wol, *ah, *al;
    cudaGetSymbolAddress((void**)&xh, g_xh);
    cudaGetSymbolAddress((void**)&xl, g_xl);
    cudaGetSymbolAddress((void**)&wqh, g_wqh);
    cudaGetSymbolAddress((void**)&wql, g_wql);
    cudaGetSymbolAddress((void**)&woh, g_woh);
    cudaGetSymbolAddress((void**)&wol, g_wol);
    cudaGetSymbolAddress((void**)&ah, g_ah);
    cudaGetSymbolAddress((void**)&al, g_al);

    cudaFuncSetAttribute(gemm_bf16x3<0>, cudaFuncAttributeMaxDynamicSharedMemorySize, GEMM_SMEM);
    cudaFuncSetAttribute(gemm_bf16x3<1>, cudaFuncAttributeMaxDynamicSharedMemorySize, GEMM_SMEM);
    cudaFuncSetAttribute(patch_attn_kernel, cudaFuncAttributeMaxDynamicSharedMemorySize, PATCH_SMEM);

    // 1. splits
    split_kernel<<<(S_TOT * GK / 4 + 255) / 256, 256>>>(x, xh, xl, S_TOT * GK / 4);
    split_kernel<<<(1536 * GK / 4 + 255) / 256, 256>>>(w_qkv, wqh, wql, 1536 * GK / 4);
    split_kernel<<<(512 * GK / 4 + 255) / 256, 256>>>(w_out, woh, wol, 512 * GK / 4);

    // 2. QKV GEMM -> g_qkv scatter
    {
        dim3 grid(1536 / 128, (S_TOT + 127) / 128);
        gemm_bf16x3<1><<<grid, 512, GEMM_SMEM>>>(xh, xl, wqh, wql, b_qkv, nullptr, S_TOT, 0);
    }
    // 3. RoPE
    rope_kernel<<<L_PAT / 8, 256>>>(coords);
    // 4. CLS attention split-K + combine
    {
        dim3 grid(32, 8);
        cls_part_kernel<<<grid, 256>>>();
        cls_combine_kernel<<<32, 64>>>();
    }
    // 5. Patch attention
    {
        dim3 grid(L_PAT / 64, H_NUM);
        patch_attn_kernel<<<grid, 256, PATCH_SMEM>>>();
    }
    // 6. split attention output
    split_kernel<<<(S_TOT * GK / 4 + 255) / 256, 256>>>(attn_ptr, ah, al, S_TOT * GK / 4);
    // 7. out projection
    {
        dim3 grid(512 / 128, (S_TOT + 127) / 128);
        gemm_bf16x3<0><<<grid, 512, GEMM_SMEM>>>(ah, al, woh, wol, b_out, out, S_TOT, 512);
    }
}

// round 9
// speedup vs baseline: 1.2500x; 1.2500x over previous
#include <cuda_runtime.h>
#include <cuda_fp16.h>
#include <cuda_bf16.h>
#include <math.h>
#include <stdint.h>

#define S_TOT 8196
#define L_PAT 8192
#define H_NUM 8
#define HD 64
#define NUM_CLS 4
#define WIN 32
#define WLEN 65
#define CTX 69
#define GK 512

// scratch
__device__ float g_qkv[3ull * H_NUM * S_TOT * HD];
__device__ float g_attn[(size_t)S_TOT * 512];
__device__ float g_clsp[32 * 8 * 66];
__device__ __half g_wqh[1536 * GK];
__device__ __half g_wql[1536 * GK];
__device__ __half g_woh[512 * GK];
__device__ __half g_wol[512 * GK];

__constant__ float c_ftbl[16] = {
    1.0f, 0.5623413252f, 0.3162277660f, 0.1778279410f,
    0.1f, 0.05623413252f, 0.03162277660f, 0.01778279410f,
    0.01f, 0.005623413252f, 0.003162277660f, 0.001778279410f,
    0.001f, 0.0005623413252f, 0.0003162277660f, 0.0001778279410f
};

extern __shared__ char dynsm[];

__device__ __forceinline__ uint32_t smem_u32(const void* p) {
    uint32_t a;
    asm("{ .reg .u64 t; cvta.to.shared.u64 t, %1; cvt.u32.u64 %0, t; }" : "=r"(a) : "l"(p));
    return a;
}
__device__ __forceinline__ void ldm_x4(uint32_t* r, uint32_t addr) {
    asm volatile("ldmatrix.sync.aligned.m8n8.x4.shared.b16 {%0,%1,%2,%3}, [%4];"
                 : "=r"(r[0]), "=r"(r[1]), "=r"(r[2]), "=r"(r[3]) : "r"(addr));
}
__device__ __forceinline__ void mma_h(float* c, const uint32_t* a, uint32_t b0, uint32_t b1) {
    asm volatile("mma.sync.aligned.m16n8k16.row.col.f32.f16.f16.f32 "
                 "{%0,%1,%2,%3}, {%4,%5,%6,%7}, {%8,%9}, {%0,%1,%2,%3};"
                 : "+f"(c[0]), "+f"(c[1]), "+f"(c[2]), "+f"(c[3])
                 : "r"(a[0]), "r"(a[1]), "r"(a[2]), "r"(a[3]), "r"(b0), "r"(b1));
}
__device__ __forceinline__ uint32_t packf16(float a, float b) {
    __half2 t = __floats2half2_rn(a, b);
    return *(uint32_t*)&t;
}
// fast exp on FMA pipe (x <= 0 domain)
__device__ __forceinline__ float fexp(float x) {
    x = fmaxf(x, -80.0f);
    float z = fmaf(x, 1.442695041f, 12582912.0f);
    float n = z - 12582912.0f;
    float f = fmaf(x, 1.442695041f, -n);
    float r = 1.3333558e-3f;
    r = fmaf(r, f, 9.6181291e-3f);
    r = fmaf(r, f, 5.5504109e-2f);
    r = fmaf(r, f, 2.4022651e-1f);
    r = fmaf(r, f, 6.9314718e-1f);
    r = fmaf(r, f, 1.0f);
    return r * __int_as_float(((int)n + 127) << 23);
}

// ---------------------------------------------------------------------------
// weight split: fp32 -> (hi, lo) fp16, round-to-nearest
// ---------------------------------------------------------------------------
__global__ void wsplit_kernel(const float* __restrict__ src,
                              __half* __restrict__ hi,
                              __half* __restrict__ lo, int n4) {
    int i = blockIdx.x * 256 + threadIdx.x;
    if (i >= n4) return;
    float4 v = *(const float4*)(src + (size_t)i * 4);
    __half h0 = __float2half_rn(v.x), h1 = __float2half_rn(v.y);
    __half h2 = __float2half_rn(v.z), h3 = __float2half_rn(v.w);
    __half l0 = __float2half_rn(v.x - __half2float(h0));
    __half l1 = __float2half_rn(v.y - __half2float(h1));
    __half l2 = __float2half_rn(v.z - __half2float(h2));
    __half l3 = __float2half_rn(v.w - __half2float(h3));
    __half2* hp = (__half2*)(hi + (size_t)i * 4);
    __half2* lp = (__half2*)(lo + (size_t)i * 4);
    hp[0] = __half2(h0, h1); hp[1] = __half2(h2, h3);
    lp[0] = __half2(l0, l1); lp[1] = __half2(l2, l3);
}

// ---------------------------------------------------------------------------
// fp16x2 mma.sync GEMM: C = A(fp32->fp16 fused) * (Bh+Bl)^T + bias
// 512 threads (16 warps 4x4), CTA tile 128x128, warp tile 32x32, k-chunk 64,
// double-buffered smem with register prefetch. 2 MMA passes per fragment.
// MODE 0: row-major C.  MODE 1: scatter into g_qkv.
// ---------------------------------------------------------------------------
#define SMS 72
#define TILE_E (128 * SMS)               // fp16 elems per tile
#define STAGE_E (3 * TILE_E)             // A, Bh, Bl
#define TILE_B (TILE_E * 2)
#define STAGE_B (STAGE_E * 2)
#define GEMM_SMEM (2 * STAGE_B)          // 110592 B

template<int MODE>
__launch_bounds__(512)
__global__ void gemm_f16x2(const float* __restrict__ A,
                           const __half* __restrict__ Bh,
                           const __half* __restrict__ Bl,
                           const float* __restrict__ bias,
                           float* __restrict__ C, int M, int Ntot) {
    __half* sm = (__half*)dynsm;

    const int tid = threadIdx.x;
    const int wid = tid >> 5;
    const int lane = tid & 31;
    const int wm = (wid >> 2) * 32;
    const int wn = (wid & 3) * 32;
    const int bm = blockIdx.y * 128;
    const int bn = blockIdx.x * 128;

    float c[2][4][4];
#pragma unroll
    for (int i = 0; i < 2; i++)
#pragma unroll
        for (int j = 0; j < 4; j++)
#pragma unroll
            for (int r = 0; r < 4; r++) c[i][j][r] = 0.f;

    const uint32_t smb = smem_u32(sm);
    const int lrow = lane & 15;
    const int lcol = (lane >> 4) * 8;

    // A slots: 4 x float4 (128x64 fp32 / 512 thr); B slots: 2 x uint4 per tile
    float4 pa[4];
    uint4 pbh[2], pbl[2];
    int alr[4], alc[4], brow[2], bc8[2];
#pragma unroll
    for (int it = 0; it < 4; it++) {
        int idx = tid + it * 512;
        alr[it] = idx >> 4;
        alc[it] = (idx & 15) * 4;
    }
#pragma unroll
    for (int it = 0; it < 2; it++) {
        int idx = tid + it * 512;
        brow[it] = idx >> 3;
        bc8[it] = (idx & 7) * 8;
    }

    auto ldg_stage = [&](int ch) {
#pragma unroll
        for (int it = 0; it < 4; it++) {
            int gr = bm + alr[it];
            pa[it] = make_float4(0.f, 0.f, 0.f, 0.f);
            if (gr < M) pa[it] = *(const float4*)&A[(size_t)gr * GK + ch * 64 + alc[it]];
        }
#pragma unroll
        for (int it = 0; it < 2; it++) {
            size_t off = (size_t)(bn + brow[it]) * GK + ch * 64 + bc8[it];
            pbh[it] = *(const uint4*)(Bh + off);
            pbl[it] = *(const uint4*)(Bl + off);
        }
    };
    auto sts_stage = [&](int st) {
        __half* sA = sm + st * STAGE_E;
        __half* sBh = sA + TILE_E;
        __half* sBl = sA + 2 * TILE_E;
#pragma unroll
        for (int it = 0; it < 4; it++) {
            int off = alr[it] * SMS + alc[it];
            float4 v = pa[it];
            uint2 pk = make_uint2(packf16(v.x, v.y), packf16(v.z, v.w));
            *(uint2*)(sA + off) = pk;
        }
#pragma unroll
        for (int it = 0; it < 2; it++) {
            int off = brow[it] * SMS + bc8[it];
            *(uint4*)(sBh + off) = pbh[it];
            *(uint4*)(sBl + off) = pbl[it];
        }
    };

    ldg_stage(0);
    sts_stage(0);
    __syncthreads();

    for (int ch = 0; ch < GK / 64; ch++) {
        int st = ch & 1;
        if (ch < GK / 64 - 1) ldg_stage(ch + 1);

        uint32_t a_b = smb + st * STAGE_B;
        uint32_t bh_b = a_b + TILE_B;
        uint32_t bl_b = a_b + 2 * TILE_B;

#pragma unroll
        for (int kk = 0; kk < 4; kk++) {
            uint32_t af[2][4], bfh[2][4], bfl[2][4];
#pragma unroll
            for (int mt = 0; mt < 2; mt++) {
                uint32_t off = ((wm + mt * 16 + lrow) * SMS + kk * 16 + lcol) * 2;
                ldm_x4(af[mt], a_b + off);
            }
#pragma unroll
            for (int g = 0; g < 2; g++) {
                uint32_t off = ((wn + g * 16 + lrow) * SMS + kk * 16 + lcol) * 2;
                ldm_x4(bfh[g], bh_b + off);
                ldm_x4(bfl[g], bl_b + off);
            }
#pragma unroll
            for (int mt = 0; mt < 2; mt++) {
#pragma unroll
                for (int nt = 0; nt < 4; nt++) {
                    int g = nt >> 1, s = nt & 1;
                    mma_h(c[mt][nt], af[mt], bfh[g][s], bfh[g][s + 2]);
                    mma_h(c[mt][nt], af[mt], bfl[g][s], bfl[g][s + 2]);
                }
            }
        }
        if (ch < GK / 64 - 1) sts_stage(st ^ 1);
        __syncthreads();
    }

    const int gid = lane >> 2;
    const int tig = lane & 3;
#pragma unroll
    for (int mt = 0; mt < 2; mt++) {
#pragma unroll
        for (int nt = 0; nt < 4; nt++) {
            int n = bn + wn + nt * 8 + tig * 2;
            float bx = bias[n], by = bias[n + 1];
            int m0 = bm + wm + mt * 16 + gid;
#pragma unroll
            for (int half = 0; half < 2; half++) {
                int m = m0 + half * 8;
                if (m >= M) continue;
                float vx = c[mt][nt][half * 2 + 0] + bx;
                float vy = c[mt][nt][half * 2 + 1] + by;
                if (MODE == 0) {
                    *(float2*)&C[(size_t)m * Ntot + n] = make_float2(vx, vy);
                } else {
                    int sel = n >> 9, h = (n >> 6) & 7, d = n & 63;
                    *(float2*)&g_qkv[(((size_t)(sel * 8 + h) * S_TOT) + m) * 64 + d] =
                        make_float2(vx, vy);
                }
            }
        }
    }
}

// ---------------------------------------------------------------------------
// RoPE2D: block = 8 tokens, thread = (token, pair); loops over h.
// ---------------------------------------------------------------------------
__launch_bounds__(256)
__global__ void rope_kernel(const float* __restrict__ coords) {
    int tid = threadIdx.x;
    int t = tid >> 5, p = tid & 31;
    int l = blockIdx.x * 8 + t;
    float cx = coords[2 * l + 0];
    float cy = coords[2 * l + 1];
    float freq = c_ftbl[p & 15];
    float coord = ((p < 16) ? cx : cy) * 1e-5f;
    float s, c;
    __sincosf(coord * freq, &s, &c);

#pragma unroll
    for (int h = 0; h < 8; h++) {
        size_t bq = ((size_t)h * S_TOT + NUM_CLS + l) * 64 + 2 * p;
        size_t bk = ((size_t)(8 + h) * S_TOT + NUM_CLS + l) * 64 + 2 * p;
        float2 q = *(float2*)&g_qkv[bq];
        *(float2*)&g_qkv[bq] = make_float2(q.x * c - q.y * s, q.y * c + q.x * s);
        float2 k = *(float2*)&g_qkv[bk];
        *(float2*)&g_qkv[bk] = make_float2(k.x * c - k.y * s, k.y * c + k.x * s);
    }
}

// ---------------------------------------------------------------------------
// CLS attention split-K
// ---------------------------------------------------------------------------
#define CCHUNK 1025

__launch_bounds__(256)
__global__ void cls_part_kernel() {
    __shared__ float qs[64];
    __shared__ float sc[CCHUNK];
    __shared__ float red[8];
    __shared__ float osum[8][64];

    int hc = blockIdx.x;
    int h = hc >> 2, ci = hc & 3;
    int chunk = blockIdx.y;
    int k0 = chunk * CCHUNK;
    int k1 = min(S_TOT, k0 + CCHUNK);
    int nk = k1 - k0;
    int tid = threadIdx.x;
    int lane = tid & 31, w = tid >> 5;

    const float* Q = &g_qkv[(((size_t)h * S_TOT) + ci) * 64];
    const float* Kb = &g_qkv[(size_t)(8 + h) * S_TOT * 64];
    const float* Vb = &g_qkv[(size_t)(16 + h) * S_TOT * 64];

    if (tid < 64) qs[tid] = Q[tid];
    __syncthreads();

    float lmax = -INFINITY;
    for (int s = tid; s < nk; s += 256) {
        const float4* kr = (const float4*)(Kb + (size_t)(k0 + s) * 64);
        float a = 0.f;
#pragma unroll
        for (int i = 0; i < 16; i++) {
            float4 kv = kr[i];
            float4 qv = *(float4*)&qs[i * 4];
            a += kv.x * qv.x + kv.y * qv.y + kv.z * qv.z + kv.w * qv.w;
        }
        a *= 0.125f;
        sc[s] = a;
        lmax = fmaxf(lmax, a);
    }
#pragma unroll
    for (int o = 16; o > 0; o >>= 1) lmax = fmaxf(lmax, __shfl_xor_sync(0xffffffffu, lmax, o));
    if (lane == 0) red[w] = lmax;
    __syncthreads();
    float gmax = red[0];
#pragma unroll
    for (int i = 1; i < 8; i++) gmax = fmaxf(gmax, red[i]);
    __syncthreads();

    float lsum = 0.f;
    for (int s = tid; s < nk; s += 256) {
        float p = __expf(sc[s] - gmax);
        sc[s] = p;
        lsum += p;
    }
#pragma unroll
    for (int o = 16; o > 0; o >>= 1) lsum += __shfl_xor_sync(0xffffffffu, lsum, o);
    if (lane == 0) red[w] = lsum;
    __syncthreads();
    float gsum = 0.f;
#pragma unroll
    for (int i = 0; i < 8; i++) gsum += red[i];

    float acc[64];
#pragma unroll
    for (int d = 0; d < 64; d++) acc[d] = 0.f;
    for (int s = tid; s < nk; s += 256) {
        float p = sc[s];
        const float4* vr = (const float4*)(Vb + (size_t)(k0 + s) * 64);
#pragma unroll
        for (int i = 0; i < 16; i++) {
            float4 vv = vr[i];
            acc[i * 4 + 0] = fmaf(p, vv.x, acc[i * 4 + 0]);
            acc[i * 4 + 1] = fmaf(p, vv.y, acc[i * 4 + 1]);
            acc[i * 4 + 2] = fmaf(p, vv.z, acc[i * 4 + 2]);
            acc[i * 4 + 3] = fmaf(p, vv.w, acc[i * 4 + 3]);
        }
    }
#pragma unroll
    for (int d = 0; d < 64; d++) {
        float v = acc[d];
#pragma unroll
        for (int o = 16; o > 0; o >>= 1) v += __shfl_down_sync(0xffffffffu, v, o);
        if (lane == 0) osum[w][d] = v;
    }
    __syncthreads();

    float* dst = &g_clsp[((size_t)hc * 8 + chunk) * 66];
    if (tid == 0) { dst[0] = gmax; dst[1] = gsum; }
    if (tid < 64) {
        float v = 0.f;
#pragma unroll
        for (int i = 0; i < 8; i++) v += osum[i][tid];
        dst[2 + tid] = v;
    }
}

__global__ void cls_combine_kernel() {
    int hc = blockIdx.x;
    int h = hc >> 2, ci = hc & 3;
    int d = threadIdx.x;
    const float* base = &g_clsp[(size_t)hc * 8 * 66];
    float M = -INFINITY;
#pragma unroll
    for (int c = 0; c < 8; c++) M = fmaxf(M, base[c * 66]);
    float S = 0.f, A = 0.f;
#pragma unroll
    for (int c = 0; c < 8; c++) {
        float w = __expf(base[c * 66] - M);
        S = fmaf(base[c * 66 + 1], w, S);
        A = fmaf(base[c * 66 + 2 + d], w, A);
    }
    g_attn[(size_t)ci * 512 + h * 64 + d] = A / S;
}

// ---------------------------------------------------------------------------
// Patch attention (register-blocked, FMA-pipe exp)
// ---------------------------------------------------------------------------
#define KSS 68
#define PATCH_SMEM ((128*KSS + 128*KSS + 256 + 256 + 64*72) * 4)

__launch_bounds__(256)
__global__ void patch_attn_kernel() {
    float* sm = (float*)dynsm;
    float* ks = sm;
    float* vs = ks + 128 * KSS;
    float* kc = vs + 128 * KSS;
    float* vc = kc + 256;
    float* sc = vc + 256;

    int h = blockIdx.y;
    int l0 = blockIdx.x * 64;
    int tid = threadIdx.x;

    const float* Qb = &g_qkv[(size_t)h * S_TOT * 64];
    const float* Kb = &g_qkv[(size_t)(8 + h) * S_TOT * 64];
    const float* Vb = &g_qkv[(size_t)(16 + h) * S_TOT * 64];

    for (int i = tid; i < 128 * 16; i += 256) {
        int r = i >> 4, c4 = (i & 15) << 2;
        int kp = l0 - WIN + r;
        float4 kv = make_float4(0.f, 0.f, 0.f, 0.f);
        float4 vv = make_float4(0.f, 0.f, 0.f, 0.f);
        if (kp >= 0 && kp < L_PAT) {
            kv = *(const float4*)&Kb[(size_t)(NUM_CLS + kp) * 64 + c4];
            vv = *(const float4*)&Vb[(size_t)(NUM_CLS + kp) * 64 + c4];
        }
        *(float4*)&ks[r * KSS + c4] = kv;
        *(float4*)&vs[r * KSS + c4] = vv;
    }
    if (tid < 64) {
        int r = tid >> 4, c4 = (tid & 15) << 2;
        *(float4*)&kc[r * 64 + c4] = *(const float4*)&Kb[(size_t)r * 64 + c4];
        *(float4*)&vc[r * 64 + c4] = *(const float4*)&Vb[(size_t)r * 64 + c4];
    }

    const int qg = tid >> 4;
    const int jp = (tid >> 2) & 3;
    const int dc = tid & 3;
    const int qi0 = qg * 4;
    const int dof = dc * 16;

    float qreg[4][16];
#pragma unroll
    for (int qq = 0; qq < 4; qq++)
#pragma unroll
        for (int i = 0; i < 4; i++)
            *(float4*)&qreg[qq][i * 4] =
                *(const float4*)&Qb[(size_t)(NUM_CLS + l0 + qi0 + qq) * 64 + dof + i * 4];
    __syncthreads();

    for (int ri = jp; ri < 72; ri += 4) {
        const float* kr;
        if (ri < 4) kr = &kc[ri * 64 + dof];
        else        kr = &ks[(qi0 + ri - 4) * KSS + dof];
        float kf[16];
#pragma unroll
        for (int i = 0; i < 4; i++) *(float4*)&kf[i * 4] = *(const float4*)&kr[i * 4];
        float acc[4] = {0.f, 0.f, 0.f, 0.f};
#pragma unroll
        for (int dd = 0; dd < 16; dd++) {
            float kv = kf[dd];
            acc[0] = fmaf(qreg[0][dd], kv, acc[0]);
            acc[1] = fmaf(qreg[1][dd], kv, acc[1]);
            acc[2] = fmaf(qreg[2][dd], kv, acc[2]);
            acc[3] = fmaf(qreg[3][dd], kv, acc[3]);
        }
#pragma unroll
        for (int o = 1; o <= 2; o <<= 1) {
            acc[0] += __shfl_xor_sync(0xffffffffu, acc[0], o);
            acc[1] += __shfl_xor_sync(0xffffffffu, acc[1], o);
            acc[2] += __shfl_xor_sync(0xffffffffu, acc[2], o);
            acc[3] += __shfl_xor_sync(0xffffffffu, acc[3], o);
        }
        if (dc == 0) {
            if (ri < 4) {
#pragma unroll
                for (int qq = 0; qq < 4; qq++)
                    sc[(qi0 + qq) * 72 + ri] = acc[qq] * 0.125f;
            } else {
                int rw = ri - 4;
                int pos = l0 + qi0 + rw - WIN;
                bool okpos = (pos >= 0) && (pos < L_PAT);
#pragma unroll
                for (int qq = 0; qq < 4; qq++) {
                    int w = rw - qq;
                    if (w >= 0 && w <= 64)
                        sc[(qi0 + qq) * 72 + 4 + w] = okpos ? acc[qq] * 0.125f : -1e30f;
                }
            }
        }
    }
    __syncthreads();

    {
        int row = tid >> 2, sub = tid & 3;
        float* srow = &sc[row * 72];
        float m = -INFINITY;
        for (int j = sub; j < CTX; j += 4) m = fmaxf(m, srow[j]);
        m = fmaxf(m, __shfl_xor_sync(0xffffffffu, m, 1));
        m = fmaxf(m, __shfl_xor_sync(0xffffffffu, m, 2));
        float sum = 0.f;
        for (int j = sub; j < CTX; j += 4) {
            float p = fexp(srow[j] - m);
            srow[j] = p;
            sum += p;
        }
        sum += __shfl_xor_sync(0xffffffffu, sum, 1);
        sum += __shfl_xor_sync(0xffffffffu, sum, 2);
        float inv = 1.0f / sum;
        for (int j = sub; j < CTX; j += 4) srow[j] *= inv;
    }
    __syncthreads();

    float oacc[4][16];
#pragma unroll
    for (int qq = 0; qq < 4; qq++)
#pragma unroll
        for (int dd = 0; dd < 16; dd++) oacc[qq][dd] = 0.f;

    for (int ri = jp; ri < 72; ri += 4) {
        const float* vr;
        float p[4];
        if (ri < 4) {
            vr = &vc[ri * 64 + dof];
#pragma unroll
            for (int qq = 0; qq < 4; qq++) p[qq] = sc[(qi0 + qq) * 72 + ri];
        } else {
            int rw = ri - 4;
            vr = &vs[(qi0 + rw) * KSS + dof];
#pragma unroll
            for (int qq = 0; qq < 4; qq++) {
                int w = rw - qq;
                p[qq] = (w >= 0 && w <= 64) ? sc[(qi0 + qq) * 72 + 4 + w] : 0.f;
            }
        }
        float vf[16];
#pragma unroll
        for (int i = 0; i < 4; i++) *(float4*)&vf[i * 4] = *(const float4*)&vr[i * 4];
#pragma unroll
        for (int dd = 0; dd < 16; dd++) {
            float vv = vf[dd];
            oacc[0][dd] = fmaf(p[0], vv, oacc[0][dd]);
            oacc[1][dd] = fmaf(p[1], vv, oacc[1][dd]);
            oacc[2][dd] = fmaf(p[2], vv, oacc[2][dd]);
            oacc[3][dd] = fmaf(p[3], vv, oacc[3][dd]);
        }
    }
#pragma unroll
    for (int o = 4; o <= 8; o <<= 1)
#pragma unroll
        for (int qq = 0; qq < 4; qq++)
#pragma unroll
            for (int dd = 0; dd < 16; dd++)
                oacc[qq][dd] += __shfl_xor_sync(0xffffffffu, oacc[qq][dd], o);

    if (jp == 0) {
#pragma unroll
        for (int qq = 0; qq < 4; qq++)
#pragma unroll
            for (int i = 0; i < 4; i++)
                *(float4*)&g_attn[(size_t)(NUM_CLS + l0 + qi0 + qq) * 512 + h * 64 + dof + i * 4] =
                    *(float4*)&oacc[qq][i * 4];
    }
}

// ---------------------------------------------------------------------------
extern "C" void kernel_launch(void* const* d_in, const int* in_sizes, int n_in,
                              void* d_out, int out_size) {
    const float* x      = (const float*)d_in[0];
    const float* coords = (const float*)d_in[1];
    const float* w_qkv  = (const float*)d_in[2];
    const float* b_qkv  = (const float*)d_in[3];
    const float* w_out  = (const float*)d_in[4];
    const float* b_out  = (const float*)d_in[5];
    float* out = (float*)d_out;

    float* attn_ptr = nullptr;
    cudaGetSymbolAddress((void**)&attn_ptr, g_attn);
    __half *wqh, *wql, *woh, *wol;
    cudaGetSymbolAddress((void**)&wqh, g_wqh);
    cudaGetSymbolAddress((void**)&wql, g_wql);
    cudaGetSymbolAddress((void**)&woh, g_woh);
    cudaGetSymbolAddress((void**)&wol, g_wol);

    cudaFuncSetAttribute(gemm_f16x2<0>, cudaFuncAttributeMaxDynamicSharedMemorySize, GEMM_SMEM);
    cudaFuncSetAttribute(gemm_f16x2<1>, cudaFuncAttributeMaxDynamicSharedMemorySize, GEMM_SMEM);
    cudaFuncSetAttribute(patch_attn_kernel, cudaFuncAttributeMaxDynamicSharedMemorySize, PATCH_SMEM);

    // 1. weight splits (cheap)
    wsplit_kernel<<<(1536 * GK / 4 + 255) / 256, 256>>>(w_qkv, wqh, wql, 1536 * GK / 4);
    wsplit_kernel<<<(512 * GK / 4 + 255) / 256, 256>>>(w_out, woh, wol, 512 * GK / 4);

    // 2. QKV GEMM -> g_qkv scatter
    {
        dim3 grid(1536 / 128, (S_TOT + 127) / 128);
        gemm_f16x2<1><<<grid, 512, GEMM_SMEM>>>(x, wqh, wql, b_qkv, nullptr, S_TOT, 0);
    }
    // 3. RoPE
    rope_kernel<<<L_PAT / 8, 256>>>(coords);
    // 4. CLS attention split-K + combine
    {
        dim3 grid(32, 8);
        cls_part_kernel<<<grid, 256>>>();
        cls_combine_kernel<<<32, 64>>>();
    }
    // 5. Patch attention
    {
        dim3 grid(L_PAT / 64, H_NUM);
        patch_attn_kernel<<<grid, 256, PATCH_SMEM>>>();
    }
    // 6. out projection
    {
        dim3 grid(512 / 128, (S_TOT + 127) / 128);
        gemm_f16x2<0><<<grid, 512, GEMM_SMEM>>>(attn_ptr, woh, wol, b_out, out, S_TOT, 512);
    }
}

// round 10
// speedup vs baseline: 1.3957x; 1.1166x over previous
#include <cuda_runtime.h>
#include <cuda_fp16.h>
#include <cuda_bf16.h>
#include <math.h>
#include <stdint.h>

#define S_TOT 8196
#define L_PAT 8192
#define H_NUM 8
#define HD 64
#define NUM_CLS 4
#define WIN 32
#define WLEN 65
#define CTX 69
#define GK 512

// scratch
__device__ float g_qkv[3ull * H_NUM * S_TOT * HD];
__device__ float g_attn[(size_t)S_TOT * 512];
__device__ float g_clsp[32 * 8 * 66];
__device__ float2 g_rtab[(size_t)L_PAT * 32];     // cos/sin per (token, pair)
__device__ __half g_wqh[1536 * GK];
__device__ __half g_wql[1536 * GK];
__device__ __half g_woh[512 * GK];
__device__ __half g_wol[512 * GK];

__constant__ float c_ftbl[16] = {
    1.0f, 0.5623413252f, 0.3162277660f, 0.1778279410f,
    0.1f, 0.05623413252f, 0.03162277660f, 0.01778279410f,
    0.01f, 0.005623413252f, 0.003162277660f, 0.001778279410f,
    0.001f, 0.0005623413252f, 0.0003162277660f, 0.0001778279410f
};

extern __shared__ char dynsm[];

__device__ __forceinline__ uint32_t smem_u32(const void* p) {
    uint32_t a;
    asm("{ .reg .u64 t; cvta.to.shared.u64 t, %1; cvt.u32.u64 %0, t; }" : "=r"(a) : "l"(p));
    return a;
}
__device__ __forceinline__ void ldm_x4(uint32_t* r, uint32_t addr) {
    asm volatile("ldmatrix.sync.aligned.m8n8.x4.shared.b16 {%0,%1,%2,%3}, [%4];"
                 : "=r"(r[0]), "=r"(r[1]), "=r"(r[2]), "=r"(r[3]) : "r"(addr));
}
__device__ __forceinline__ void mma_h(float* c, const uint32_t* a, uint32_t b0, uint32_t b1) {
    asm volatile("mma.sync.aligned.m16n8k16.row.col.f32.f16.f16.f32 "
                 "{%0,%1,%2,%3}, {%4,%5,%6,%7}, {%8,%9}, {%0,%1,%2,%3};"
                 : "+f"(c[0]), "+f"(c[1]), "+f"(c[2]), "+f"(c[3])
                 : "r"(a[0]), "r"(a[1]), "r"(a[2]), "r"(a[3]), "r"(b0), "r"(b1));
}
__device__ __forceinline__ uint32_t packf16(float a, float b) {
    __half2 t = __floats2half2_rn(a, b);
    return *(uint32_t*)&t;
}
// fast exp on FMA pipe (x <= 0 domain)
__device__ __forceinline__ float fexp(float x) {
    x = fmaxf(x, -80.0f);
    float z = fmaf(x, 1.442695041f, 12582912.0f);
    float n = z - 12582912.0f;
    float f = fmaf(x, 1.442695041f, -n);
    float r = 1.3333558e-3f;
    r = fmaf(r, f, 9.6181291e-3f);
    r = fmaf(r, f, 5.5504109e-2f);
    r = fmaf(r, f, 2.4022651e-1f);
    r = fmaf(r, f, 6.9314718e-1f);
    r = fmaf(r, f, 1.0f);
    return r * __int_as_float(((int)n + 127) << 23);
}
// load 16 halves -> 16 floats
__device__ __forceinline__ void ld16h(const __half* p, float* out) {
    uint4 u0 = *(const uint4*)p;
    uint4 u1 = *(const uint4*)(p + 8);
    const __half2* h0 = (const __half2*)&u0;
    const __half2* h1 = (const __half2*)&u1;
#pragma unroll
    for (int j = 0; j < 4; j++) {
        float2 f = __half22float2(h0[j]);
        out[2 * j] = f.x; out[2 * j + 1] = f.y;
    }
#pragma unroll
    for (int j = 0; j < 4; j++) {
        float2 f = __half22float2(h1[j]);
        out[8 + 2 * j] = f.x; out[8 + 2 * j + 1] = f.y;
    }
}

// ---------------------------------------------------------------------------
// weight split: fp32 -> (hi, lo) fp16, round-to-nearest
// ---------------------------------------------------------------------------
__global__ void wsplit_kernel(const float* __restrict__ src,
                              __half* __restrict__ hi,
                              __half* __restrict__ lo, int n4) {
    int i = blockIdx.x * 256 + threadIdx.x;
    if (i >= n4) return;
    float4 v = *(const float4*)(src + (size_t)i * 4);
    __half h0 = __float2half_rn(v.x), h1 = __float2half_rn(v.y);
    __half h2 = __float2half_rn(v.z), h3 = __float2half_rn(v.w);
    __half l0 = __float2half_rn(v.x - __half2float(h0));
    __half l1 = __float2half_rn(v.y - __half2float(h1));
    __half l2 = __float2half_rn(v.z - __half2float(h2));
    __half l3 = __float2half_rn(v.w - __half2float(h3));
    __half2* hp = (__half2*)(hi + (size_t)i * 4);
    __half2* lp = (__half2*)(lo + (size_t)i * 4);
    hp[0] = __half2(h0, h1); hp[1] = __half2(h2, h3);
    lp[0] = __half2(l0, l1); lp[1] = __half2(l2, l3);
}

// ---------------------------------------------------------------------------
// rope cos/sin table: idx -> (l = idx>>5, p = idx&31)
// ---------------------------------------------------------------------------
__global__ void rope_table_kernel(const float* __restrict__ coords) {
    int idx = blockIdx.x * 256 + threadIdx.x;
    int l = idx >> 5, p = idx & 31;
    float cx = coords[2 * l + 0];
    float cy = coords[2 * l + 1];
    float freq = c_ftbl[p & 15];
    float coord = ((p < 16) ? cx : cy) * 1e-5f;
    float s, c;
    __sincosf(coord * freq, &s, &c);
    g_rtab[idx] = make_float2(c, s);
}

// ---------------------------------------------------------------------------
// fp16x2 mma.sync GEMM (MODE 1 fuses RoPE in epilogue via g_rtab)
// ---------------------------------------------------------------------------
#define SMS 72
#define TILE_E (128 * SMS)
#define STAGE_E (3 * TILE_E)
#define TILE_B (TILE_E * 2)
#define STAGE_B (STAGE_E * 2)
#define GEMM_SMEM (2 * STAGE_B)

template<int MODE>
__launch_bounds__(512)
__global__ void gemm_f16x2(const float* __restrict__ A,
                           const __half* __restrict__ Bh,
                           const __half* __restrict__ Bl,
                           const float* __restrict__ bias,
                           float* __restrict__ C, int M, int Ntot) {
    __half* sm = (__half*)dynsm;

    const int tid = threadIdx.x;
    const int wid = tid >> 5;
    const int lane = tid & 31;
    const int wm = (wid >> 2) * 32;
    const int wn = (wid & 3) * 32;
    const int bm = blockIdx.y * 128;
    const int bn = blockIdx.x * 128;

    float c[2][4][4];
#pragma unroll
    for (int i = 0; i < 2; i++)
#pragma unroll
        for (int j = 0; j < 4; j++)
#pragma unroll
            for (int r = 0; r < 4; r++) c[i][j][r] = 0.f;

    const uint32_t smb = smem_u32(sm);
    const int lrow = lane & 15;
    const int lcol = (lane >> 4) * 8;

    float4 pa[4];
    uint4 pbh[2], pbl[2];
    int alr[4], alc[4], brow[2], bc8[2];
#pragma unroll
    for (int it = 0; it < 4; it++) {
        int idx = tid + it * 512;
        alr[it] = idx >> 4;
        alc[it] = (idx & 15) * 4;
    }
#pragma unroll
    for (int it = 0; it < 2; it++) {
        int idx = tid + it * 512;
        brow[it] = idx >> 3;
        bc8[it] = (idx & 7) * 8;
    }

    auto ldg_stage = [&](int ch) {
#pragma unroll
        for (int it = 0; it < 4; it++) {
            int gr = bm + alr[it];
            pa[it] = make_float4(0.f, 0.f, 0.f, 0.f);
            if (gr < M) pa[it] = *(const float4*)&A[(size_t)gr * GK + ch * 64 + alc[it]];
        }
#pragma unroll
        for (int it = 0; it < 2; it++) {
            size_t off = (size_t)(bn + brow[it]) * GK + ch * 64 + bc8[it];
            pbh[it] = *(const uint4*)(Bh + off);
            pbl[it] = *(const uint4*)(Bl + off);
        }
    };
    auto sts_stage = [&](int st) {
        __half* sA = sm + st * STAGE_E;
        __half* sBh = sA + TILE_E;
        __half* sBl = sA + 2 * TILE_E;
#pragma unroll
        for (int it = 0; it < 4; it++) {
            int off = alr[it] * SMS + alc[it];
            float4 v = pa[it];
            uint2 pk = make_uint2(packf16(v.x, v.y), packf16(v.z, v.w));
            *(uint2*)(sA + off) = pk;
        }
#pragma unroll
        for (int it = 0; it < 2; it++) {
            int off = brow[it] * SMS + bc8[it];
            *(uint4*)(sBh + off) = pbh[it];
            *(uint4*)(sBl + off) = pbl[it];
        }
    };

    ldg_stage(0);
    sts_stage(0);
    __syncthreads();

    for (int ch = 0; ch < GK / 64; ch++) {
        int st = ch & 1;
        if (ch < GK / 64 - 1) ldg_stage(ch + 1);

        uint32_t a_b = smb + st * STAGE_B;
        uint32_t bh_b = a_b + TILE_B;
        uint32_t bl_b = a_b + 2 * TILE_B;

#pragma unroll
        for (int kk = 0; kk < 4; kk++) {
            uint32_t af[2][4], bfh[2][4], bfl[2][4];
#pragma unroll
            for (int mt = 0; mt < 2; mt++) {
                uint32_t off = ((wm + mt * 16 + lrow) * SMS + kk * 16 + lcol) * 2;
                ldm_x4(af[mt], a_b + off);
            }
#pragma unroll
            for (int g = 0; g < 2; g++) {
                uint32_t off = ((wn + g * 16 + lrow) * SMS + kk * 16 + lcol) * 2;
                ldm_x4(bfh[g], bh_b + off);
                ldm_x4(bfl[g], bl_b + off);
            }
#pragma unroll
            for (int mt = 0; mt < 2; mt++) {
#pragma unroll
                for (int nt = 0; nt < 4; nt++) {
                    int g = nt >> 1, s = nt & 1;
                    mma_h(c[mt][nt], af[mt], bfh[g][s], bfh[g][s + 2]);
                    mma_h(c[mt][nt], af[mt], bfl[g][s], bfl[g][s + 2]);
                }
            }
        }
        if (ch < GK / 64 - 1) sts_stage(st ^ 1);
        __syncthreads();
    }

    const int gid = lane >> 2;
    const int tig = lane & 3;
#pragma unroll
    for (int mt = 0; mt < 2; mt++) {
#pragma unroll
        for (int nt = 0; nt < 4; nt++) {
            int n = bn + wn + nt * 8 + tig * 2;
            float bx = bias[n], by = bias[n + 1];
            int m0 = bm + wm + mt * 16 + gid;
#pragma unroll
            for (int half = 0; half < 2; half++) {
                int m = m0 + half * 8;
                if (m >= M) continue;
                float vx = c[mt][nt][half * 2 + 0] + bx;
                float vy = c[mt][nt][half * 2 + 1] + by;
                if (MODE == 0) {
                    *(float2*)&C[(size_t)m * Ntot + n] = make_float2(vx, vy);
                } else {
                    int sel = n >> 9, h = (n >> 6) & 7, d = n & 63;
                    if (sel < 2 && m >= NUM_CLS) {
                        float2 cs = g_rtab[(size_t)(m - NUM_CLS) * 32 + (d >> 1)];
                        float rx = vx * cs.x - vy * cs.y;
                        float ry = vy * cs.x + vx * cs.y;
                        vx = rx; vy = ry;
                    }
                    *(float2*)&g_qkv[(((size_t)(sel * 8 + h) * S_TOT) + m) * 64 + d] =
                        make_float2(vx, vy);
                }
            }
        }
    }
}

// ---------------------------------------------------------------------------
// CLS attention: block = (h, chunk), all 4 cls queries together.
// ---------------------------------------------------------------------------
#define CCHUNK 1025
#define SCB 1028

__launch_bounds__(256)
__global__ void cls_part_kernel() {
    __shared__ float qs[4 * 64];
    __shared__ float scb[4 * SCB];
    __shared__ float red[4][8];
    __shared__ float gm[4], gs[4];
    __shared__ float osum[8][4][64];

    int h = blockIdx.x;
    int chunk = blockIdx.y;
    int k0 = chunk * CCHUNK;
    int k1 = min(S_TOT, k0 + CCHUNK);
    int nk = k1 - k0;
    int tid = threadIdx.x;
    int lane = tid & 31, w = tid >> 5;

    const float* Kb = &g_qkv[(size_t)(8 + h) * S_TOT * 64];
    const float* Vb = &g_qkv[(size_t)(16 + h) * S_TOT * 64];

    // q_cls: [ci][d]
    {
        int ci = tid >> 6, d = tid & 63;
        qs[tid] = g_qkv[(((size_t)h * S_TOT) + ci) * 64 + d];
    }
    __syncthreads();

    // scores for all 4 cls queries
    float lmax[4] = {-INFINITY, -INFINITY, -INFINITY, -INFINITY};
    for (int s = tid; s < nk; s += 256) {
        const float4* kr = (const float4*)(Kb + (size_t)(k0 + s) * 64);
        float a[4] = {0.f, 0.f, 0.f, 0.f};
#pragma unroll
        for (int i = 0; i < 16; i++) {
            float4 kv = kr[i];
#pragma unroll
            for (int ci = 0; ci < 4; ci++) {
                float4 qv = *(float4*)&qs[ci * 64 + i * 4];
                a[ci] += kv.x * qv.x + kv.y * qv.y + kv.z * qv.z + kv.w * qv.w;
            }
        }
#pragma unroll
        for (int ci = 0; ci < 4; ci++) {
            float sa = a[ci] * 0.125f;
            scb[ci * SCB + s] = sa;
            lmax[ci] = fmaxf(lmax[ci], sa);
        }
    }
#pragma unroll
    for (int ci = 0; ci < 4; ci++) {
#pragma unroll
        for (int o = 16; o > 0; o >>= 1)
            lmax[ci] = fmaxf(lmax[ci], __shfl_xor_sync(0xffffffffu, lmax[ci], o));
        if (lane == 0) red[ci][w] = lmax[ci];
    }
    __syncthreads();
    float gmaxv[4];
#pragma unroll
    for (int ci = 0; ci < 4; ci++) {
        float m = red[ci][0];
#pragma unroll
        for (int i = 1; i < 8; i++) m = fmaxf(m, red[ci][i]);
        gmaxv[ci] = m;
    }
    __syncthreads();

    float lsum[4] = {0.f, 0.f, 0.f, 0.f};
    for (int s = tid; s < nk; s += 256) {
#pragma unroll
        for (int ci = 0; ci < 4; ci++) {
            float p = __expf(scb[ci * SCB + s] - gmaxv[ci]);
            scb[ci * SCB + s] = p;
            lsum[ci] += p;
        }
    }
#pragma unroll
    for (int ci = 0; ci < 4; ci++) {
#pragma unroll
        for (int o = 16; o > 0; o >>= 1)
            lsum[ci] += __shfl_xor_sync(0xffffffffu, lsum[ci], o);
        if (lane == 0) red[ci][w] = lsum[ci];
    }
    __syncthreads();
    if (tid < 4) {
        float ssum = 0.f;
#pragma unroll
        for (int i = 0; i < 8; i++) ssum += red[tid][i];
        gs[tid] = ssum;
        gm[tid] = gmaxv[tid];
    }

    // PV: thread = (sl = tid>>2, dc = tid&3). V read once per block.
    int sl = tid >> 2, dcc = tid & 3, dof = dcc * 16;
    float acc[4][16];
#pragma unroll
    for (int ci = 0; ci < 4; ci++)
#pragma unroll
        for (int dd = 0; dd < 16; dd++) acc[ci][dd] = 0.f;

    for (int s = sl; s < nk; s += 64) {
        float p[4];
#pragma unroll
        for (int ci = 0; ci < 4; ci++) p[ci] = scb[ci * SCB + s];
        const float* vr = Vb + (size_t)(k0 + s) * 64 + dof;
        float vf[16];
#pragma unroll
        for (int i = 0; i < 4; i++) *(float4*)&vf[i * 4] = *(const float4*)&vr[i * 4];
#pragma unroll
        for (int dd = 0; dd < 16; dd++) {
            float vv = vf[dd];
            acc[0][dd] = fmaf(p[0], vv, acc[0][dd]);
            acc[1][dd] = fmaf(p[1], vv, acc[1][dd]);
            acc[2][dd] = fmaf(p[2], vv, acc[2][dd]);
            acc[3][dd] = fmaf(p[3], vv, acc[3][dd]);
        }
    }
#pragma unroll
    for (int o = 4; o <= 16; o <<= 1)
#pragma unroll
        for (int ci = 0; ci < 4; ci++)
#pragma unroll
            for (int dd = 0; dd < 16; dd++)
                acc[ci][dd] += __shfl_xor_sync(0xffffffffu, acc[ci][dd], o);

    if ((lane & 28) == 0) {
#pragma unroll
        for (int ci = 0; ci < 4; ci++)
#pragma unroll
            for (int dd = 0; dd < 16; dd++)
                osum[w][ci][dof + dd] = acc[ci][dd];
    }
    __syncthreads();

    {
        int ci = tid >> 6, d = tid & 63;
        float v = 0.f;
#pragma unroll
        for (int i = 0; i < 8; i++) v += osum[i][ci][d];
        float* dst = &g_clsp[((size_t)(h * 4 + ci) * 8 + chunk) * 66];
        dst[2 + d] = v;
        if (d == 0) { dst[0] = gm[ci]; dst[1] = gs[ci]; }
    }
}

__global__ void cls_combine_kernel() {
    int hc = blockIdx.x;
    int h = hc >> 2, ci = hc & 3;
    int d = threadIdx.x;
    const float* base = &g_clsp[(size_t)hc * 8 * 66];
    float M = -INFINITY;
#pragma unroll
    for (int c = 0; c < 8; c++) M = fmaxf(M, base[c * 66]);
    float S = 0.f, A = 0.f;
#pragma unroll
    for (int c = 0; c < 8; c++) {
        float w = __expf(base[c * 66] - M);
        S = fmaf(base[c * 66 + 1], w, S);
        A = fmaf(base[c * 66 + 2 + d], w, A);
    }
    g_attn[(size_t)ci * 512 + h * 64 + d] = A / S;
}

// ---------------------------------------------------------------------------
// Patch attention: fp16 K/V smem, thread owns 2 queries, 24 warps/SM target.
// thread: dc = tid&3 (16-dim chunk), jp = (tid>>2)&1 (row parity), qg = tid>>3.
// ---------------------------------------------------------------------------
#define KSH 72
#define PATCH_SMEM ((128 * KSH * 2 + 256 + 256) * 2 + (64 * 72) * 4)

__launch_bounds__(256, 3)
__global__ void patch_attn_kernel() {
    __half* ksh = (__half*)dynsm;
    __half* vsh = ksh + 128 * KSH;
    __half* kch = vsh + 128 * KSH;
    __half* vch = kch + 256;
    float* sc = (float*)(vch + 256);

    int h = blockIdx.y;
    int l0 = blockIdx.x * 64;
    int tid = threadIdx.x;

    const float* Qb = &g_qkv[(size_t)h * S_TOT * 64];
    const float* Kb = &g_qkv[(size_t)(8 + h) * S_TOT * 64];
    const float* Vb = &g_qkv[(size_t)(16 + h) * S_TOT * 64];

    for (int i = tid; i < 128 * 16; i += 256) {
        int r = i >> 4, c4 = (i & 15) << 2;
        int kp = l0 - WIN + r;
        float4 kv = make_float4(0.f, 0.f, 0.f, 0.f);
        float4 vv = make_float4(0.f, 0.f, 0.f, 0.f);
        if (kp >= 0 && kp < L_PAT) {
            kv = *(const float4*)&Kb[(size_t)(NUM_CLS + kp) * 64 + c4];
            vv = *(const float4*)&Vb[(size_t)(NUM_CLS + kp) * 64 + c4];
        }
        *(uint2*)&ksh[r * KSH + c4] = make_uint2(packf16(kv.x, kv.y), packf16(kv.z, kv.w));
        *(uint2*)&vsh[r * KSH + c4] = make_uint2(packf16(vv.x, vv.y), packf16(vv.z, vv.w));
    }
    if (tid < 64) {
        int r = tid >> 4, c4 = (tid & 15) << 2;
        float4 kv = *(const float4*)&Kb[(size_t)r * 64 + c4];
        float4 vv = *(const float4*)&Vb[(size_t)r * 64 + c4];
        *(uint2*)&kch[r * 64 + c4] = make_uint2(packf16(kv.x, kv.y), packf16(kv.z, kv.w));
        *(uint2*)&vch[r * 64 + c4] = make_uint2(packf16(vv.x, vv.y), packf16(vv.z, vv.w));
    }

    const int dc = tid & 3;
    const int jp = (tid >> 2) & 1;
    const int qg = tid >> 3;
    const int qi0 = qg * 2;
    const int dof = dc * 16;

    float qreg[2][16];
#pragma unroll
    for (int qq = 0; qq < 2; qq++)
#pragma unroll
        for (int i = 0; i < 4; i++)
            *(float4*)&qreg[qq][i * 4] =
                *(const float4*)&Qb[(size_t)(NUM_CLS + l0 + qi0 + qq) * 64 + dof + i * 4];
    __syncthreads();

    // ---- scores ----
    for (int ri = jp; ri < 70; ri += 2) {
        const __half* kr = (ri < 4) ? &kch[ri * 64 + dof]
                                    : &ksh[(qi0 + ri - 4) * KSH + dof];
        float kf[16];
        ld16h(kr, kf);
        float acc0 = 0.f, acc1 = 0.f;
#pragma unroll
        for (int dd = 0; dd < 16; dd++) {
            acc0 = fmaf(qreg[0][dd], kf[dd], acc0);
            acc1 = fmaf(qreg[1][dd], kf[dd], acc1);
        }
        acc0 += __shfl_xor_sync(0xffffffffu, acc0, 1);
        acc0 += __shfl_xor_sync(0xffffffffu, acc0, 2);
        acc1 += __shfl_xor_sync(0xffffffffu, acc1, 1);
        acc1 += __shfl_xor_sync(0xffffffffu, acc1, 2);
        if (dc == 0) {
            if (ri < 4) {
                sc[qi0 * 72 + ri] = acc0 * 0.125f;
                sc[(qi0 + 1) * 72 + ri] = acc1 * 0.125f;
            } else {
                int rw = ri - 4;
                int pos = l0 + qi0 + rw - WIN;
                bool ok = (pos >= 0) && (pos < L_PAT);
                if (rw <= 64) sc[qi0 * 72 + 4 + rw] = ok ? acc0 * 0.125f : -1e30f;
                int w1 = rw - 1;
                if (w1 >= 0) sc[(qi0 + 1) * 72 + 4 + w1] = ok ? acc1 * 0.125f : -1e30f;
            }
        }
    }
    __syncthreads();

    // ---- softmax (4 threads per row) ----
    {
        int row = tid >> 2, sub = tid & 3;
        float* srow = &sc[row * 72];
        float m = -INFINITY;
        for (int j = sub; j < CTX; j += 4) m = fmaxf(m, srow[j]);
        m = fmaxf(m, __shfl_xor_sync(0xffffffffu, m, 1));
        m = fmaxf(m, __shfl_xor_sync(0xffffffffu, m, 2));
        float sum = 0.f;
        for (int j = sub; j < CTX; j += 4) {
            float p = fexp(srow[j] - m);
            srow[j] = p;
            sum += p;
        }
        sum += __shfl_xor_sync(0xffffffffu, sum, 1);
        sum += __shfl_xor_sync(0xffffffffu, sum, 2);
        float inv = 1.0f / sum;
        for (int j = sub; j < CTX; j += 4) srow[j] *= inv;
    }
    __syncthreads();

    // ---- PV ----
    float oacc[2][16];
#pragma unroll
    for (int qq = 0; qq < 2; qq++)
#pragma unroll
        for (int dd = 0; dd < 16; dd++) oacc[qq][dd] = 0.f;

    for (int ri = jp; ri < 70; ri += 2) {
        const __half* vr;
        float p0, p1;
        if (ri < 4) {
            vr = &vch[ri * 64 + dof];
            p0 = sc[qi0 * 72 + ri];
            p1 = sc[(qi0 + 1) * 72 + ri];
        } else {
            int rw = ri - 4;
            vr = &vsh[(qi0 + rw) * KSH + dof];
            p0 = (rw <= 64) ? sc[qi0 * 72 + 4 + rw] : 0.f;
            int w1 = rw - 1;
            p1 = (w1 >= 0) ? sc[(qi0 + 1) * 72 + 4 + w1] : 0.f;
        }
        float vf[16];
        ld16h(vr, vf);
#pragma unroll
        for (int dd = 0; dd < 16; dd++) {
            oacc[0][dd] = fmaf(p0, vf[dd], oacc[0][dd]);
            oacc[1][dd] = fmaf(p1, vf[dd], oacc[1][dd]);
        }
    }
#pragma unroll
    for (int qq = 0; qq < 2; qq++)
#pragma unroll
        for (int dd = 0; dd < 16; dd++)
            oacc[qq][dd] += __shfl_xor_sync(0xffffffffu, oacc[qq][dd], 4);

    if (jp == 0) {
#pragma unroll
        for (int qq = 0; qq < 2; qq++)
#pragma unroll
            for (int i = 0; i < 4; i++)
                *(float4*)&g_attn[(size_t)(NUM_CLS + l0 + qi0 + qq) * 512 + h * 64 + dof + i * 4] =
                    *(float4*)&oacc[qq][i * 4];
    }
}

// ---------------------------------------------------------------------------
extern "C" void kernel_launch(void* const* d_in, const int* in_sizes, int n_in,
                              void* d_out, int out_size) {
    const float* x      = (const float*)d_in[0];
    const float* coords = (const float*)d_in[1];
    const float* w_qkv  = (const float*)d_in[2];
    const float* b_qkv  = (const float*)d_in[3];
    const float* w_out  = (const float*)d_in[4];
    const float* b_out  = (const float*)d_in[5];
    float* out = (float*)d_out;

    float* attn_ptr = nullptr;
    cudaGetSymbolAddress((void**)&attn_ptr, g_attn);
    __half *wqh, *wql, *woh, *wol;
    cudaGetSymbolAddress((void**)&wqh, g_wqh);
    cudaGetSymbolAddress((void**)&wql, g_wql);
    cudaGetSymbolAddress((void**)&woh, g_woh);
    cudaGetSymbolAddress((void**)&wol, g_wol);

    cudaFuncSetAttribute(gemm_f16x2<0>, cudaFuncAttributeMaxDynamicSharedMemorySize, GEMM_SMEM);
    cudaFuncSetAttribute(gemm_f16x2<1>, cudaFuncAttributeMaxDynamicSharedMemorySize, GEMM_SMEM);
    cudaFuncSetAttribute(patch_attn_kernel, cudaFuncAttributeMaxDynamicSharedMemorySize, PATCH_SMEM);

    // 1. weight splits + rope table
    wsplit_kernel<<<(1536 * GK / 4 + 255) / 256, 256>>>(w_qkv, wqh, wql, 1536 * GK / 4);
    wsplit_kernel<<<(512 * GK / 4 + 255) / 256, 256>>>(w_out, woh, wol, 512 * GK / 4);
    rope_table_kernel<<<(L_PAT * 32) / 256, 256>>>(coords);

    // 2. QKV GEMM (rope fused in epilogue) -> g_qkv scatter
    {
        dim3 grid(1536 / 128, (S_TOT + 127) / 128);
        gemm_f16x2<1><<<grid, 512, GEMM_SMEM>>>(x, wqh, wql, b_qkv, nullptr, S_TOT, 0);
    }
    // 3. CLS attention (merged) + combine
    {
        dim3 grid(8, 8);
        cls_part_kernel<<<grid, 256>>>();
        cls_combine_kernel<<<32, 64>>>();
    }
    // 4. Patch attention
    {
        dim3 grid(L_PAT / 64, H_NUM);
        patch_attn_kernel<<<grid, 256, PATCH_SMEM>>>();
    }
    // 5. out projection
    {
        dim3 grid(512 / 128, (S_TOT + 127) / 128);
        gemm_f16x2<0><<<grid, 512, GEMM_SMEM>>>(attn_ptr, woh, wol, b_out, out, S_TOT, 512);
    }
}

// round 11
// speedup vs baseline: 1.4074x; 1.0084x over previous
#include <cuda_runtime.h>
#include <cuda_fp16.h>
#include <cuda_bf16.h>
#include <math.h>
#include <stdint.h>

#define S_TOT 8196
#define L_PAT 8192
#define H_NUM 8
#define HD 64
#define NUM_CLS 4
#define WIN 32
#define WLEN 65
#define CTX 69
#define GK 512

// scratch
__device__ float g_qkv[3ull * H_NUM * S_TOT * HD];
__device__ float g_attn[(size_t)S_TOT * 512];
__device__ float g_clsp[32 * 8 * 66];
__device__ float2 g_rtab[(size_t)L_PAT * 32];
__device__ __half g_xf[(size_t)S_TOT * GK];       // x as fp16
__device__ __half g_af[(size_t)S_TOT * GK];       // attn as fp16
__device__ __half g_wqh[1536 * GK];
__device__ __half g_wql[1536 * GK];
__device__ __half g_woh[512 * GK];
__device__ __half g_wol[512 * GK];

__constant__ float c_ftbl[16] = {
    1.0f, 0.5623413252f, 0.3162277660f, 0.1778279410f,
    0.1f, 0.05623413252f, 0.03162277660f, 0.01778279410f,
    0.01f, 0.005623413252f, 0.003162277660f, 0.001778279410f,
    0.001f, 0.0005623413252f, 0.0003162277660f, 0.0001778279410f
};

extern __shared__ char dynsm[];

__device__ __forceinline__ uint32_t smem_u32(const void* p) {
    uint32_t a;
    asm("{ .reg .u64 t; cvta.to.shared.u64 t, %1; cvt.u32.u64 %0, t; }" : "=r"(a) : "l"(p));
    return a;
}
__device__ __forceinline__ void ldm_x4(uint32_t* r, uint32_t addr) {
    asm volatile("ldmatrix.sync.aligned.m8n8.x4.shared.b16 {%0,%1,%2,%3}, [%4];"
                 : "=r"(r[0]), "=r"(r[1]), "=r"(r[2]), "=r"(r[3]) : "r"(addr));
}
__device__ __forceinline__ void mma_h(float* c, const uint32_t* a, uint32_t b0, uint32_t b1) {
    asm volatile("mma.sync.aligned.m16n8k16.row.col.f32.f16.f16.f32 "
                 "{%0,%1,%2,%3}, {%4,%5,%6,%7}, {%8,%9}, {%0,%1,%2,%3};"
                 : "+f"(c[0]), "+f"(c[1]), "+f"(c[2]), "+f"(c[3])
                 : "r"(a[0]), "r"(a[1]), "r"(a[2]), "r"(a[3]), "r"(b0), "r"(b1));
}
__device__ __forceinline__ uint32_t packf16(float a, float b) {
    __half2 t = __floats2half2_rn(a, b);
    return *(uint32_t*)&t;
}
__device__ __forceinline__ void cp16(uint32_t dst, const void* src, int sz) {
    asm volatile("cp.async.cg.shared.global [%0], [%1], 16, %2;"
                 :: "r"(dst), "l"(src), "r"(sz));
}
#define CP_COMMIT() asm volatile("cp.async.commit_group;" ::: "memory")
#define CP_WAIT0()  asm volatile("cp.async.wait_group 0;" ::: "memory")

// fast exp on FMA pipe (x <= 0 domain)
__device__ __forceinline__ float fexp(float x) {
    x = fmaxf(x, -80.0f);
    float z = fmaf(x, 1.442695041f, 12582912.0f);
    float n = z - 12582912.0f;
    float f = fmaf(x, 1.442695041f, -n);
    float r = 1.3333558e-3f;
    r = fmaf(r, f, 9.6181291e-3f);
    r = fmaf(r, f, 5.5504109e-2f);
    r = fmaf(r, f, 2.4022651e-1f);
    r = fmaf(r, f, 6.9314718e-1f);
    r = fmaf(r, f, 1.0f);
    return r * __int_as_float(((int)n + 127) << 23);
}
__device__ __forceinline__ void ld16h(const __half* p, float* out) {
    uint4 u0 = *(const uint4*)p;
    uint4 u1 = *(const uint4*)(p + 8);
    const __half2* h0 = (const __half2*)&u0;
    const __half2* h1 = (const __half2*)&u1;
#pragma unroll
    for (int j = 0; j < 4; j++) {
        float2 f = __half22float2(h0[j]);
        out[2 * j] = f.x; out[2 * j + 1] = f.y;
    }
#pragma unroll
    for (int j = 0; j < 4; j++) {
        float2 f = __half22float2(h1[j]);
        out[8 + 2 * j] = f.x; out[8 + 2 * j + 1] = f.y;
    }
}

// ---------------------------------------------------------------------------
// fp32 -> fp16 convert
// ---------------------------------------------------------------------------
__global__ void tof16_kernel(const float* __restrict__ src,
                             __half* __restrict__ dst, int n4) {
    int i = blockIdx.x * 256 + threadIdx.x;
    if (i >= n4) return;
    float4 v = *(const float4*)(src + (size_t)i * 4);
    *(uint2*)(dst + (size_t)i * 4) = make_uint2(packf16(v.x, v.y), packf16(v.z, v.w));
}

// ---------------------------------------------------------------------------
// weight split: fp32 -> (hi, lo) fp16, round-to-nearest
// ---------------------------------------------------------------------------
__global__ void wsplit_kernel(const float* __restrict__ src,
                              __half* __restrict__ hi,
                              __half* __restrict__ lo, int n4) {
    int i = blockIdx.x * 256 + threadIdx.x;
    if (i >= n4) return;
    float4 v = *(const float4*)(src + (size_t)i * 4);
    __half h0 = __float2half_rn(v.x), h1 = __float2half_rn(v.y);
    __half h2 = __float2half_rn(v.z), h3 = __float2half_rn(v.w);
    __half l0 = __float2half_rn(v.x - __half2float(h0));
    __half l1 = __float2half_rn(v.y - __half2float(h1));
    __half l2 = __float2half_rn(v.z - __half2float(h2));
    __half l3 = __float2half_rn(v.w - __half2float(h3));
    __half2* hp = (__half2*)(hi + (size_t)i * 4);
    __half2* lp = (__half2*)(lo + (size_t)i * 4);
    hp[0] = __half2(h0, h1); hp[1] = __half2(h2, h3);
    lp[0] = __half2(l0, l1); lp[1] = __half2(l2, l3);
}

// ---------------------------------------------------------------------------
// rope cos/sin table
// ---------------------------------------------------------------------------
__global__ void rope_table_kernel(const float* __restrict__ coords) {
    int idx = blockIdx.x * 256 + threadIdx.x;
    int l = idx >> 5, p = idx & 31;
    float cx = coords[2 * l + 0];
    float cy = coords[2 * l + 1];
    float freq = c_ftbl[p & 15];
    float coord = ((p < 16) ? cx : cy) * 1e-5f;
    float s, c;
    __sincosf(coord * freq, &s, &c);
    g_rtab[idx] = make_float2(c, s);
}

// ---------------------------------------------------------------------------
// fp16x2 mma.sync GEMM, all-fp16 operands via cp.async.
// 256 threads, 8 warps (2x4), CTA tile 128x128, warp tile 64x32, k-chunk 64,
// 2-stage cp.async double buffer.  MODE 1 fuses RoPE in epilogue.
// ---------------------------------------------------------------------------
#define SMS 72
#define TILE_B (128 * SMS * 2)           // 18432 B per tile
#define STAGE_B (3 * TILE_B)             // A, Bh, Bl = 55296 B
#define GEMM_SMEM (2 * STAGE_B)          // 110592 B

template<int MODE>
__launch_bounds__(256)
__global__ void gemm_f16x2(const __half* __restrict__ A,
                           const __half* __restrict__ Bh,
                           const __half* __restrict__ Bl,
                           const float* __restrict__ bias,
                           float* __restrict__ C, int M, int Ntot) {
    const int tid = threadIdx.x;
    const int wid = tid >> 5;
    const int lane = tid & 31;
    const int wm = (wid >> 2) * 64;
    const int wn = (wid & 3) * 32;
    const int bm = blockIdx.y * 128;
    const int bn = blockIdx.x * 128;

    float c[4][4][4];
#pragma unroll
    for (int i = 0; i < 4; i++)
#pragma unroll
        for (int j = 0; j < 4; j++)
#pragma unroll
            for (int r = 0; r < 4; r++) c[i][j][r] = 0.f;

    const uint32_t smb = smem_u32(dynsm);
    const int lrow = lane & 15;
    const int lcol = (lane >> 4) * 8;

    auto cp_chunk = [&](int ch, int st) {
        uint32_t sb = smb + st * STAGE_B;
#pragma unroll
        for (int it = 0; it < 12; it++) {
            int idx = tid + it * 256;
            int tile = idx >> 10;        // 0..2
            int slot = idx & 1023;
            int row = slot >> 3;
            int c16 = slot & 7;
            uint32_t dst = sb + tile * TILE_B + row * (SMS * 2) + c16 * 16;
            if (tile == 0) {
                int gr = bm + row;
                cp16(dst, A + (size_t)gr * GK + ch * 64 + c16 * 8, gr < M ? 16 : 0);
            } else if (tile == 1) {
                cp16(dst, Bh + (size_t)(bn + row) * GK + ch * 64 + c16 * 8, 16);
            } else {
                cp16(dst, Bl + (size_t)(bn + row) * GK + ch * 64 + c16 * 8, 16);
            }
        }
        CP_COMMIT();
    };

    cp_chunk(0, 0);

    for (int ch = 0; ch < GK / 64; ch++) {
        int st = ch & 1;
        CP_WAIT0();
        __syncthreads();
        if (ch < GK / 64 - 1) cp_chunk(ch + 1, st ^ 1);

        uint32_t a_b = smb + st * STAGE_B;
        uint32_t bh_b = a_b + TILE_B;
        uint32_t bl_b = a_b + 2 * TILE_B;

#pragma unroll
        for (int kk = 0; kk < 4; kk++) {
            uint32_t af[4][4], bfh[2][4], bfl[2][4];
#pragma unroll
            for (int mt = 0; mt < 4; mt++) {
                uint32_t off = ((wm + mt * 16 + lrow) * SMS + kk * 16 + lcol) * 2;
                ldm_x4(af[mt], a_b + off);
            }
#pragma unroll
            for (int g = 0; g < 2; g++) {
                uint32_t off = ((wn + g * 16 + lrow) * SMS + kk * 16 + lcol) * 2;
                ldm_x4(bfh[g], bh_b + off);
                ldm_x4(bfl[g], bl_b + off);
            }
#pragma unroll
            for (int mt = 0; mt < 4; mt++) {
#pragma unroll
                for (int nt = 0; nt < 4; nt++) {
                    int g = nt >> 1, s = nt & 1;
                    mma_h(c[mt][nt], af[mt], bfh[g][s], bfh[g][s + 2]);
                    mma_h(c[mt][nt], af[mt], bfl[g][s], bfl[g][s + 2]);
                }
            }
        }
    }

    const int gid = lane >> 2;
    const int tig = lane & 3;
#pragma unroll
    for (int mt = 0; mt < 4; mt++) {
#pragma unroll
        for (int nt = 0; nt < 4; nt++) {
            int n = bn + wn + nt * 8 + tig * 2;
            float bx = bias[n], by = bias[n + 1];
            int m0 = bm + wm + mt * 16 + gid;
#pragma unroll
            for (int half = 0; half < 2; half++) {
                int m = m0 + half * 8;
                if (m >= M) continue;
                float vx = c[mt][nt][half * 2 + 0] + bx;
                float vy = c[mt][nt][half * 2 + 1] + by;
                if (MODE == 0) {
                    *(float2*)&C[(size_t)m * Ntot + n] = make_float2(vx, vy);
                } else {
                    int sel = n >> 9, h = (n >> 6) & 7, d = n & 63;
                    if (sel < 2 && m >= NUM_CLS) {
                        float2 cs = g_rtab[(size_t)(m - NUM_CLS) * 32 + (d >> 1)];
                        float rx = vx * cs.x - vy * cs.y;
                        float ry = vy * cs.x + vx * cs.y;
                        vx = rx; vy = ry;
                    }
                    *(float2*)&g_qkv[(((size_t)(sel * 8 + h) * S_TOT) + m) * 64 + d] =
                        make_float2(vx, vy);
                }
            }
        }
    }
}

// ---------------------------------------------------------------------------
// CLS attention: block = (h, chunk), all 4 cls queries together.
// ---------------------------------------------------------------------------
#define CCHUNK 1025
#define SCB 1028

__launch_bounds__(256)
__global__ void cls_part_kernel() {
    __shared__ float qs[4 * 64];
    __shared__ float scb[4 * SCB];
    __shared__ float red[4][8];
    __shared__ float gm[4], gs[4];
    __shared__ float osum[8][4][64];

    int h = blockIdx.x;
    int chunk = blockIdx.y;
    int k0 = chunk * CCHUNK;
    int k1 = min(S_TOT, k0 + CCHUNK);
    int nk = k1 - k0;
    int tid = threadIdx.x;
    int lane = tid & 31, w = tid >> 5;

    const float* Kb = &g_qkv[(size_t)(8 + h) * S_TOT * 64];
    const float* Vb = &g_qkv[(size_t)(16 + h) * S_TOT * 64];

    {
        int ci = tid >> 6, d = tid & 63;
        qs[tid] = g_qkv[(((size_t)h * S_TOT) + ci) * 64 + d];
    }
    __syncthreads();

    float lmax[4] = {-INFINITY, -INFINITY, -INFINITY, -INFINITY};
    for (int s = tid; s < nk; s += 256) {
        const float4* kr = (const float4*)(Kb + (size_t)(k0 + s) * 64);
        float a[4] = {0.f, 0.f, 0.f, 0.f};
#pragma unroll
        for (int i = 0; i < 16; i++) {
            float4 kv = kr[i];
#pragma unroll
            for (int ci = 0; ci < 4; ci++) {
                float4 qv = *(float4*)&qs[ci * 64 + i * 4];
                a[ci] += kv.x * qv.x + kv.y * qv.y + kv.z * qv.z + kv.w * qv.w;
            }
        }
#pragma unroll
        for (int ci = 0; ci < 4; ci++) {
            float sa = a[ci] * 0.125f;
            scb[ci * SCB + s] = sa;
            lmax[ci] = fmaxf(lmax[ci], sa);
        }
    }
#pragma unroll
    for (int ci = 0; ci < 4; ci++) {
#pragma unroll
        for (int o = 16; o > 0; o >>= 1)
            lmax[ci] = fmaxf(lmax[ci], __shfl_xor_sync(0xffffffffu, lmax[ci], o));
        if (lane == 0) red[ci][w] = lmax[ci];
    }
    __syncthreads();
    float gmaxv[4];
#pragma unroll
    for (int ci = 0; ci < 4; ci++) {
        float m = red[ci][0];
#pragma unroll
        for (int i = 1; i < 8; i++) m = fmaxf(m, red[ci][i]);
        gmaxv[ci] = m;
    }
    __syncthreads();

    float lsum[4] = {0.f, 0.f, 0.f, 0.f};
    for (int s = tid; s < nk; s += 256) {
#pragma unroll
        for (int ci = 0; ci < 4; ci++) {
            float p = __expf(scb[ci * SCB + s] - gmaxv[ci]);
            scb[ci * SCB + s] = p;
            lsum[ci] += p;
        }
    }
#pragma unroll
    for (int ci = 0; ci < 4; ci++) {
#pragma unroll
        for (int o = 16; o > 0; o >>= 1)
            lsum[ci] += __shfl_xor_sync(0xffffffffu, lsum[ci], o);
        if (lane == 0) red[ci][w] = lsum[ci];
    }
    __syncthreads();
    if (tid < 4) {
        float ssum = 0.f;
#pragma unroll
        for (int i = 0; i < 8; i++) ssum += red[tid][i];
        gs[tid] = ssum;
        gm[tid] = gmaxv[tid];
    }

    int sl = tid >> 2, dcc = tid & 3, dof = dcc * 16;
    float acc[4][16];
#pragma unroll
    for (int ci = 0; ci < 4; ci++)
#pragma unroll
        for (int dd = 0; dd < 16; dd++) acc[ci][dd] = 0.f;

    for (int s = sl; s < nk; s += 64) {
        float p[4];
#pragma unroll
        for (int ci = 0; ci < 4; ci++) p[ci] = scb[ci * SCB + s];
        const float* vr = Vb + (size_t)(k0 + s) * 64 + dof;
        float vf[16];
#pragma unroll
        for (int i = 0; i < 4; i++) *(float4*)&vf[i * 4] = *(const float4*)&vr[i * 4];
#pragma unroll
        for (int dd = 0; dd < 16; dd++) {
            float vv = vf[dd];
            acc[0][dd] = fmaf(p[0], vv, acc[0][dd]);
            acc[1][dd] = fmaf(p[1], vv, acc[1][dd]);
            acc[2][dd] = fmaf(p[2], vv, acc[2][dd]);
            acc[3][dd] = fmaf(p[3], vv, acc[3][dd]);
        }
    }
#pragma unroll
    for (int o = 4; o <= 16; o <<= 1)
#pragma unroll
        for (int ci = 0; ci < 4; ci++)
#pragma unroll
            for (int dd = 0; dd < 16; dd++)
                acc[ci][dd] += __shfl_xor_sync(0xffffffffu, acc[ci][dd], o);

    if ((lane & 28) == 0) {
#pragma unroll
        for (int ci = 0; ci < 4; ci++)
#pragma unroll
            for (int dd = 0; dd < 16; dd++)
                osum[w][ci][dof + dd] = acc[ci][dd];
    }
    __syncthreads();

    {
        int ci = tid >> 6, d = tid & 63;
        float v = 0.f;
#pragma unroll
        for (int i = 0; i < 8; i++) v += osum[i][ci][d];
        float* dst = &g_clsp[((size_t)(h * 4 + ci) * 8 + chunk) * 66];
        dst[2 + d] = v;
        if (d == 0) { dst[0] = gm[ci]; dst[1] = gs[ci]; }
    }
}

__global__ void cls_combine_kernel() {
    int hc = blockIdx.x;
    int h = hc >> 2, ci = hc & 3;
    int d = threadIdx.x;
    const float* base = &g_clsp[(size_t)hc * 8 * 66];
    float M = -INFINITY;
#pragma unroll
    for (int c = 0; c < 8; c++) M = fmaxf(M, base[c * 66]);
    float S = 0.f, A = 0.f;
#pragma unroll
    for (int c = 0; c < 8; c++) {
        float w = __expf(base[c * 66] - M);
        S = fmaf(base[c * 66 + 1], w, S);
        A = fmaf(base[c * 66 + 2 + d], w, A);
    }
    g_attn[(size_t)ci * 512 + h * 64 + d] = A / S;
}

// ---------------------------------------------------------------------------
// Patch attention (R10 version: fp16 K/V smem, 2 queries/thread)
// ---------------------------------------------------------------------------
#define KSH 72
#define PATCH_SMEM ((128 * KSH * 2 + 256 + 256) * 2 + (64 * 72) * 4)

__launch_bounds__(256, 3)
__global__ void patch_attn_kernel() {
    __half* ksh = (__half*)dynsm;
    __half* vsh = ksh + 128 * KSH;
    __half* kch = vsh + 128 * KSH;
    __half* vch = kch + 256;
    float* sc = (float*)(vch + 256);

    int h = blockIdx.y;
    int l0 = blockIdx.x * 64;
    int tid = threadIdx.x;

    const float* Qb = &g_qkv[(size_t)h * S_TOT * 64];
    const float* Kb = &g_qkv[(size_t)(8 + h) * S_TOT * 64];
    const float* Vb = &g_qkv[(size_t)(16 + h) * S_TOT * 64];

    for (int i = tid; i < 128 * 16; i += 256) {
        int r = i >> 4, c4 = (i & 15) << 2;
        int kp = l0 - WIN + r;
        float4 kv = make_float4(0.f, 0.f, 0.f, 0.f);
        float4 vv = make_float4(0.f, 0.f, 0.f, 0.f);
        if (kp >= 0 && kp < L_PAT) {
            kv = *(const float4*)&Kb[(size_t)(NUM_CLS + kp) * 64 + c4];
            vv = *(const float4*)&Vb[(size_t)(NUM_CLS + kp) * 64 + c4];
        }
        *(uint2*)&ksh[r * KSH + c4] = make_uint2(packf16(kv.x, kv.y), packf16(kv.z, kv.w));
        *(uint2*)&vsh[r * KSH + c4] = make_uint2(packf16(vv.x, vv.y), packf16(vv.z, vv.w));
    }
    if (tid < 64) {
        int r = tid >> 4, c4 = (tid & 15) << 2;
        float4 kv = *(const float4*)&Kb[(size_t)r * 64 + c4];
        float4 vv = *(const float4*)&Vb[(size_t)r * 64 + c4];
        *(uint2*)&kch[r * 64 + c4] = make_uint2(packf16(kv.x, kv.y), packf16(kv.z, kv.w));
        *(uint2*)&vch[r * 64 + c4] = make_uint2(packf16(vv.x, vv.y), packf16(vv.z, vv.w));
    }

    const int dc = tid & 3;
    const int jp = (tid >> 2) & 1;
    const int qg = tid >> 3;
    const int qi0 = qg * 2;
    const int dof = dc * 16;

    float qreg[2][16];
#pragma unroll
    for (int qq = 0; qq < 2; qq++)
#pragma unroll
        for (int i = 0; i < 4; i++)
            *(float4*)&qreg[qq][i * 4] =
                *(const float4*)&Qb[(size_t)(NUM_CLS + l0 + qi0 + qq) * 64 + dof + i * 4];
    __syncthreads();

    for (int ri = jp; ri < 70; ri += 2) {
        const __half* kr = (ri < 4) ? &kch[ri * 64 + dof]
                                    : &ksh[(qi0 + ri - 4) * KSH + dof];
        float kf[16];
        ld16h(kr, kf);
        float acc0 = 0.f, acc1 = 0.f;
#pragma unroll
        for (int dd = 0; dd < 16; dd++) {
            acc0 = fmaf(qreg[0][dd], kf[dd], acc0);
            acc1 = fmaf(qreg[1][dd], kf[dd], acc1);
        }
        acc0 += __shfl_xor_sync(0xffffffffu, acc0, 1);
        acc0 += __shfl_xor_sync(0xffffffffu, acc0, 2);
        acc1 += __shfl_xor_sync(0xffffffffu, acc1, 1);
        acc1 += __shfl_xor_sync(0xffffffffu, acc1, 2);
        if (dc == 0) {
            if (ri < 4) {
                sc[qi0 * 72 + ri] = acc0 * 0.125f;
                sc[(qi0 + 1) * 72 + ri] = acc1 * 0.125f;
            } else {
                int rw = ri - 4;
                int pos = l0 + qi0 + rw - WIN;
                bool ok = (pos >= 0) && (pos < L_PAT);
                if (rw <= 64) sc[qi0 * 72 + 4 + rw] = ok ? acc0 * 0.125f : -1e30f;
                int w1 = rw - 1;
                if (w1 >= 0) sc[(qi0 + 1) * 72 + 4 + w1] = ok ? acc1 * 0.125f : -1e30f;
            }
        }
    }
    __syncthreads();

    {
        int row = tid >> 2, sub = tid & 3;
        float* srow = &sc[row * 72];
        float m = -INFINITY;
        for (int j = sub; j < CTX; j += 4) m = fmaxf(m, srow[j]);
        m = fmaxf(m, __shfl_xor_sync(0xffffffffu, m, 1));
        m = fmaxf(m, __shfl_xor_sync(0xffffffffu, m, 2));
        float sum = 0.f;
        for (int j = sub; j < CTX; j += 4) {
            float p = fexp(srow[j] - m);
            srow[j] = p;
            sum += p;
        }
        sum += __shfl_xor_sync(0xffffffffu, sum, 1);
        sum += __shfl_xor_sync(0xffffffffu, sum, 2);
        float inv = 1.0f / sum;
        for (int j = sub; j < CTX; j += 4) srow[j] *= inv;
    }
    __syncthreads();

    float oacc[2][16];
#pragma unroll
    for (int qq = 0; qq < 2; qq++)
#pragma unroll
        for (int dd = 0; dd < 16; dd++) oacc[qq][dd] = 0.f;

    for (int ri = jp; ri < 70; ri += 2) {
        const __half* vr;
        float p0, p1;
        if (ri < 4) {
            vr = &vch[ri * 64 + dof];
            p0 = sc[qi0 * 72 + ri];
            p1 = sc[(qi0 + 1) * 72 + ri];
        } else {
            int rw = ri - 4;
            vr = &vsh[(qi0 + rw) * KSH + dof];
            p0 = (rw <= 64) ? sc[qi0 * 72 + 4 + rw] : 0.f;
            int w1 = rw - 1;
            p1 = (w1 >= 0) ? sc[(qi0 + 1) * 72 + 4 + w1] : 0.f;
        }
        float vf[16];
        ld16h(vr, vf);
#pragma unroll
        for (int dd = 0; dd < 16; dd++) {
            oacc[0][dd] = fmaf(p0, vf[dd], oacc[0][dd]);
            oacc[1][dd] = fmaf(p1, vf[dd], oacc[1][dd]);
        }
    }
#pragma unroll
    for (int qq = 0; qq < 2; qq++)
#pragma unroll
        for (int dd = 0; dd < 16; dd++)
            oacc[qq][dd] += __shfl_xor_sync(0xffffffffu, oacc[qq][dd], 4);

    if (jp == 0) {
#pragma unroll
        for (int qq = 0; qq < 2; qq++)
#pragma unroll
            for (int i = 0; i < 4; i++)
                *(float4*)&g_attn[(size_t)(NUM_CLS + l0 + qi0 + qq) * 512 + h * 64 + dof + i * 4] =
                    *(float4*)&oacc[qq][i * 4];
    }
}

// ---------------------------------------------------------------------------
extern "C" void kernel_launch(void* const* d_in, const int* in_sizes, int n_in,
                              void* d_out, int out_size) {
    const float* x      = (const float*)d_in[0];
    const float* coords = (const float*)d_in[1];
    const float* w_qkv  = (const float*)d_in[2];
    const float* b_qkv  = (const float*)d_in[3];
    const float* w_out  = (const float*)d_in[4];
    const float* b_out  = (const float*)d_in[5];
    float* out = (float*)d_out;

    float* attn_ptr = nullptr;
    cudaGetSymbolAddress((void**)&attn_ptr, g_attn);
    __half *xf, *af, *wqh, *wql, *woh, *wol;
    cudaGetSymbolAddress((void**)&xf, g_xf);
    cudaGetSymbolAddress((void**)&af, g_af);
    cudaGetSymbolAddress((void**)&wqh, g_wqh);
    cudaGetSymbolAddress((void**)&wql, g_wql);
    cudaGetSymbolAddress((void**)&woh, g_woh);
    cudaGetSymbolAddress((void**)&wol, g_wol);

    cudaFuncSetAttribute(gemm_f16x2<0>, cudaFuncAttributeMaxDynamicSharedMemorySize, GEMM_SMEM);
    cudaFuncSetAttribute(gemm_f16x2<1>, cudaFuncAttributeMaxDynamicSharedMemorySize, GEMM_SMEM);
    cudaFuncSetAttribute(patch_attn_kernel, cudaFuncAttributeMaxDynamicSharedMemorySize, PATCH_SMEM);

    const int NA4 = S_TOT * GK / 4;

    // 1. converts + weight splits + rope table
    tof16_kernel<<<(NA4 + 255) / 256, 256>>>(x, xf, NA4);
    wsplit_kernel<<<(1536 * GK / 4 + 255) / 256, 256>>>(w_qkv, wqh, wql, 1536 * GK / 4);
    wsplit_kernel<<<(512 * GK / 4 + 255) / 256, 256>>>(w_out, woh, wol, 512 * GK / 4);
    rope_table_kernel<<<(L_PAT * 32) / 256, 256>>>(coords);

    // 2. QKV GEMM (rope fused) -> g_qkv scatter
    {
        dim3 grid(1536 / 128, (S_TOT + 127) / 128);
        gemm_f16x2<1><<<grid, 256, GEMM_SMEM>>>(xf, wqh, wql, b_qkv, nullptr, S_TOT, 0);
    }
    // 3. CLS attention + combine
    {
        dim3 grid(8, 8);
        cls_part_kernel<<<grid, 256>>>();
        cls_combine_kernel<<<32, 64>>>();
    }
    // 4. Patch attention
    {
        dim3 grid(L_PAT / 64, H_NUM);
        patch_attn_kernel<<<grid, 256, PATCH_SMEM>>>();
    }
    // 5. convert attn, out projection
    tof16_kernel<<<(NA4 + 255) / 256, 256>>>(attn_ptr, af, NA4);
    {
        dim3 grid(512 / 128, (S_TOT + 127) / 128);
        gemm_f16x2<0><<<grid, 256, GEMM_SMEM>>>(af, woh, wol, b_out, out, S_TOT, 512);
    }
}

// round 12
// speedup vs baseline: 1.7330x; 1.2314x over previous
#include <cuda_runtime.h>
#include <cuda_fp16.h>
#include <cuda_bf16.h>
#include <math.h>
#include <stdint.h>

#define S_TOT 8196
#define L_PAT 8192
#define H_NUM 8
#define HD 64
#define NUM_CLS 4
#define WIN 32
#define WLEN 65
#define CTX 69
#define GK 512

// scratch
__device__ float g_qkv[3ull * H_NUM * S_TOT * HD];
__device__ float g_attn[(size_t)S_TOT * 512];
__device__ float g_clsp[32 * 8 * 66];
__device__ float2 g_rtab[(size_t)L_PAT * 32];
__device__ __half g_xf[(size_t)S_TOT * GK];       // x as fp16
__device__ __half g_af[(size_t)S_TOT * GK];       // attn as fp16
__device__ __half g_wqf[1536 * GK];
__device__ __half g_wof[512 * GK];

__constant__ float c_ftbl[16] = {
    1.0f, 0.5623413252f, 0.3162277660f, 0.1778279410f,
    0.1f, 0.05623413252f, 0.03162277660f, 0.01778279410f,
    0.01f, 0.005623413252f, 0.003162277660f, 0.001778279410f,
    0.001f, 0.0005623413252f, 0.0003162277660f, 0.0001778279410f
};

extern __shared__ char dynsm[];

__device__ __forceinline__ uint32_t smem_u32(const void* p) {
    uint32_t a;
    asm("{ .reg .u64 t; cvta.to.shared.u64 t, %1; cvt.u32.u64 %0, t; }" : "=r"(a) : "l"(p));
    return a;
}
__device__ __forceinline__ void ldm_x4(uint32_t* r, uint32_t addr) {
    asm volatile("ldmatrix.sync.aligned.m8n8.x4.shared.b16 {%0,%1,%2,%3}, [%4];"
                 : "=r"(r[0]), "=r"(r[1]), "=r"(r[2]), "=r"(r[3]) : "r"(addr));
}
__device__ __forceinline__ void mma_h(float* c, const uint32_t* a, uint32_t b0, uint32_t b1) {
    asm volatile("mma.sync.aligned.m16n8k16.row.col.f32.f16.f16.f32 "
                 "{%0,%1,%2,%3}, {%4,%5,%6,%7}, {%8,%9}, {%0,%1,%2,%3};"
                 : "+f"(c[0]), "+f"(c[1]), "+f"(c[2]), "+f"(c[3])
                 : "r"(a[0]), "r"(a[1]), "r"(a[2]), "r"(a[3]), "r"(b0), "r"(b1));
}
__device__ __forceinline__ uint32_t packf16(float a, float b) {
    __half2 t = __floats2half2_rn(a, b);
    return *(uint32_t*)&t;
}
__device__ __forceinline__ void cp16(uint32_t dst, const void* src, int sz) {
    asm volatile("cp.async.cg.shared.global [%0], [%1], 16, %2;"
                 :: "r"(dst), "l"(src), "r"(sz));
}
#define CP_COMMIT() asm volatile("cp.async.commit_group;" ::: "memory")
#define CP_WAIT0()  asm volatile("cp.async.wait_group 0;" ::: "memory")

// fast exp on FMA pipe (x <= 0 domain)
__device__ __forceinline__ float fexp(float x) {
    x = fmaxf(x, -80.0f);
    float z = fmaf(x, 1.442695041f, 12582912.0f);
    float n = z - 12582912.0f;
    float f = fmaf(x, 1.442695041f, -n);
    float r = 1.3333558e-3f;
    r = fmaf(r, f, 9.6181291e-3f);
    r = fmaf(r, f, 5.5504109e-2f);
    r = fmaf(r, f, 2.4022651e-1f);
    r = fmaf(r, f, 6.9314718e-1f);
    r = fmaf(r, f, 1.0f);
    return r * __int_as_float(((int)n + 127) << 23);
}
__device__ __forceinline__ void ld16h(const __half* p, float* out) {
    uint4 u0 = *(const uint4*)p;
    uint4 u1 = *(const uint4*)(p + 8);
    const __half2* h0 = (const __half2*)&u0;
    const __half2* h1 = (const __half2*)&u1;
#pragma unroll
    for (int j = 0; j < 4; j++) {
        float2 f = __half22float2(h0[j]);
        out[2 * j] = f.x; out[2 * j + 1] = f.y;
    }
#pragma unroll
    for (int j = 0; j < 4; j++) {
        float2 f = __half22float2(h1[j]);
        out[8 + 2 * j] = f.x; out[8 + 2 * j + 1] = f.y;
    }
}

// ---------------------------------------------------------------------------
// fp32 -> fp16 convert
// ---------------------------------------------------------------------------
__global__ void tof16_kernel(const float* __restrict__ src,
                             __half* __restrict__ dst, int n4) {
    int i = blockIdx.x * 256 + threadIdx.x;
    if (i >= n4) return;
    float4 v = *(const float4*)(src + (size_t)i * 4);
    *(uint2*)(dst + (size_t)i * 4) = make_uint2(packf16(v.x, v.y), packf16(v.z, v.w));
}

// ---------------------------------------------------------------------------
// rope cos/sin table
// ---------------------------------------------------------------------------
__global__ void rope_table_kernel(const float* __restrict__ coords) {
    int idx = blockIdx.x * 256 + threadIdx.x;
    int l = idx >> 5, p = idx & 31;
    float cx = coords[2 * l + 0];
    float cy = coords[2 * l + 1];
    float freq = c_ftbl[p & 15];
    float coord = ((p < 16) ? cx : cy) * 1e-5f;
    float s, c;
    __sincosf(coord * freq, &s, &c);
    g_rtab[idx] = make_float2(c, s);
}

// ---------------------------------------------------------------------------
// plain fp16 mma.sync GEMM (single pass), cp.async double buffer.
// 256 threads, 8 warps (2x4), CTA tile 128x128, warp tile 64x32, k-chunk 64.
// MODE 1 fuses RoPE in epilogue.
// ---------------------------------------------------------------------------
#define SMS 72
#define TILE_B (128 * SMS * 2)           // 18432 B per tile
#define STAGE_B (2 * TILE_B)             // A, B = 36864 B
#define GEMM_SMEM (2 * STAGE_B)          // 73728 B

template<int MODE>
__launch_bounds__(256)
__global__ void gemm_f16(const __half* __restrict__ A,
                         const __half* __restrict__ B,
                         const float* __restrict__ bias,
                         float* __restrict__ C, int M, int Ntot) {
    const int tid = threadIdx.x;
    const int wid = tid >> 5;
    const int lane = tid & 31;
    const int wm = (wid >> 2) * 64;
    const int wn = (wid & 3) * 32;
    const int bm = blockIdx.y * 128;
    const int bn = blockIdx.x * 128;

    float c[4][4][4];
#pragma unroll
    for (int i = 0; i < 4; i++)
#pragma unroll
        for (int j = 0; j < 4; j++)
#pragma unroll
            for (int r = 0; r < 4; r++) c[i][j][r] = 0.f;

    const uint32_t smb = smem_u32(dynsm);
    const int lrow = lane & 15;
    const int lcol = (lane >> 4) * 8;

    auto cp_chunk = [&](int ch, int st) {
        uint32_t sb = smb + st * STAGE_B;
#pragma unroll
        for (int it = 0; it < 8; it++) {
            int idx = tid + it * 256;
            int tile = idx >> 10;        // 0..1
            int slot = idx & 1023;
            int row = slot >> 3;
            int c16 = slot & 7;
            uint32_t dst = sb + tile * TILE_B + row * (SMS * 2) + c16 * 16;
            if (tile == 0) {
                int gr = bm + row;
                cp16(dst, A + (size_t)gr * GK + ch * 64 + c16 * 8, gr < M ? 16 : 0);
            } else {
                cp16(dst, B + (size_t)(bn + row) * GK + ch * 64 + c16 * 8, 16);
            }
        }
        CP_COMMIT();
    };

    cp_chunk(0, 0);

    for (int ch = 0; ch < GK / 64; ch++) {
        int st = ch & 1;
        CP_WAIT0();
        __syncthreads();
        if (ch < GK / 64 - 1) cp_chunk(ch + 1, st ^ 1);

        uint32_t a_b = smb + st * STAGE_B;
        uint32_t b_b = a_b + TILE_B;

#pragma unroll
        for (int kk = 0; kk < 4; kk++) {
            uint32_t af[4][4], bf[2][4];
#pragma unroll
            for (int mt = 0; mt < 4; mt++) {
                uint32_t off = ((wm + mt * 16 + lrow) * SMS + kk * 16 + lcol) * 2;
                ldm_x4(af[mt], a_b + off);
            }
#pragma unroll
            for (int g = 0; g < 2; g++) {
                uint32_t off = ((wn + g * 16 + lrow) * SMS + kk * 16 + lcol) * 2;
                ldm_x4(bf[g], b_b + off);
            }
#pragma unroll
            for (int mt = 0; mt < 4; mt++) {
#pragma unroll
                for (int nt = 0; nt < 4; nt++) {
                    int g = nt >> 1, s = nt & 1;
                    mma_h(c[mt][nt], af[mt], bf[g][s], bf[g][s + 2]);
                }
            }
        }
    }

    const int gid = lane >> 2;
    const int tig = lane & 3;
#pragma unroll
    for (int mt = 0; mt < 4; mt++) {
#pragma unroll
        for (int nt = 0; nt < 4; nt++) {
            int n = bn + wn + nt * 8 + tig * 2;
            float bx = bias[n], by = bias[n + 1];
            int m0 = bm + wm + mt * 16 + gid;
#pragma unroll
            for (int half = 0; half < 2; half++) {
                int m = m0 + half * 8;
                if (m >= M) continue;
                float vx = c[mt][nt][half * 2 + 0] + bx;
                float vy = c[mt][nt][half * 2 + 1] + by;
                if (MODE == 0) {
                    *(float2*)&C[(size_t)m * Ntot + n] = make_float2(vx, vy);
                } else {
                    int sel = n >> 9, h = (n >> 6) & 7, d = n & 63;
                    if (sel < 2 && m >= NUM_CLS) {
                        float2 cs = g_rtab[(size_t)(m - NUM_CLS) * 32 + (d >> 1)];
                        float rx = vx * cs.x - vy * cs.y;
                        float ry = vy * cs.x + vx * cs.y;
                        vx = rx; vy = ry;
                    }
                    *(float2*)&g_qkv[(((size_t)(sel * 8 + h) * S_TOT) + m) * 64 + d] =
                        make_float2(vx, vy);
                }
            }
        }
    }
}

// ---------------------------------------------------------------------------
// CLS attention: block = (h, chunk), all 4 cls queries together.
// ---------------------------------------------------------------------------
#define CCHUNK 1025
#define SCB 1028

__launch_bounds__(256)
__global__ void cls_part_kernel() {
    __shared__ float qs[4 * 64];
    __shared__ float scb[4 * SCB];
    __shared__ float red[4][8];
    __shared__ float gm[4], gs[4];
    __shared__ float osum[8][4][64];

    int h = blockIdx.x;
    int chunk = blockIdx.y;
    int k0 = chunk * CCHUNK;
    int k1 = min(S_TOT, k0 + CCHUNK);
    int nk = k1 - k0;
    int tid = threadIdx.x;
    int lane = tid & 31, w = tid >> 5;

    const float* Kb = &g_qkv[(size_t)(8 + h) * S_TOT * 64];
    const float* Vb = &g_qkv[(size_t)(16 + h) * S_TOT * 64];

    {
        int ci = tid >> 6, d = tid & 63;
        qs[tid] = g_qkv[(((size_t)h * S_TOT) + ci) * 64 + d];
    }
    __syncthreads();

    float lmax[4] = {-INFINITY, -INFINITY, -INFINITY, -INFINITY};
    for (int s = tid; s < nk; s += 256) {
        const float4* kr = (const float4*)(Kb + (size_t)(k0 + s) * 64);
        float a[4] = {0.f, 0.f, 0.f, 0.f};
#pragma unroll
        for (int i = 0; i < 16; i++) {
            float4 kv = kr[i];
#pragma unroll
            for (int ci = 0; ci < 4; ci++) {
                float4 qv = *(float4*)&qs[ci * 64 + i * 4];
                a[ci] += kv.x * qv.x + kv.y * qv.y + kv.z * qv.z + kv.w * qv.w;
            }
        }
#pragma unroll
        for (int ci = 0; ci < 4; ci++) {
            float sa = a[ci] * 0.125f;
            scb[ci * SCB + s] = sa;
            lmax[ci] = fmaxf(lmax[ci], sa);
        }
    }
#pragma unroll
    for (int ci = 0; ci < 4; ci++) {
#pragma unroll
        for (int o = 16; o > 0; o >>= 1)
            lmax[ci] = fmaxf(lmax[ci], __shfl_xor_sync(0xffffffffu, lmax[ci], o));
        if (lane == 0) red[ci][w] = lmax[ci];
    }
    __syncthreads();
    float gmaxv[4];
#pragma unroll
    for (int ci = 0; ci < 4; ci++) {
        float m = red[ci][0];
#pragma unroll
        for (int i = 1; i < 8; i++) m = fmaxf(m, red[ci][i]);
        gmaxv[ci] = m;
    }
    __syncthreads();

    float lsum[4] = {0.f, 0.f, 0.f, 0.f};
    for (int s = tid; s < nk; s += 256) {
#pragma unroll
        for (int ci = 0; ci < 4; ci++) {
            float p = __expf(scb[ci * SCB + s] - gmaxv[ci]);
            scb[ci * SCB + s] = p;
            lsum[ci] += p;
        }
    }
#pragma unroll
    for (int ci = 0; ci < 4; ci++) {
#pragma unroll
        for (int o = 16; o > 0; o >>= 1)
            lsum[ci] += __shfl_xor_sync(0xffffffffu, lsum[ci], o);
        if (lane == 0) red[ci][w] = lsum[ci];
    }
    __syncthreads();
    if (tid < 4) {
        float ssum = 0.f;
#pragma unroll
        for (int i = 0; i < 8; i++) ssum += red[tid][i];
        gs[tid] = ssum;
        gm[tid] = gmaxv[tid];
    }

    int sl = tid >> 2, dcc = tid & 3, dof = dcc * 16;
    float acc[4][16];
#pragma unroll
    for (int ci = 0; ci < 4; ci++)
#pragma unroll
        for (int dd = 0; dd < 16; dd++) acc[ci][dd] = 0.f;

    for (int s = sl; s < nk; s += 64) {
        float p[4];
#pragma unroll
        for (int ci = 0; ci < 4; ci++) p[ci] = scb[ci * SCB + s];
        const float* vr = Vb + (size_t)(k0 + s) * 64 + dof;
        float vf[16];
#pragma unroll
        for (int i = 0; i < 4; i++) *(float4*)&vf[i * 4] = *(const float4*)&vr[i * 4];
#pragma unroll
        for (int dd = 0; dd < 16; dd++) {
            float vv = vf[dd];
            acc[0][dd] = fmaf(p[0], vv, acc[0][dd]);
            acc[1][dd] = fmaf(p[1], vv, acc[1][dd]);
            acc[2][dd] = fmaf(p[2], vv, acc[2][dd]);
            acc[3][dd] = fmaf(p[3], vv, acc[3][dd]);
        }
    }
#pragma unroll
    for (int o = 4; o <= 16; o <<= 1)
#pragma unroll
        for (int ci = 0; ci < 4; ci++)
#pragma unroll
            for (int dd = 0; dd < 16; dd++)
                acc[ci][dd] += __shfl_xor_sync(0xffffffffu, acc[ci][dd], o);

    if ((lane & 28) == 0) {
#pragma unroll
        for (int ci = 0; ci < 4; ci++)
#pragma unroll
            for (int dd = 0; dd < 16; dd++)
                osum[w][ci][dof + dd] = acc[ci][dd];
    }
    __syncthreads();

    {
        int ci = tid >> 6, d = tid & 63;
        float v = 0.f;
#pragma unroll
        for (int i = 0; i < 8; i++) v += osum[i][ci][d];
        float* dst = &g_clsp[((size_t)(h * 4 + ci) * 8 + chunk) * 66];
        dst[2 + d] = v;
        if (d == 0) { dst[0] = gm[ci]; dst[1] = gs[ci]; }
    }
}

__global__ void cls_combine_kernel() {
    int hc = blockIdx.x;
    int h = hc >> 2, ci = hc & 3;
    int d = threadIdx.x;
    const float* base = &g_clsp[(size_t)hc * 8 * 66];
    float M = -INFINITY;
#pragma unroll
    for (int c = 0; c < 8; c++) M = fmaxf(M, base[c * 66]);
    float S = 0.f, A = 0.f;
#pragma unroll
    for (int c = 0; c < 8; c++) {
        float w = __expf(base[c * 66] - M);
        S = fmaf(base[c * 66 + 1], w, S);
        A = fmaf(base[c * 66 + 2 + d], w, A);
    }
    g_attn[(size_t)ci * 512 + h * 64 + d] = A / S;
}

// ---------------------------------------------------------------------------
// Patch attention (fp16 K/V smem, 2 queries/thread)
// ---------------------------------------------------------------------------
#define KSH 72
#define PATCH_SMEM ((128 * KSH * 2 + 256 + 256) * 2 + (64 * 72) * 4)

__launch_bounds__(256, 3)
__global__ void patch_attn_kernel() {
    __half* ksh = (__half*)dynsm;
    __half* vsh = ksh + 128 * KSH;
    __half* kch = vsh + 128 * KSH;
    __half* vch = kch + 256;
    float* sc = (float*)(vch + 256);

    int h = blockIdx.y;
    int l0 = blockIdx.x * 64;
    int tid = threadIdx.x;

    const float* Qb = &g_qkv[(size_t)h * S_TOT * 64];
    const float* Kb = &g_qkv[(size_t)(8 + h) * S_TOT * 64];
    const float* Vb = &g_qkv[(size_t)(16 + h) * S_TOT * 64];

    for (int i = tid; i < 128 * 16; i += 256) {
        int r = i >> 4, c4 = (i & 15) << 2;
        int kp = l0 - WIN + r;
        float4 kv = make_float4(0.f, 0.f, 0.f, 0.f);
        float4 vv = make_float4(0.f, 0.f, 0.f, 0.f);
        if (kp >= 0 && kp < L_PAT) {
            kv = *(const float4*)&Kb[(size_t)(NUM_CLS + kp) * 64 + c4];
            vv = *(const float4*)&Vb[(size_t)(NUM_CLS + kp) * 64 + c4];
        }
        *(uint2*)&ksh[r * KSH + c4] = make_uint2(packf16(kv.x, kv.y), packf16(kv.z, kv.w));
        *(uint2*)&vsh[r * KSH + c4] = make_uint2(packf16(vv.x, vv.y), packf16(vv.z, vv.w));
    }
    if (tid < 64) {
        int r = tid >> 4, c4 = (tid & 15) << 2;
        float4 kv = *(const float4*)&Kb[(size_t)r * 64 + c4];
        float4 vv = *(const float4*)&Vb[(size_t)r * 64 + c4];
        *(uint2*)&kch[r * 64 + c4] = make_uint2(packf16(kv.x, kv.y), packf16(kv.z, kv.w));
        *(uint2*)&vch[r * 64 + c4] = make_uint2(packf16(vv.x, vv.y), packf16(vv.z, vv.w));
    }

    const int dc = tid & 3;
    const int jp = (tid >> 2) & 1;
    const int qg = tid >> 3;
    const int qi0 = qg * 2;
    const int dof = dc * 16;

    float qreg[2][16];
#pragma unroll
    for (int qq = 0; qq < 2; qq++)
#pragma unroll
        for (int i = 0; i < 4; i++)
            *(float4*)&qreg[qq][i * 4] =
                *(const float4*)&Qb[(size_t)(NUM_CLS + l0 + qi0 + qq) * 64 + dof + i * 4];
    __syncthreads();

    for (int ri = jp; ri < 70; ri += 2) {
        const __half* kr = (ri < 4) ? &kch[ri * 64 + dof]
                                    : &ksh[(qi0 + ri - 4) * KSH + dof];
        float kf[16];
        ld16h(kr, kf);
        float acc0 = 0.f, acc1 = 0.f;
#pragma unroll
        for (int dd = 0; dd < 16; dd++) {
            acc0 = fmaf(qreg[0][dd], kf[dd], acc0);
            acc1 = fmaf(qreg[1][dd], kf[dd], acc1);
        }
        acc0 += __shfl_xor_sync(0xffffffffu, acc0, 1);
        acc0 += __shfl_xor_sync(0xffffffffu, acc0, 2);
        acc1 += __shfl_xor_sync(0xffffffffu, acc1, 1);
        acc1 += __shfl_xor_sync(0xffffffffu, acc1, 2);
        if (dc == 0) {
            if (ri < 4) {
                sc[qi0 * 72 + ri] = acc0 * 0.125f;
                sc[(qi0 + 1) * 72 + ri] = acc1 * 0.125f;
            } else {
                int rw = ri - 4;
                int pos = l0 + qi0 + rw - WIN;
                bool ok = (pos >= 0) && (pos < L_PAT);
                if (rw <= 64) sc[qi0 * 72 + 4 + rw] = ok ? acc0 * 0.125f : -1e30f;
                int w1 = rw - 1;
                if (w1 >= 0) sc[(qi0 + 1) * 72 + 4 + w1] = ok ? acc1 * 0.125f : -1e30f;
            }
        }
    }
    __syncthreads();

    {
        int row = tid >> 2, sub = tid & 3;
        float* srow = &sc[row * 72];
        float m = -INFINITY;
        for (int j = sub; j < CTX; j += 4) m = fmaxf(m, srow[j]);
        m = fmaxf(m, __shfl_xor_sync(0xffffffffu, m, 1));
        m = fmaxf(m, __shfl_xor_sync(0xffffffffu, m, 2));
        float sum = 0.f;
        for (int j = sub; j < CTX; j += 4) {
            float p = fexp(srow[j] - m);
            srow[j] = p;
            sum += p;
        }
        sum += __shfl_xor_sync(0xffffffffu, sum, 1);
        sum += __shfl_xor_sync(0xffffffffu, sum, 2);
        float inv = 1.0f / sum;
        for (int j = sub; j < CTX; j += 4) srow[j] *= inv;
    }
    __syncthreads();

    float oacc[2][16];
#pragma unroll
    for (int qq = 0; qq < 2; qq++)
#pragma unroll
        for (int dd = 0; dd < 16; dd++) oacc[qq][dd] = 0.f;

    for (int ri = jp; ri < 70; ri += 2) {
        const __half* vr;
        float p0, p1;
        if (ri < 4) {
            vr = &vch[ri * 64 + dof];
            p0 = sc[qi0 * 72 + ri];
            p1 = sc[(qi0 + 1) * 72 + ri];
        } else {
            int rw = ri - 4;
            vr = &vsh[(qi0 + rw) * KSH + dof];
            p0 = (rw <= 64) ? sc[qi0 * 72 + 4 + rw] : 0.f;
            int w1 = rw - 1;
            p1 = (w1 >= 0) ? sc[(qi0 + 1) * 72 + 4 + w1] : 0.f;
        }
        float vf[16];
        ld16h(vr, vf);
#pragma unroll
        for (int dd = 0; dd < 16; dd++) {
            oacc[0][dd] = fmaf(p0, vf[dd], oacc[0][dd]);
            oacc[1][dd] = fmaf(p1, vf[dd], oacc[1][dd]);
        }
    }
#pragma unroll
    for (int qq = 0; qq < 2; qq++)
#pragma unroll
        for (int dd = 0; dd < 16; dd++)
            oacc[qq][dd] += __shfl_xor_sync(0xffffffffu, oacc[qq][dd], 4);

    if (jp == 0) {
#pragma unroll
        for (int qq = 0; qq < 2; qq++)
#pragma unroll
            for (int i = 0; i < 4; i++)
                *(float4*)&g_attn[(size_t)(NUM_CLS + l0 + qi0 + qq) * 512 + h * 64 + dof + i * 4] =
                    *(float4*)&oacc[qq][i * 4];
    }
}

// ---------------------------------------------------------------------------
extern "C" void kernel_launch(void* const* d_in, const int* in_sizes, int n_in,
                              void* d_out, int out_size) {
    const float* x      = (const float*)d_in[0];
    const float* coords = (const float*)d_in[1];
    const float* w_qkv  = (const float*)d_in[2];
    const float* b_qkv  = (const float*)d_in[3];
    const float* w_out  = (const float*)d_in[4];
    const float* b_out  = (const float*)d_in[5];
    float* out = (float*)d_out;

    float* attn_ptr = nullptr;
    cudaGetSymbolAddress((void**)&attn_ptr, g_attn);
    __half *xf, *af, *wqf, *wof;
    cudaGetSymbolAddress((void**)&xf, g_xf);
    cudaGetSymbolAddress((void**)&af, g_af);
    cudaGetSymbolAddress((void**)&wqf, g_wqf);
    cudaGetSymbolAddress((void**)&wof, g_wof);

    cudaFuncSetAttribute(gemm_f16<0>, cudaFuncAttributeMaxDynamicSharedMemorySize, GEMM_SMEM);
    cudaFuncSetAttribute(gemm_f16<1>, cudaFuncAttributeMaxDynamicSharedMemorySize, GEMM_SMEM);
    cudaFuncSetAttribute(patch_attn_kernel, cudaFuncAttributeMaxDynamicSharedMemorySize, PATCH_SMEM);

    const int NA4 = S_TOT * GK / 4;

    // 1. converts + rope table
    tof16_kernel<<<(NA4 + 255) / 256, 256>>>(x, xf, NA4);
    tof16_kernel<<<(1536 * GK / 4 + 255) / 256, 256>>>(w_qkv, wqf, 1536 * GK / 4);
    tof16_kernel<<<(512 * GK / 4 + 255) / 256, 256>>>(w_out, wof, 512 * GK / 4);
    rope_table_kernel<<<(L_PAT * 32) / 256, 256>>>(coords);

    // 2. QKV GEMM (rope fused) -> g_qkv scatter
    {
        dim3 grid(1536 / 128, (S_TOT + 127) / 128);
        gemm_f16<1><<<grid, 256, GEMM_SMEM>>>(xf, wqf, b_qkv, nullptr, S_TOT, 0);
    }
    // 3. CLS attention + combine
    {
        dim3 grid(8, 8);
        cls_part_kernel<<<grid, 256>>>();
        cls_combine_kernel<<<32, 64>>>();
    }
    // 4. Patch attention
    {
        dim3 grid(L_PAT / 64, H_NUM);
        patch_attn_kernel<<<grid, 256, PATCH_SMEM>>>();
    }
    // 5. convert attn, out projection
    tof16_kernel<<<(NA4 + 255) / 256, 256>>>(attn_ptr, af, NA4);
    {
        dim3 grid(512 / 128, (S_TOT + 127) / 128);
        gemm_f16<0><<<grid, 256, GEMM_SMEM>>>(af, wof, b_out, out, S_TOT, 512);
    }
}

// round 13
// speedup vs baseline: 2.1152x; 1.2205x over previous
#include <cuda_runtime.h>
#include <cuda_fp16.h>
#include <cuda_bf16.h>
#include <math.h>
#include <stdint.h>

#define S_TOT 8196
#define L_PAT 8192
#define H_NUM 8
#define HD 64
#define NUM_CLS 4
#define WIN 32
#define WLEN 65
#define CTX 69
#define GK 512

// scratch
__device__ float g_qkv[3ull * H_NUM * S_TOT * HD];
__device__ float g_clsp[32 * 8 * 66];
__device__ float2 g_rtab[(size_t)L_PAT * 32];
__device__ __half g_xf[(size_t)S_TOT * GK];       // x as fp16
__device__ __half g_af[(size_t)S_TOT * GK];       // attn output as fp16
__device__ __half g_wqf[1536 * GK];
__device__ __half g_wof[512 * GK];

__constant__ float c_ftbl[16] = {
    1.0f, 0.5623413252f, 0.3162277660f, 0.1778279410f,
    0.1f, 0.05623413252f, 0.03162277660f, 0.01778279410f,
    0.01f, 0.005623413252f, 0.003162277660f, 0.001778279410f,
    0.001f, 0.0005623413252f, 0.0003162277660f, 0.0001778279410f
};

extern __shared__ char dynsm[];

__device__ __forceinline__ uint32_t smem_u32(const void* p) {
    uint32_t a;
    asm("{ .reg .u64 t; cvta.to.shared.u64 t, %1; cvt.u32.u64 %0, t; }" : "=r"(a) : "l"(p));
    return a;
}
__device__ __forceinline__ void ldm_x4(uint32_t* r, uint32_t addr) {
    asm volatile("ldmatrix.sync.aligned.m8n8.x4.shared.b16 {%0,%1,%2,%3}, [%4];"
                 : "=r"(r[0]), "=r"(r[1]), "=r"(r[2]), "=r"(r[3]) : "r"(addr));
}
__device__ __forceinline__ void ldm_x4t(uint32_t* r, uint32_t addr) {
    asm volatile("ldmatrix.sync.aligned.m8n8.x4.trans.shared.b16 {%0,%1,%2,%3}, [%4];"
                 : "=r"(r[0]), "=r"(r[1]), "=r"(r[2]), "=r"(r[3]) : "r"(addr));
}
__device__ __forceinline__ void mma_h(float* c, const uint32_t* a, uint32_t b0, uint32_t b1) {
    asm volatile("mma.sync.aligned.m16n8k16.row.col.f32.f16.f16.f32 "
                 "{%0,%1,%2,%3}, {%4,%5,%6,%7}, {%8,%9}, {%0,%1,%2,%3};"
                 : "+f"(c[0]), "+f"(c[1]), "+f"(c[2]), "+f"(c[3])
                 : "r"(a[0]), "r"(a[1]), "r"(a[2]), "r"(a[3]), "r"(b0), "r"(b1));
}
__device__ __forceinline__ uint32_t packf16(float a, float b) {
    __half2 t = __floats2half2_rn(a, b);
    return *(uint32_t*)&t;
}
__device__ __forceinline__ void cp16(uint32_t dst, const void* src, int sz) {
    asm volatile("cp.async.cg.shared.global [%0], [%1], 16, %2;"
                 :: "r"(dst), "l"(src), "r"(sz));
}
#define CP_COMMIT() asm volatile("cp.async.commit_group;" ::: "memory")
#define CP_WAIT0()  asm volatile("cp.async.wait_group 0;" ::: "memory")

// fast exp on FMA pipe (x <= 0 domain)
__device__ __forceinline__ float fexp(float x) {
    x = fmaxf(x, -80.0f);
    float z = fmaf(x, 1.442695041f, 12582912.0f);
    float n = z - 12582912.0f;
    float f = fmaf(x, 1.442695041f, -n);
    float r = 1.3333558e-3f;
    r = fmaf(r, f, 9.6181291e-3f);
    r = fmaf(r, f, 5.5504109e-2f);
    r = fmaf(r, f, 2.4022651e-1f);
    r = fmaf(r, f, 6.9314718e-1f);
    r = fmaf(r, f, 1.0f);
    return r * __int_as_float(((int)n + 127) << 23);
}

// ---------------------------------------------------------------------------
// fp32 -> fp16 convert
// ---------------------------------------------------------------------------
__global__ void tof16_kernel(const float* __restrict__ src,
                             __half* __restrict__ dst, int n4) {
    int i = blockIdx.x * 256 + threadIdx.x;
    if (i >= n4) return;
    float4 v = *(const float4*)(src + (size_t)i * 4);
    *(uint2*)(dst + (size_t)i * 4) = make_uint2(packf16(v.x, v.y), packf16(v.z, v.w));
}

// ---------------------------------------------------------------------------
// rope cos/sin table
// ---------------------------------------------------------------------------
__global__ void rope_table_kernel(const float* __restrict__ coords) {
    int idx = blockIdx.x * 256 + threadIdx.x;
    int l = idx >> 5, p = idx & 31;
    float cx = coords[2 * l + 0];
    float cy = coords[2 * l + 1];
    float freq = c_ftbl[p & 15];
    float coord = ((p < 16) ? cx : cy) * 1e-5f;
    float s, c;
    __sincosf(coord * freq, &s, &c);
    g_rtab[idx] = make_float2(c, s);
}

// ---------------------------------------------------------------------------
// plain fp16 mma.sync GEMM (single pass), cp.async double buffer.
// ---------------------------------------------------------------------------
#define SMS 72
#define TILE_B (128 * SMS * 2)
#define STAGE_B (2 * TILE_B)
#define GEMM_SMEM (2 * STAGE_B)

template<int MODE>
__launch_bounds__(256)
__global__ void gemm_f16(const __half* __restrict__ A,
                         const __half* __restrict__ B,
                         const float* __restrict__ bias,
                         float* __restrict__ C, int M, int Ntot) {
    const int tid = threadIdx.x;
    const int wid = tid >> 5;
    const int lane = tid & 31;
    const int wm = (wid >> 2) * 64;
    const int wn = (wid & 3) * 32;
    const int bm = blockIdx.y * 128;
    const int bn = blockIdx.x * 128;

    float c[4][4][4];
#pragma unroll
    for (int i = 0; i < 4; i++)
#pragma unroll
        for (int j = 0; j < 4; j++)
#pragma unroll
            for (int r = 0; r < 4; r++) c[i][j][r] = 0.f;

    const uint32_t smb = smem_u32(dynsm);
    const int lrow = lane & 15;
    const int lcol = (lane >> 4) * 8;

    auto cp_chunk = [&](int ch, int st) {
        uint32_t sb = smb + st * STAGE_B;
#pragma unroll
        for (int it = 0; it < 8; it++) {
            int idx = tid + it * 256;
            int tile = idx >> 10;
            int slot = idx & 1023;
            int row = slot >> 3;
            int c16 = slot & 7;
            uint32_t dst = sb + tile * TILE_B + row * (SMS * 2) + c16 * 16;
            if (tile == 0) {
                int gr = bm + row;
                cp16(dst, A + (size_t)gr * GK + ch * 64 + c16 * 8, gr < M ? 16 : 0);
            } else {
                cp16(dst, B + (size_t)(bn + row) * GK + ch * 64 + c16 * 8, 16);
            }
        }
        CP_COMMIT();
    };

    cp_chunk(0, 0);

    for (int ch = 0; ch < GK / 64; ch++) {
        int st = ch & 1;
        CP_WAIT0();
        __syncthreads();
        if (ch < GK / 64 - 1) cp_chunk(ch + 1, st ^ 1);

        uint32_t a_b = smb + st * STAGE_B;
        uint32_t b_b = a_b + TILE_B;

#pragma unroll
        for (int kk = 0; kk < 4; kk++) {
            uint32_t af[4][4], bf[2][4];
#pragma unroll
            for (int mt = 0; mt < 4; mt++) {
                uint32_t off = ((wm + mt * 16 + lrow) * SMS + kk * 16 + lcol) * 2;
                ldm_x4(af[mt], a_b + off);
            }
#pragma unroll
            for (int g = 0; g < 2; g++) {
                uint32_t off = ((wn + g * 16 + lrow) * SMS + kk * 16 + lcol) * 2;
                ldm_x4(bf[g], b_b + off);
            }
#pragma unroll
            for (int mt = 0; mt < 4; mt++) {
#pragma unroll
                for (int nt = 0; nt < 4; nt++) {
                    int g = nt >> 1, s = nt & 1;
                    mma_h(c[mt][nt], af[mt], bf[g][s], bf[g][s + 2]);
                }
            }
        }
    }

    const int gid = lane >> 2;
    const int tig = lane & 3;
#pragma unroll
    for (int mt = 0; mt < 4; mt++) {
#pragma unroll
        for (int nt = 0; nt < 4; nt++) {
            int n = bn + wn + nt * 8 + tig * 2;
            float bx = bias[n], by = bias[n + 1];
            int m0 = bm + wm + mt * 16 + gid;
#pragma unroll
            for (int half = 0; half < 2; half++) {
                int m = m0 + half * 8;
                if (m >= M) continue;
                float vx = c[mt][nt][half * 2 + 0] + bx;
                float vy = c[mt][nt][half * 2 + 1] + by;
                if (MODE == 0) {
                    *(float2*)&C[(size_t)m * Ntot + n] = make_float2(vx, vy);
                } else {
                    int sel = n >> 9, h = (n >> 6) & 7, d = n & 63;
                    if (sel < 2 && m >= NUM_CLS) {
                        float2 cs = g_rtab[(size_t)(m - NUM_CLS) * 32 + (d >> 1)];
                        float rx = vx * cs.x - vy * cs.y;
                        float ry = vy * cs.x + vx * cs.y;
                        vx = rx; vy = ry;
                    }
                    *(float2*)&g_qkv[(((size_t)(sel * 8 + h) * S_TOT) + m) * 64 + d] =
                        make_float2(vx, vy);
                }
            }
        }
    }
}

// ---------------------------------------------------------------------------
// CLS attention split-K (unchanged) + combine writing fp16
// ---------------------------------------------------------------------------
#define CCHUNK 1025
#define SCBW 1028

__launch_bounds__(256)
__global__ void cls_part_kernel() {
    __shared__ float qs[4 * 64];
    __shared__ float scb[4 * SCBW];
    __shared__ float red[4][8];
    __shared__ float gm[4], gs[4];
    __shared__ float osum[8][4][64];

    int h = blockIdx.x;
    int chunk = blockIdx.y;
    int k0 = chunk * CCHUNK;
    int k1 = min(S_TOT, k0 + CCHUNK);
    int nk = k1 - k0;
    int tid = threadIdx.x;
    int lane = tid & 31, w = tid >> 5;

    const float* Kb = &g_qkv[(size_t)(8 + h) * S_TOT * 64];
    const float* Vb = &g_qkv[(size_t)(16 + h) * S_TOT * 64];

    {
        int ci = tid >> 6, d = tid & 63;
        qs[tid] = g_qkv[(((size_t)h * S_TOT) + ci) * 64 + d];
    }
    __syncthreads();

    float lmax[4] = {-INFINITY, -INFINITY, -INFINITY, -INFINITY};
    for (int s = tid; s < nk; s += 256) {
        const float4* kr = (const float4*)(Kb + (size_t)(k0 + s) * 64);
        float a[4] = {0.f, 0.f, 0.f, 0.f};
#pragma unroll
        for (int i = 0; i < 16; i++) {
            float4 kv = kr[i];
#pragma unroll
            for (int ci = 0; ci < 4; ci++) {
                float4 qv = *(float4*)&qs[ci * 64 + i * 4];
                a[ci] += kv.x * qv.x + kv.y * qv.y + kv.z * qv.z + kv.w * qv.w;
            }
        }
#pragma unroll
        for (int ci = 0; ci < 4; ci++) {
            float sa = a[ci] * 0.125f;
            scb[ci * SCBW + s] = sa;
            lmax[ci] = fmaxf(lmax[ci], sa);
        }
    }
#pragma unroll
    for (int ci = 0; ci < 4; ci++) {
#pragma unroll
        for (int o = 16; o > 0; o >>= 1)
            lmax[ci] = fmaxf(lmax[ci], __shfl_xor_sync(0xffffffffu, lmax[ci], o));
        if (lane == 0) red[ci][w] = lmax[ci];
    }
    __syncthreads();
    float gmaxv[4];
#pragma unroll
    for (int ci = 0; ci < 4; ci++) {
        float m = red[ci][0];
#pragma unroll
        for (int i = 1; i < 8; i++) m = fmaxf(m, red[ci][i]);
        gmaxv[ci] = m;
    }
    __syncthreads();

    float lsum[4] = {0.f, 0.f, 0.f, 0.f};
    for (int s = tid; s < nk; s += 256) {
#pragma unroll
        for (int ci = 0; ci < 4; ci++) {
            float p = __expf(scb[ci * SCBW + s] - gmaxv[ci]);
            scb[ci * SCBW + s] = p;
            lsum[ci] += p;
        }
    }
#pragma unroll
    for (int ci = 0; ci < 4; ci++) {
#pragma unroll
        for (int o = 16; o > 0; o >>= 1)
            lsum[ci] += __shfl_xor_sync(0xffffffffu, lsum[ci], o);
        if (lane == 0) red[ci][w] = lsum[ci];
    }
    __syncthreads();
    if (tid < 4) {
        float ssum = 0.f;
#pragma unroll
        for (int i = 0; i < 8; i++) ssum += red[tid][i];
        gs[tid] = ssum;
        gm[tid] = gmaxv[tid];
    }

    int sl = tid >> 2, dcc = tid & 3, dof = dcc * 16;
    float acc[4][16];
#pragma unroll
    for (int ci = 0; ci < 4; ci++)
#pragma unroll
        for (int dd = 0; dd < 16; dd++) acc[ci][dd] = 0.f;

    for (int s = sl; s < nk; s += 64) {
        float p[4];
#pragma unroll
        for (int ci = 0; ci < 4; ci++) p[ci] = scb[ci * SCBW + s];
        const float* vr = Vb + (size_t)(k0 + s) * 64 + dof;
        float vf[16];
#pragma unroll
        for (int i = 0; i < 4; i++) *(float4*)&vf[i * 4] = *(const float4*)&vr[i * 4];
#pragma unroll
        for (int dd = 0; dd < 16; dd++) {
            float vv = vf[dd];
            acc[0][dd] = fmaf(p[0], vv, acc[0][dd]);
            acc[1][dd] = fmaf(p[1], vv, acc[1][dd]);
            acc[2][dd] = fmaf(p[2], vv, acc[2][dd]);
            acc[3][dd] = fmaf(p[3], vv, acc[3][dd]);
        }
    }
#pragma unroll
    for (int o = 4; o <= 16; o <<= 1)
#pragma unroll
        for (int ci = 0; ci < 4; ci++)
#pragma unroll
            for (int dd = 0; dd < 16; dd++)
                acc[ci][dd] += __shfl_xor_sync(0xffffffffu, acc[ci][dd], o);

    if ((lane & 28) == 0) {
#pragma unroll
        for (int ci = 0; ci < 4; ci++)
#pragma unroll
            for (int dd = 0; dd < 16; dd++)
                osum[w][ci][dof + dd] = acc[ci][dd];
    }
    __syncthreads();

    {
        int ci = tid >> 6, d = tid & 63;
        float v = 0.f;
#pragma unroll
        for (int i = 0; i < 8; i++) v += osum[i][ci][d];
        float* dst = &g_clsp[((size_t)(h * 4 + ci) * 8 + chunk) * 66];
        dst[2 + d] = v;
        if (d == 0) { dst[0] = gm[ci]; dst[1] = gs[ci]; }
    }
}

__global__ void cls_combine_kernel() {
    int hc = blockIdx.x;
    int h = hc >> 2, ci = hc & 3;
    int d = threadIdx.x;
    const float* base = &g_clsp[(size_t)hc * 8 * 66];
    float M = -INFINITY;
#pragma unroll
    for (int c = 0; c < 8; c++) M = fmaxf(M, base[c * 66]);
    float S = 0.f, A = 0.f;
#pragma unroll
    for (int c = 0; c < 8; c++) {
        float w = __expf(base[c * 66] - M);
        S = fmaf(base[c * 66 + 1], w, S);
        A = fmaf(base[c * 66 + 2 + d], w, A);
    }
    g_af[(size_t)ci * 512 + h * 64 + d] = __float2half(A / S);
}

// ---------------------------------------------------------------------------
// Patch attention on tensor cores (flash-style).
// 256 threads = 8 warps: 4 m16-tiles x 2 k-halves (80 each).
// Slab: 160 rows (128 window + 4 cls + 28 zero). S in regs, softmax on frags,
// P split hi/lo fp16 in regs (exact), PV via ldmatrix.trans on V.
// ---------------------------------------------------------------------------
#define PST 72
#define SQ_E (64 * PST)
#define SK_E (160 * PST)
#define PATCH_SMEM ((SQ_E + 2 * SK_E) * 2 + 128 * 4 + 128 * 4 + 4 * 16 * 66 * 4)

__launch_bounds__(256)
__global__ void patch_attn_kernel() {
    __half* sQ = (__half*)dynsm;
    __half* sK = sQ + SQ_E;
    __half* sV = sK + SK_E;
    float* hm = (float*)(dynsm + (SQ_E + 2 * SK_E) * 2);
    float* hs = hm + 128;
    float* redb = hs + 128;   // [4][16][66]

    int h = blockIdx.y;
    int l0 = blockIdx.x * 64;
    int tid = threadIdx.x;

    const float* Qb = &g_qkv[(size_t)h * S_TOT * 64];
    const float* Kb = &g_qkv[(size_t)(8 + h) * S_TOT * 64];
    const float* Vb = &g_qkv[(size_t)(16 + h) * S_TOT * 64];

    // Q (scaled by 0.125)
    for (int i = tid; i < 64 * 8; i += 256) {
        int r = i >> 3, c8 = (i & 7) * 8;
        const float* src = &Qb[(size_t)(NUM_CLS + l0 + r) * 64 + c8];
        float4 a = *(const float4*)src;
        float4 b = *(const float4*)(src + 4);
        uint4 pk = make_uint4(packf16(a.x * 0.125f, a.y * 0.125f),
                              packf16(a.z * 0.125f, a.w * 0.125f),
                              packf16(b.x * 0.125f, b.y * 0.125f),
                              packf16(b.z * 0.125f, b.w * 0.125f));
        *(uint4*)&sQ[r * PST + c8] = pk;
    }
    // K/V slab: rows 0..127 window, 128..131 cls, 132..159 zero
    for (int i = tid; i < 160 * 8; i += 256) {
        int r = i >> 3, c8 = (i & 7) * 8;
        float4 ka = make_float4(0.f, 0.f, 0.f, 0.f), kb = ka, va = ka, vb = ka;
        if (r < 128) {
            int kp = l0 - WIN + r;
            if (kp >= 0 && kp < L_PAT) {
                const float* ks = &Kb[(size_t)(NUM_CLS + kp) * 64 + c8];
                const float* vs = &Vb[(size_t)(NUM_CLS + kp) * 64 + c8];
                ka = *(const float4*)ks; kb = *(const float4*)(ks + 4);
                va = *(const float4*)vs; vb = *(const float4*)(vs + 4);
            }
        } else if (r < 132) {
            const float* ks = &Kb[(size_t)(r - 128) * 64 + c8];
            const float* vs = &Vb[(size_t)(r - 128) * 64 + c8];
            ka = *(const float4*)ks; kb = *(const float4*)(ks + 4);
            va = *(const float4*)vs; vb = *(const float4*)(vs + 4);
        }
        *(uint4*)&sK[r * PST + c8] = make_uint4(packf16(ka.x, ka.y), packf16(ka.z, ka.w),
                                                packf16(kb.x, kb.y), packf16(kb.z, kb.w));
        *(uint4*)&sV[r * PST + c8] = make_uint4(packf16(va.x, va.y), packf16(va.z, va.w),
                                                packf16(vb.x, vb.y), packf16(vb.z, vb.w));
    }
    __syncthreads();

    const int wid = tid >> 5;
    const int lane = tid & 31;
    const int wm = (wid >> 1) * 16;       // m-tile
    const int wh = wid & 1;               // k-half
    const int wn = wh * 80;               // slab-col base
    const int lrow = lane & 15;
    const int lcol = (lane >> 4) * 8;
    const int gid = lane >> 2;
    const int tig = lane & 3;

    const uint32_t sQb = smem_u32(sQ);
    const uint32_t sKb = smem_u32(sK);
    const uint32_t sVb = smem_u32(sV);

    // ---- QK^T ----
    float sf[5][2][4];
#pragma unroll
    for (int g = 0; g < 5; g++)
#pragma unroll
        for (int s = 0; s < 2; s++)
#pragma unroll
            for (int r = 0; r < 4; r++) sf[g][s][r] = 0.f;

#pragma unroll
    for (int kt = 0; kt < 4; kt++) {
        uint32_t af[4];
        ldm_x4(af, sQb + ((wm + lrow) * PST + kt * 16 + lcol) * 2);
#pragma unroll
        for (int g = 0; g < 5; g++) {
            uint32_t bf[4];
            ldm_x4(bf, sKb + ((wn + g * 16 + lrow) * PST + kt * 16 + lcol) * 2);
            mma_h(sf[g][0], af, bf[0], bf[2]);
            mma_h(sf[g][1], af, bf[1], bf[3]);
        }
    }

    // ---- mask + softmax on fragments ----
    const int row0 = wm + gid;
    const int row1 = row0 + 8;
    float mx0 = -INFINITY, mx1 = -INFINITY;
#pragma unroll
    for (int g = 0; g < 5; g++)
#pragma unroll
        for (int s = 0; s < 2; s++)
#pragma unroll
            for (int j = 0; j < 2; j++) {
                int n = wn + g * 16 + s * 8 + tig * 2 + j;
                bool base_ok;
                if (n < 128) {
                    int pos = l0 - WIN + n;
                    base_ok = (pos >= 0) && (pos < L_PAT);
                } else base_ok = (n < 132);
                bool v0 = base_ok && (n >= 128 || (n >= row0 && n <= row0 + 64));
                bool v1 = base_ok && (n >= 128 || (n >= row1 && n <= row1 + 64));
                float a0 = v0 ? sf[g][s][j] : -1e30f;
                float a1 = v1 ? sf[g][s][j + 2] : -1e30f;
                sf[g][s][j] = a0;
                sf[g][s][j + 2] = a1;
                mx0 = fmaxf(mx0, a0);
                mx1 = fmaxf(mx1, a1);
            }
    mx0 = fmaxf(mx0, __shfl_xor_sync(0xffffffffu, mx0, 1));
    mx0 = fmaxf(mx0, __shfl_xor_sync(0xffffffffu, mx0, 2));
    mx1 = fmaxf(mx1, __shfl_xor_sync(0xffffffffu, mx1, 1));
    mx1 = fmaxf(mx1, __shfl_xor_sync(0xffffffffu, mx1, 2));
    if (tig == 0) {
        hm[row0 * 2 + wh] = mx0;
        hm[row1 * 2 + wh] = mx1;
    }
    __syncthreads();
    float M0 = fmaxf(hm[row0 * 2], hm[row0 * 2 + 1]);
    float M1 = fmaxf(hm[row1 * 2], hm[row1 * 2 + 1]);

    float sum0 = 0.f, sum1 = 0.f;
#pragma unroll
    for (int g = 0; g < 5; g++)
#pragma unroll
        for (int s = 0; s < 2; s++) {
            float p0 = fexp(sf[g][s][0] - M0);
            float p1 = fexp(sf[g][s][1] - M0);
            float p2 = fexp(sf[g][s][2] - M1);
            float p3 = fexp(sf[g][s][3] - M1);
            sf[g][s][0] = p0; sf[g][s][1] = p1;
            sf[g][s][2] = p2; sf[g][s][3] = p3;
            sum0 += p0 + p1;
            sum1 += p2 + p3;
        }
    sum0 += __shfl_xor_sync(0xffffffffu, sum0, 1);
    sum0 += __shfl_xor_sync(0xffffffffu, sum0, 2);
    sum1 += __shfl_xor_sync(0xffffffffu, sum1, 1);
    sum1 += __shfl_xor_sync(0xffffffffu, sum1, 2);
    if (tig == 0) {
        hs[row0 * 2 + wh] = sum0;
        hs[row1 * 2 + wh] = sum1;
    }
    __syncthreads();
    float inv0 = 1.0f / (hs[row0 * 2] + hs[row0 * 2 + 1]);
    float inv1 = 1.0f / (hs[row1 * 2] + hs[row1 * 2 + 1]);

    // ---- P hi/lo A-fragments (exact split) ----
    uint32_t PhA[5][4], PlA[5][4];
#pragma unroll
    for (int kt = 0; kt < 5; kt++) {
#pragma unroll
        for (int s = 0; s < 2; s++) {
            float p00 = sf[kt][s][0] * inv0;
            float p01 = sf[kt][s][1] * inv0;
            float p10 = sf[kt][s][2] * inv1;
            float p11 = sf[kt][s][3] * inv1;
            __half h00 = __float2half_rn(p00), h01 = __float2half_rn(p01);
            __half h10 = __float2half_rn(p10), h11 = __float2half_rn(p11);
            PhA[kt][0 + s * 2] = packf16(__half2float(h00), __half2float(h01));
            PhA[kt][1 + s * 2] = packf16(__half2float(h10), __half2float(h11));
            PlA[kt][0 + s * 2] = packf16(p00 - __half2float(h00), p01 - __half2float(h01));
            PlA[kt][1 + s * 2] = packf16(p10 - __half2float(h10), p11 - __half2float(h11));
        }
    }

    // ---- PV ----
    float of[8][4];
#pragma unroll
    for (int i = 0; i < 8; i++)
#pragma unroll
        for (int r = 0; r < 4; r++) of[i][r] = 0.f;

#pragma unroll
    for (int dt2 = 0; dt2 < 4; dt2++) {
#pragma unroll
        for (int kt = 0; kt < 5; kt++) {
            uint32_t vb[4];
            ldm_x4t(vb, sVb + ((wn + kt * 16 + lrow) * PST + dt2 * 16 + lcol) * 2);
            mma_h(of[2 * dt2 + 0], PhA[kt], vb[0], vb[1]);
            mma_h(of[2 * dt2 + 1], PhA[kt], vb[2], vb[3]);
            mma_h(of[2 * dt2 + 0], PlA[kt], vb[0], vb[1]);
            mma_h(of[2 * dt2 + 1], PlA[kt], vb[2], vb[3]);
        }
    }

    // ---- cross-half reduce + write fp16 ----
    float* rb = redb + (wm >> 4) * 16 * 66;
    if (wh == 1) {
#pragma unroll
        for (int dt = 0; dt < 8; dt++) {
            int d = dt * 8 + tig * 2;
            *(float2*)&rb[gid * 66 + d] = make_float2(of[dt][0], of[dt][1]);
            *(float2*)&rb[(gid + 8) * 66 + d] = make_float2(of[dt][2], of[dt][3]);
        }
    }
    __syncthreads();
    if (wh == 0) {
#pragma unroll
        for (int dt = 0; dt < 8; dt++) {
            int d = dt * 8 + tig * 2;
            float2 r0 = *(float2*)&rb[gid * 66 + d];
            float2 r1 = *(float2*)&rb[(gid + 8) * 66 + d];
            int grow0 = NUM_CLS + l0 + row0;
            int grow1 = NUM_CLS + l0 + row1;
            *(uint32_t*)&g_af[(size_t)grow0 * 512 + h * 64 + d] =
                packf16(of[dt][0] + r0.x, of[dt][1] + r0.y);
            *(uint32_t*)&g_af[(size_t)grow1 * 512 + h * 64 + d] =
                packf16(of[dt][2] + r1.x, of[dt][3] + r1.y);
        }
    }
}

// ---------------------------------------------------------------------------
extern "C" void kernel_launch(void* const* d_in, const int* in_sizes, int n_in,
                              void* d_out, int out_size) {
    const float* x      = (const float*)d_in[0];
    const float* coords = (const float*)d_in[1];
    const float* w_qkv  = (const float*)d_in[2];
    const float* b_qkv  = (const float*)d_in[3];
    const float* w_out  = (const float*)d_in[4];
    const float* b_out  = (const float*)d_in[5];
    float* out = (float*)d_out;

    __half *xf, *af, *wqf, *wof;
    cudaGetSymbolAddress((void**)&xf, g_xf);
    cudaGetSymbolAddress((void**)&af, g_af);
    cudaGetSymbolAddress((void**)&wqf, g_wqf);
    cudaGetSymbolAddress((void**)&wof, g_wof);

    cudaFuncSetAttribute(gemm_f16<0>, cudaFuncAttributeMaxDynamicSharedMemorySize, GEMM_SMEM);
    cudaFuncSetAttribute(gemm_f16<1>, cudaFuncAttributeMaxDynamicSharedMemorySize, GEMM_SMEM);
    cudaFuncSetAttribute(patch_attn_kernel, cudaFuncAttributeMaxDynamicSharedMemorySize, PATCH_SMEM);

    const int NA4 = S_TOT * GK / 4;

    // 1. converts + rope table
    tof16_kernel<<<(NA4 + 255) / 256, 256>>>(x, xf, NA4);
    tof16_kernel<<<(1536 * GK / 4 + 255) / 256, 256>>>(w_qkv, wqf, 1536 * GK / 4);
    tof16_kernel<<<(512 * GK / 4 + 255) / 256, 256>>>(w_out, wof, 512 * GK / 4);
    rope_table_kernel<<<(L_PAT * 32) / 256, 256>>>(coords);

    // 2. QKV GEMM (rope fused) -> g_qkv scatter
    {
        dim3 grid(1536 / 128, (S_TOT + 127) / 128);
        gemm_f16<1><<<grid, 256, GEMM_SMEM>>>(xf, wqf, b_qkv, nullptr, S_TOT, 0);
    }
    // 3. CLS attention + combine (fp16 out)
    {
        dim3 grid(8, 8);
        cls_part_kernel<<<grid, 256>>>();
        cls_combine_kernel<<<32, 64>>>();
    }
    // 4. Patch attention (tensor cores, fp16 out)
    {
        dim3 grid(L_PAT / 64, H_NUM);
        patch_attn_kernel<<<grid, 256, PATCH_SMEM>>>();
    }
    // 5. out projection (reads g_af directly)
    {
        dim3 grid(512 / 128, (S_TOT + 127) / 128);
        gemm_f16<0><<<grid, 256, GEMM_SMEM>>>(af, wof, b_out, out, S_TOT, 512);
    }
}

// round 14
// speedup vs baseline: 2.3829x; 1.1266x over previous
#include <cuda_runtime.h>
#include <cuda_fp16.h>
#include <cuda_bf16.h>
#include <math.h>
#include <stdint.h>

#define S_TOT 8196
#define L_PAT 8192
#define H_NUM 8
#define HD 64
#define NUM_CLS 4
#define WIN 32
#define WLEN 65
#define CTX 69
#define GK 512

// scratch
__device__ float g_qkv[3ull * H_NUM * S_TOT * HD];
__device__ float g_clsp[32 * 16 * 66];
__device__ float2 g_rtab[(size_t)L_PAT * 32];
__device__ __half g_xf[(size_t)S_TOT * GK];
__device__ __half g_af[(size_t)S_TOT * GK];
__device__ __half g_wqf[1536 * GK];
__device__ __half g_wof[512 * GK];

__constant__ float c_ftbl[16] = {
    1.0f, 0.5623413252f, 0.3162277660f, 0.1778279410f,
    0.1f, 0.05623413252f, 0.03162277660f, 0.01778279410f,
    0.01f, 0.005623413252f, 0.003162277660f, 0.001778279410f,
    0.001f, 0.0005623413252f, 0.0003162277660f, 0.0001778279410f
};

extern __shared__ char dynsm[];

__device__ __forceinline__ uint32_t smem_u32(const void* p) {
    uint32_t a;
    asm("{ .reg .u64 t; cvta.to.shared.u64 t, %1; cvt.u32.u64 %0, t; }" : "=r"(a) : "l"(p));
    return a;
}
__device__ __forceinline__ void ldm_x4(uint32_t* r, uint32_t addr) {
    asm volatile("ldmatrix.sync.aligned.m8n8.x4.shared.b16 {%0,%1,%2,%3}, [%4];"
                 : "=r"(r[0]), "=r"(r[1]), "=r"(r[2]), "=r"(r[3]) : "r"(addr));
}
__device__ __forceinline__ void ldm_x4t(uint32_t* r, uint32_t addr) {
    asm volatile("ldmatrix.sync.aligned.m8n8.x4.trans.shared.b16 {%0,%1,%2,%3}, [%4];"
                 : "=r"(r[0]), "=r"(r[1]), "=r"(r[2]), "=r"(r[3]) : "r"(addr));
}
__device__ __forceinline__ void mma_h(float* c, const uint32_t* a, uint32_t b0, uint32_t b1) {
    asm volatile("mma.sync.aligned.m16n8k16.row.col.f32.f16.f16.f32 "
                 "{%0,%1,%2,%3}, {%4,%5,%6,%7}, {%8,%9}, {%0,%1,%2,%3};"
                 : "+f"(c[0]), "+f"(c[1]), "+f"(c[2]), "+f"(c[3])
                 : "r"(a[0]), "r"(a[1]), "r"(a[2]), "r"(a[3]), "r"(b0), "r"(b1));
}
__device__ __forceinline__ uint32_t packf16(float a, float b) {
    __half2 t = __floats2half2_rn(a, b);
    return *(uint32_t*)&t;
}
__device__ __forceinline__ void cp16(uint32_t dst, const void* src, int sz) {
    asm volatile("cp.async.cg.shared.global [%0], [%1], 16, %2;"
                 :: "r"(dst), "l"(src), "r"(sz));
}
#define CP_COMMIT() asm volatile("cp.async.commit_group;" ::: "memory")
#define CP_WAIT0()  asm volatile("cp.async.wait_group 0;" ::: "memory")

// fast exp on FMA pipe (x <= 0 domain)
__device__ __forceinline__ float fexp(float x) {
    x = fmaxf(x, -80.0f);
    float z = fmaf(x, 1.442695041f, 12582912.0f);
    float n = z - 12582912.0f;
    float f = fmaf(x, 1.442695041f, -n);
    float r = 1.3333558e-3f;
    r = fmaf(r, f, 9.6181291e-3f);
    r = fmaf(r, f, 5.5504109e-2f);
    r = fmaf(r, f, 2.4022651e-1f);
    r = fmaf(r, f, 6.9314718e-1f);
    r = fmaf(r, f, 1.0f);
    return r * __int_as_float(((int)n + 127) << 23);
}

// ---------------------------------------------------------------------------
// prep: fused x/wq/wo converts + rope table, region-switched on blockIdx.x
// ---------------------------------------------------------------------------
#define NB_X  ((S_TOT * GK / 4 + 255) / 256)
#define NB_WQ (1536 * GK / 4 / 256)
#define NB_WO (512 * GK / 4 / 256)
#define NB_RT (L_PAT * 32 / 256)
#define NB_PREP (NB_X + NB_WQ + NB_WO + NB_RT)

__global__ void prep_kernel(const float* __restrict__ x,
                            const float* __restrict__ w_qkv,
                            const float* __restrict__ w_out,
                            const float* __restrict__ coords) {
    int b = blockIdx.x;
    if (b < NB_X) {
        int i = b * 256 + threadIdx.x;
        if (i < S_TOT * GK / 4) {
            float4 v = *(const float4*)(x + (size_t)i * 4);
            *(uint2*)(g_xf + (size_t)i * 4) =
                make_uint2(packf16(v.x, v.y), packf16(v.z, v.w));
        }
        return;
    }
    b -= NB_X;
    if (b < NB_WQ) {
        int i = b * 256 + threadIdx.x;
        float4 v = *(const float4*)(w_qkv + (size_t)i * 4);
        *(uint2*)(g_wqf + (size_t)i * 4) =
            make_uint2(packf16(v.x, v.y), packf16(v.z, v.w));
        return;
    }
    b -= NB_WQ;
    if (b < NB_WO) {
        int i = b * 256 + threadIdx.x;
        float4 v = *(const float4*)(w_out + (size_t)i * 4);
        *(uint2*)(g_wof + (size_t)i * 4) =
            make_uint2(packf16(v.x, v.y), packf16(v.z, v.w));
        return;
    }
    b -= NB_WO;
    {
        int idx = b * 256 + threadIdx.x;
        int l = idx >> 5, p = idx & 31;
        float cx = coords[2 * l + 0];
        float cy = coords[2 * l + 1];
        float freq = c_ftbl[p & 15];
        float coord = ((p < 16) ? cx : cy) * 1e-5f;
        float s, c;
        __sincosf(coord * freq, &s, &c);
        g_rtab[idx] = make_float2(c, s);
    }
}

// ---------------------------------------------------------------------------
// plain fp16 mma.sync GEMM (single pass), cp.async double buffer.
// ---------------------------------------------------------------------------
#define SMS 72
#define TILE_B (128 * SMS * 2)
#define STAGE_B (2 * TILE_B)
#define GEMM_SMEM (2 * STAGE_B)

template<int MODE>
__launch_bounds__(256)
__global__ void gemm_f16(const __half* __restrict__ A,
                         const __half* __restrict__ B,
                         const float* __restrict__ bias,
                         float* __restrict__ C, int M, int Ntot) {
    const int tid = threadIdx.x;
    const int wid = tid >> 5;
    const int lane = tid & 31;
    const int wm = (wid >> 2) * 64;
    const int wn = (wid & 3) * 32;
    const int bm = blockIdx.y * 128;
    const int bn = blockIdx.x * 128;

    float c[4][4][4];
#pragma unroll
    for (int i = 0; i < 4; i++)
#pragma unroll
        for (int j = 0; j < 4; j++)
#pragma unroll
            for (int r = 0; r < 4; r++) c[i][j][r] = 0.f;

    const uint32_t smb = smem_u32(dynsm);
    const int lrow = lane & 15;
    const int lcol = (lane >> 4) * 8;

    auto cp_chunk = [&](int ch, int st) {
        uint32_t sb = smb + st * STAGE_B;
#pragma unroll
        for (int it = 0; it < 8; it++) {
            int idx = tid + it * 256;
            int tile = idx >> 10;
            int slot = idx & 1023;
            int row = slot >> 3;
            int c16 = slot & 7;
            uint32_t dst = sb + tile * TILE_B + row * (SMS * 2) + c16 * 16;
            if (tile == 0) {
                int gr = bm + row;
                cp16(dst, A + (size_t)gr * GK + ch * 64 + c16 * 8, gr < M ? 16 : 0);
            } else {
                cp16(dst, B + (size_t)(bn + row) * GK + ch * 64 + c16 * 8, 16);
            }
        }
        CP_COMMIT();
    };

    cp_chunk(0, 0);

    for (int ch = 0; ch < GK / 64; ch++) {
        int st = ch & 1;
        CP_WAIT0();
        __syncthreads();
        if (ch < GK / 64 - 1) cp_chunk(ch + 1, st ^ 1);

        uint32_t a_b = smb + st * STAGE_B;
        uint32_t b_b = a_b + TILE_B;

#pragma unroll
        for (int kk = 0; kk < 4; kk++) {
            uint32_t af[4][4], bf[2][4];
#pragma unroll
            for (int mt = 0; mt < 4; mt++) {
                uint32_t off = ((wm + mt * 16 + lrow) * SMS + kk * 16 + lcol) * 2;
                ldm_x4(af[mt], a_b + off);
            }
#pragma unroll
            for (int g = 0; g < 2; g++) {
                uint32_t off = ((wn + g * 16 + lrow) * SMS + kk * 16 + lcol) * 2;
                ldm_x4(bf[g], b_b + off);
            }
#pragma unroll
            for (int mt = 0; mt < 4; mt++) {
#pragma unroll
                for (int nt = 0; nt < 4; nt++) {
                    int g = nt >> 1, s = nt & 1;
                    mma_h(c[mt][nt], af[mt], bf[g][s], bf[g][s + 2]);
                }
            }
        }
    }

    const int gid = lane >> 2;
    const int tig = lane & 3;
#pragma unroll
    for (int mt = 0; mt < 4; mt++) {
#pragma unroll
        for (int nt = 0; nt < 4; nt++) {
            int n = bn + wn + nt * 8 + tig * 2;
            float bx = bias[n], by = bias[n + 1];
            int m0 = bm + wm + mt * 16 + gid;
#pragma unroll
            for (int half = 0; half < 2; half++) {
                int m = m0 + half * 8;
                if (m >= M) continue;
                float vx = c[mt][nt][half * 2 + 0] + bx;
                float vy = c[mt][nt][half * 2 + 1] + by;
                if (MODE == 0) {
                    *(float2*)&C[(size_t)m * Ntot + n] = make_float2(vx, vy);
                } else {
                    int sel = n >> 9, h = (n >> 6) & 7, d = n & 63;
                    if (sel < 2 && m >= NUM_CLS) {
                        float2 cs = g_rtab[(size_t)(m - NUM_CLS) * 32 + (d >> 1)];
                        float rx = vx * cs.x - vy * cs.y;
                        float ry = vy * cs.x + vx * cs.y;
                        vx = rx; vy = ry;
                    }
                    *(float2*)&g_qkv[(((size_t)(sel * 8 + h) * S_TOT) + m) * 64 + d] =
                        make_float2(vx, vy);
                }
            }
        }
    }
}

// ---------------------------------------------------------------------------
// CLS attention split-K (16 chunks) + combine writing fp16
// ---------------------------------------------------------------------------
#define NCHUNK 16
#define CCHUNK 513
#define SCBW 516

__launch_bounds__(256)
__global__ void cls_part_kernel() {
    __shared__ float qs[4 * 64];
    __shared__ float scb[4 * SCBW];
    __shared__ float red[4][8];
    __shared__ float gm[4], gs[4];
    __shared__ float osum[8][4][64];

    int h = blockIdx.x;
    int chunk = blockIdx.y;
    int k0 = chunk * CCHUNK;
    int k1 = min(S_TOT, k0 + CCHUNK);
    int nk = k1 - k0;
    int tid = threadIdx.x;
    int lane = tid & 31, w = tid >> 5;

    const float* Kb = &g_qkv[(size_t)(8 + h) * S_TOT * 64];
    const float* Vb = &g_qkv[(size_t)(16 + h) * S_TOT * 64];

    {
        int ci = tid >> 6, d = tid & 63;
        qs[tid] = g_qkv[(((size_t)h * S_TOT) + ci) * 64 + d];
    }
    __syncthreads();

    float lmax[4] = {-INFINITY, -INFINITY, -INFINITY, -INFINITY};
    for (int s = tid; s < nk; s += 256) {
        const float4* kr = (const float4*)(Kb + (size_t)(k0 + s) * 64);
        float a[4] = {0.f, 0.f, 0.f, 0.f};
#pragma unroll
        for (int i = 0; i < 16; i++) {
            float4 kv = kr[i];
#pragma unroll
            for (int ci = 0; ci < 4; ci++) {
                float4 qv = *(float4*)&qs[ci * 64 + i * 4];
                a[ci] += kv.x * qv.x + kv.y * qv.y + kv.z * qv.z + kv.w * qv.w;
            }
        }
#pragma unroll
        for (int ci = 0; ci < 4; ci++) {
            float sa = a[ci] * 0.125f;
            scb[ci * SCBW + s] = sa;
            lmax[ci] = fmaxf(lmax[ci], sa);
        }
    }
#pragma unroll
    for (int ci = 0; ci < 4; ci++) {
#pragma unroll
        for (int o = 16; o > 0; o >>= 1)
            lmax[ci] = fmaxf(lmax[ci], __shfl_xor_sync(0xffffffffu, lmax[ci], o));
        if (lane == 0) red[ci][w] = lmax[ci];
    }
    __syncthreads();
    float gmaxv[4];
#pragma unroll
    for (int ci = 0; ci < 4; ci++) {
        float m = red[ci][0];
#pragma unroll
        for (int i = 1; i < 8; i++) m = fmaxf(m, red[ci][i]);
        gmaxv[ci] = m;
    }
    __syncthreads();

    float lsum[4] = {0.f, 0.f, 0.f, 0.f};
    for (int s = tid; s < nk; s += 256) {
#pragma unroll
        for (int ci = 0; ci < 4; ci++) {
            float p = __expf(scb[ci * SCBW + s] - gmaxv[ci]);
            scb[ci * SCBW + s] = p;
            lsum[ci] += p;
        }
    }
#pragma unroll
    for (int ci = 0; ci < 4; ci++) {
#pragma unroll
        for (int o = 16; o > 0; o >>= 1)
            lsum[ci] += __shfl_xor_sync(0xffffffffu, lsum[ci], o);
        if (lane == 0) red[ci][w] = lsum[ci];
    }
    __syncthreads();
    if (tid < 4) {
        float ssum = 0.f;
#pragma unroll
        for (int i = 0; i < 8; i++) ssum += red[tid][i];
        gs[tid] = ssum;
        gm[tid] = gmaxv[tid];
    }

    int sl = tid >> 2, dcc = tid & 3, dof = dcc * 16;
    float acc[4][16];
#pragma unroll
    for (int ci = 0; ci < 4; ci++)
#pragma unroll
        for (int dd = 0; dd < 16; dd++) acc[ci][dd] = 0.f;

    for (int s = sl; s < nk; s += 64) {
        float p[4];
#pragma unroll
        for (int ci = 0; ci < 4; ci++) p[ci] = scb[ci * SCBW + s];
        const float* vr = Vb + (size_t)(k0 + s) * 64 + dof;
        float vf[16];
#pragma unroll
        for (int i = 0; i < 4; i++) *(float4*)&vf[i * 4] = *(const float4*)&vr[i * 4];
#pragma unroll
        for (int dd = 0; dd < 16; dd++) {
            float vv = vf[dd];
            acc[0][dd] = fmaf(p[0], vv, acc[0][dd]);
            acc[1][dd] = fmaf(p[1], vv, acc[1][dd]);
            acc[2][dd] = fmaf(p[2], vv, acc[2][dd]);
            acc[3][dd] = fmaf(p[3], vv, acc[3][dd]);
        }
    }
#pragma unroll
    for (int o = 4; o <= 16; o <<= 1)
#pragma unroll
        for (int ci = 0; ci < 4; ci++)
#pragma unroll
            for (int dd = 0; dd < 16; dd++)
                acc[ci][dd] += __shfl_xor_sync(0xffffffffu, acc[ci][dd], o);

    if ((lane & 28) == 0) {
#pragma unroll
        for (int ci = 0; ci < 4; ci++)
#pragma unroll
            for (int dd = 0; dd < 16; dd++)
                osum[w][ci][dof + dd] = acc[ci][dd];
    }
    __syncthreads();

    {
        int ci = tid >> 6, d = tid & 63;
        float v = 0.f;
#pragma unroll
        for (int i = 0; i < 8; i++) v += osum[i][ci][d];
        float* dst = &g_clsp[((size_t)(h * 4 + ci) * NCHUNK + chunk) * 66];
        dst[2 + d] = v;
        if (d == 0) { dst[0] = gm[ci]; dst[1] = gs[ci]; }
    }
}

__global__ void cls_combine_kernel() {
    int hc = blockIdx.x;
    int h = hc >> 2, ci = hc & 3;
    int d = threadIdx.x;
    const float* base = &g_clsp[(size_t)hc * NCHUNK * 66];
    float M = -INFINITY;
#pragma unroll
    for (int c = 0; c < NCHUNK; c++) M = fmaxf(M, base[c * 66]);
    float S = 0.f, A = 0.f;
#pragma unroll
    for (int c = 0; c < NCHUNK; c++) {
        float w = __expf(base[c * 66] - M);
        S = fmaf(base[c * 66 + 1], w, S);
        A = fmaf(base[c * 66 + 2 + d], w, A);
    }
    g_af[(size_t)ci * 512 + h * 64 + d] = __float2half(A / S);
}

// ---------------------------------------------------------------------------
// Patch attention on tensor cores (flash-style), single-pass PV.
// ---------------------------------------------------------------------------
#define PST 72
#define SQ_E (64 * PST)
#define SK_E (160 * PST)
#define PATCH_SMEM ((SQ_E + 2 * SK_E) * 2 + 128 * 4 + 128 * 4 + 4 * 16 * 66 * 4)

__launch_bounds__(256)
__global__ void patch_attn_kernel() {
    __half* sQ = (__half*)dynsm;
    __half* sK = sQ + SQ_E;
    __half* sV = sK + SK_E;
    float* hm = (float*)(dynsm + (SQ_E + 2 * SK_E) * 2);
    float* hs = hm + 128;
    float* redb = hs + 128;

    int h = blockIdx.y;
    int l0 = blockIdx.x * 64;
    int tid = threadIdx.x;

    const float* Qb = &g_qkv[(size_t)h * S_TOT * 64];
    const float* Kb = &g_qkv[(size_t)(8 + h) * S_TOT * 64];
    const float* Vb = &g_qkv[(size_t)(16 + h) * S_TOT * 64];

    for (int i = tid; i < 64 * 8; i += 256) {
        int r = i >> 3, c8 = (i & 7) * 8;
        const float* src = &Qb[(size_t)(NUM_CLS + l0 + r) * 64 + c8];
        float4 a = *(const float4*)src;
        float4 b = *(const float4*)(src + 4);
        uint4 pk = make_uint4(packf16(a.x * 0.125f, a.y * 0.125f),
                              packf16(a.z * 0.125f, a.w * 0.125f),
                              packf16(b.x * 0.125f, b.y * 0.125f),
                              packf16(b.z * 0.125f, b.w * 0.125f));
        *(uint4*)&sQ[r * PST + c8] = pk;
    }
    for (int i = tid; i < 160 * 8; i += 256) {
        int r = i >> 3, c8 = (i & 7) * 8;
        float4 ka = make_float4(0.f, 0.f, 0.f, 0.f), kb = ka, va = ka, vb = ka;
        if (r < 128) {
            int kp = l0 - WIN + r;
            if (kp >= 0 && kp < L_PAT) {
                const float* ks = &Kb[(size_t)(NUM_CLS + kp) * 64 + c8];
                const float* vs = &Vb[(size_t)(NUM_CLS + kp) * 64 + c8];
                ka = *(const float4*)ks; kb = *(const float4*)(ks + 4);
                va = *(const float4*)vs; vb = *(const float4*)(vs + 4);
            }
        } else if (r < 132) {
            const float* ks = &Kb[(size_t)(r - 128) * 64 + c8];
            const float* vs = &Vb[(size_t)(r - 128) * 64 + c8];
            ka = *(const float4*)ks; kb = *(const float4*)(ks + 4);
            va = *(const float4*)vs; vb = *(const float4*)(vs + 4);
        }
        *(uint4*)&sK[r * PST + c8] = make_uint4(packf16(ka.x, ka.y), packf16(ka.z, ka.w),
                                                packf16(kb.x, kb.y), packf16(kb.z, kb.w));
        *(uint4*)&sV[r * PST + c8] = make_uint4(packf16(va.x, va.y), packf16(va.z, va.w),
                                                packf16(vb.x, vb.y), packf16(vb.z, vb.w));
    }
    __syncthreads();

    const int wid = tid >> 5;
    const int lane = tid & 31;
    const int wm = (wid >> 1) * 16;
    const int wh = wid & 1;
    const int wn = wh * 80;
    const int lrow = lane & 15;
    const int lcol = (lane >> 4) * 8;
    const int gid = lane >> 2;
    const int tig = lane & 3;

    const uint32_t sQb = smem_u32(sQ);
    const uint32_t sKb = smem_u32(sK);
    const uint32_t sVb = smem_u32(sV);

    // ---- QK^T ----
    float sf[5][2][4];
#pragma unroll
    for (int g = 0; g < 5; g++)
#pragma unroll
        for (int s = 0; s < 2; s++)
#pragma unroll
            for (int r = 0; r < 4; r++) sf[g][s][r] = 0.f;

#pragma unroll
    for (int kt = 0; kt < 4; kt++) {
        uint32_t af[4];
        ldm_x4(af, sQb + ((wm + lrow) * PST + kt * 16 + lcol) * 2);
#pragma unroll
        for (int g = 0; g < 5; g++) {
            uint32_t bf[4];
            ldm_x4(bf, sKb + ((wn + g * 16 + lrow) * PST + kt * 16 + lcol) * 2);
            mma_h(sf[g][0], af, bf[0], bf[2]);
            mma_h(sf[g][1], af, bf[1], bf[3]);
        }
    }

    // ---- mask + softmax on fragments ----
    const int row0 = wm + gid;
    const int row1 = row0 + 8;
    float mx0 = -INFINITY, mx1 = -INFINITY;
#pragma unroll
    for (int g = 0; g < 5; g++)
#pragma unroll
        for (int s = 0; s < 2; s++)
#pragma unroll
            for (int j = 0; j < 2; j++) {
                int n = wn + g * 16 + s * 8 + tig * 2 + j;
                bool base_ok;
                if (n < 128) {
                    int pos = l0 - WIN + n;
                    base_ok = (pos >= 0) && (pos < L_PAT);
                } else base_ok = (n < 132);
                bool v0 = base_ok && (n >= 128 || (n >= row0 && n <= row0 + 64));
                bool v1 = base_ok && (n >= 128 || (n >= row1 && n <= row1 + 64));
                float a0 = v0 ? sf[g][s][j] : -1e30f;
                float a1 = v1 ? sf[g][s][j + 2] : -1e30f;
                sf[g][s][j] = a0;
                sf[g][s][j + 2] = a1;
                mx0 = fmaxf(mx0, a0);
                mx1 = fmaxf(mx1, a1);
            }
    mx0 = fmaxf(mx0, __shfl_xor_sync(0xffffffffu, mx0, 1));
    mx0 = fmaxf(mx0, __shfl_xor_sync(0xffffffffu, mx0, 2));
    mx1 = fmaxf(mx1, __shfl_xor_sync(0xffffffffu, mx1, 1));
    mx1 = fmaxf(mx1, __shfl_xor_sync(0xffffffffu, mx1, 2));
    if (tig == 0) {
        hm[row0 * 2 + wh] = mx0;
        hm[row1 * 2 + wh] = mx1;
    }
    __syncthreads();
    float M0 = fmaxf(hm[row0 * 2], hm[row0 * 2 + 1]);
    float M1 = fmaxf(hm[row1 * 2], hm[row1 * 2 + 1]);

    float sum0 = 0.f, sum1 = 0.f;
#pragma unroll
    for (int g = 0; g < 5; g++)
#pragma unroll
        for (int s = 0; s < 2; s++) {
            float p0 = fexp(sf[g][s][0] - M0);
            float p1 = fexp(sf[g][s][1] - M0);
            float p2 = fexp(sf[g][s][2] - M1);
            float p3 = fexp(sf[g][s][3] - M1);
            sf[g][s][0] = p0; sf[g][s][1] = p1;
            sf[g][s][2] = p2; sf[g][s][3] = p3;
            sum0 += p0 + p1;
            sum1 += p2 + p3;
        }
    sum0 += __shfl_xor_sync(0xffffffffu, sum0, 1);
    sum0 += __shfl_xor_sync(0xffffffffu, sum0, 2);
    sum1 += __shfl_xor_sync(0xffffffffu, sum1, 1);
    sum1 += __shfl_xor_sync(0xffffffffu, sum1, 2);
    if (tig == 0) {
        hs[row0 * 2 + wh] = sum0;
        hs[row1 * 2 + wh] = sum1;
    }
    __syncthreads();
    float inv0 = 1.0f / (hs[row0 * 2] + hs[row0 * 2 + 1]);
    float inv1 = 1.0f / (hs[row1 * 2] + hs[row1 * 2 + 1]);

    // ---- P fp16 A-fragments (single pass) ----
    uint32_t PhA[5][4];
#pragma unroll
    for (int kt = 0; kt < 5; kt++) {
#pragma unroll
        for (int s = 0; s < 2; s++) {
            PhA[kt][0 + s * 2] = packf16(sf[kt][s][0] * inv0, sf[kt][s][1] * inv0);
            PhA[kt][1 + s * 2] = packf16(sf[kt][s][2] * inv1, sf[kt][s][3] * inv1);
        }
    }

    // ---- PV ----
    float of[8][4];
#pragma unroll
    for (int i = 0; i < 8; i++)
#pragma unroll
        for (int r = 0; r < 4; r++) of[i][r] = 0.f;

#pragma unroll
    for (int dt2 = 0; dt2 < 4; dt2++) {
#pragma unroll
        for (int kt = 0; kt < 5; kt++) {
            uint32_t vb[4];
            ldm_x4t(vb, sVb + ((wn + kt * 16 + lrow) * PST + dt2 * 16 + lcol) * 2);
            mma_h(of[2 * dt2 + 0], PhA[kt], vb[0], vb[1]);
            mma_h(of[2 * dt2 + 1], PhA[kt], vb[2], vb[3]);
        }
    }

    // ---- cross-half reduce + write fp16 ----
    float* rb = redb + (wm >> 4) * 16 * 66;
    if (wh == 1) {
#pragma unroll
        for (int dt = 0; dt < 8; dt++) {
            int d = dt * 8 + tig * 2;
            *(float2*)&rb[gid * 66 + d] = make_float2(of[dt][0], of[dt][1]);
            *(float2*)&rb[(gid + 8) * 66 + d] = make_float2(of[dt][2], of[dt][3]);
        }
    }
    __syncthreads();
    if (wh == 0) {
#pragma unroll
        for (int dt = 0; dt < 8; dt++) {
            int d = dt * 8 + tig * 2;
            float2 r0 = *(float2*)&rb[gid * 66 + d];
            float2 r1 = *(float2*)&rb[(gid + 8) * 66 + d];
            int grow0 = NUM_CLS + l0 + row0;
            int grow1 = NUM_CLS + l0 + row1;
            *(uint32_t*)&g_af[(size_t)grow0 * 512 + h * 64 + d] =
                packf16(of[dt][0] + r0.x, of[dt][1] + r0.y);
            *(uint32_t*)&g_af[(size_t)grow1 * 512 + h * 64 + d] =
                packf16(of[dt][2] + r1.x, of[dt][3] + r1.y);
        }
    }
}

// ---------------------------------------------------------------------------
extern "C" void kernel_launch(void* const* d_in, const int* in_sizes, int n_in,
                              void* d_out, int out_size) {
    const float* x      = (const float*)d_in[0];
    const float* coords = (const float*)d_in[1];
    const float* w_qkv  = (const float*)d_in[2];
    const float* b_qkv  = (const float*)d_in[3];
    const float* w_out  = (const float*)d_in[4];
    const float* b_out  = (const float*)d_in[5];
    float* out = (float*)d_out;

    __half *xf, *af, *wqf, *wof;
    cudaGetSymbolAddress((void**)&xf, g_xf);
    cudaGetSymbolAddress((void**)&af, g_af);
    cudaGetSymbolAddress((void**)&wqf, g_wqf);
    cudaGetSymbolAddress((void**)&wof, g_wof);

    cudaFuncSetAttribute(gemm_f16<0>, cudaFuncAttributeMaxDynamicSharedMemorySize, GEMM_SMEM);
    cudaFuncSetAttribute(gemm_f16<1>, cudaFuncAttributeMaxDynamicSharedMemorySize, GEMM_SMEM);
    cudaFuncSetAttribute(patch_attn_kernel, cudaFuncAttributeMaxDynamicSharedMemorySize, PATCH_SMEM);

    // 1. fused prep (converts + rope table)
    prep_kernel<<<NB_PREP, 256>>>(x, w_qkv, w_out, coords);

    // 2. QKV GEMM (rope fused) -> g_qkv scatter
    {
        dim3 grid(1536 / 128, (S_TOT + 127) / 128);
        gemm_f16<1><<<grid, 256, GEMM_SMEM>>>(xf, wqf, b_qkv, nullptr, S_TOT, 0);
    }
    // 3. CLS attention + combine
    {
        dim3 grid(8, NCHUNK);
        cls_part_kernel<<<grid, 256>>>();
        cls_combine_kernel<<<32, 64>>>();
    }
    // 4. Patch attention
    {
        dim3 grid(L_PAT / 64, H_NUM);
        patch_attn_kernel<<<grid, 256, PATCH_SMEM>>>();
    }
    // 5. out projection
    {
        dim3 grid(512 / 128, (S_TOT + 127) / 128);
        gemm_f16<0><<<grid, 256, GEMM_SMEM>>>(af, wof, b_out, out, S_TOT, 512);
    }
}

// round 15
// speedup vs baseline: 2.4618x; 1.0331x over previous
#include <cuda_runtime.h>
#include <cuda_fp16.h>
#include <cuda_bf16.h>
#include <math.h>
#include <stdint.h>

#define S_TOT 8196
#define L_PAT 8192
#define H_NUM 8
#define HD 64
#define NUM_CLS 4
#define WIN 32
#define WLEN 65
#define CTX 69
#define GK 512

// scratch
__device__ float g_qkv[3ull * H_NUM * S_TOT * HD];
__device__ float g_clsp[32 * 16 * 66];
__device__ float2 g_rtab[(size_t)L_PAT * 32];
__device__ __half g_xf[(size_t)S_TOT * GK];
__device__ __half g_af[(size_t)S_TOT * GK];
__device__ __half g_wqf[1536 * GK];
__device__ __half g_wof[512 * GK];

__constant__ float c_ftbl[16] = {
    1.0f, 0.5623413252f, 0.3162277660f, 0.1778279410f,
    0.1f, 0.05623413252f, 0.03162277660f, 0.01778279410f,
    0.01f, 0.005623413252f, 0.003162277660f, 0.001778279410f,
    0.001f, 0.0005623413252f, 0.0003162277660f, 0.0001778279410f
};

extern __shared__ char dynsm[];

__device__ __forceinline__ uint32_t smem_u32(const void* p) {
    uint32_t a;
    asm("{ .reg .u64 t; cvta.to.shared.u64 t, %1; cvt.u32.u64 %0, t; }" : "=r"(a) : "l"(p));
    return a;
}
__device__ __forceinline__ void ldm_x4(uint32_t* r, uint32_t addr) {
    asm volatile("ldmatrix.sync.aligned.m8n8.x4.shared.b16 {%0,%1,%2,%3}, [%4];"
                 : "=r"(r[0]), "=r"(r[1]), "=r"(r[2]), "=r"(r[3]) : "r"(addr));
}
__device__ __forceinline__ void ldm_x4t(uint32_t* r, uint32_t addr) {
    asm volatile("ldmatrix.sync.aligned.m8n8.x4.trans.shared.b16 {%0,%1,%2,%3}, [%4];"
                 : "=r"(r[0]), "=r"(r[1]), "=r"(r[2]), "=r"(r[3]) : "r"(addr));
}
__device__ __forceinline__ void mma_h(float* c, const uint32_t* a, uint32_t b0, uint32_t b1) {
    asm volatile("mma.sync.aligned.m16n8k16.row.col.f32.f16.f16.f32 "
                 "{%0,%1,%2,%3}, {%4,%5,%6,%7}, {%8,%9}, {%0,%1,%2,%3};"
                 : "+f"(c[0]), "+f"(c[1]), "+f"(c[2]), "+f"(c[3])
                 : "r"(a[0]), "r"(a[1]), "r"(a[2]), "r"(a[3]), "r"(b0), "r"(b1));
}
__device__ __forceinline__ uint32_t packf16(float a, float b) {
    __half2 t = __floats2half2_rn(a, b);
    return *(uint32_t*)&t;
}
__device__ __forceinline__ void cp16(uint32_t dst, const void* src, int sz) {
    asm volatile("cp.async.cg.shared.global [%0], [%1], 16, %2;"
                 :: "r"(dst), "l"(src), "r"(sz));
}
#define CP_COMMIT() asm volatile("cp.async.commit_group;" ::: "memory")
#define CP_WAIT0()  asm volatile("cp.async.wait_group 0;" ::: "memory")

// fast exp on FMA pipe (x <= 0 domain)
__device__ __forceinline__ float fexp(float x) {
    x = fmaxf(x, -80.0f);
    float z = fmaf(x, 1.442695041f, 12582912.0f);
    float n = z - 12582912.0f;
    float f = fmaf(x, 1.442695041f, -n);
    float r = 1.3333558e-3f;
    r = fmaf(r, f, 9.6181291e-3f);
    r = fmaf(r, f, 5.5504109e-2f);
    r = fmaf(r, f, 2.4022651e-1f);
    r = fmaf(r, f, 6.9314718e-1f);
    r = fmaf(r, f, 1.0f);
    return r * __int_as_float(((int)n + 127) << 23);
}

// ---------------------------------------------------------------------------
// prep: fused x/wq/wo converts + rope table, region-switched on blockIdx.x
// ---------------------------------------------------------------------------
#define NB_X  ((S_TOT * GK / 4 + 255) / 256)
#define NB_WQ (1536 * GK / 4 / 256)
#define NB_WO (512 * GK / 4 / 256)
#define NB_RT (L_PAT * 32 / 256)
#define NB_PREP (NB_X + NB_WQ + NB_WO + NB_RT)

__global__ void prep_kernel(const float* __restrict__ x,
                            const float* __restrict__ w_qkv,
                            const float* __restrict__ w_out,
                            const float* __restrict__ coords) {
    int b = blockIdx.x;
    if (b < NB_X) {
        int i = b * 256 + threadIdx.x;
        if (i < S_TOT * GK / 4) {
            float4 v = *(const float4*)(x + (size_t)i * 4);
            *(uint2*)(g_xf + (size_t)i * 4) =
                make_uint2(packf16(v.x, v.y), packf16(v.z, v.w));
        }
        return;
    }
    b -= NB_X;
    if (b < NB_WQ) {
        int i = b * 256 + threadIdx.x;
        float4 v = *(const float4*)(w_qkv + (size_t)i * 4);
        *(uint2*)(g_wqf + (size_t)i * 4) =
            make_uint2(packf16(v.x, v.y), packf16(v.z, v.w));
        return;
    }
    b -= NB_WQ;
    if (b < NB_WO) {
        int i = b * 256 + threadIdx.x;
        float4 v = *(const float4*)(w_out + (size_t)i * 4);
        *(uint2*)(g_wof + (size_t)i * 4) =
            make_uint2(packf16(v.x, v.y), packf16(v.z, v.w));
        return;
    }
    b -= NB_WO;
    {
        int idx = b * 256 + threadIdx.x;
        int l = idx >> 5, p = idx & 31;
        float cx = coords[2 * l + 0];
        float cy = coords[2 * l + 1];
        float freq = c_ftbl[p & 15];
        float coord = ((p < 16) ? cx : cy) * 1e-5f;
        float s, c;
        __sincosf(coord * freq, &s, &c);
        g_rtab[idx] = make_float2(c, s);
    }
}

// ---------------------------------------------------------------------------
// plain fp16 mma.sync GEMM (single pass), cp.async double buffer.
// ---------------------------------------------------------------------------
#define SMS 72
#define TILE_B (128 * SMS * 2)
#define STAGE_B (2 * TILE_B)
#define GEMM_SMEM (2 * STAGE_B)

template<int MODE>
__launch_bounds__(256)
__global__ void gemm_f16(const __half* __restrict__ A,
                         const __half* __restrict__ B,
                         const float* __restrict__ bias,
                         float* __restrict__ C, int M, int Ntot) {
    const int tid = threadIdx.x;
    const int wid = tid >> 5;
    const int lane = tid & 31;
    const int wm = (wid >> 2) * 64;
    const int wn = (wid & 3) * 32;
    const int bm = blockIdx.y * 128;
    const int bn = blockIdx.x * 128;

    float c[4][4][4];
#pragma unroll
    for (int i = 0; i < 4; i++)
#pragma unroll
        for (int j = 0; j < 4; j++)
#pragma unroll
            for (int r = 0; r < 4; r++) c[i][j][r] = 0.f;

    const uint32_t smb = smem_u32(dynsm);
    const int lrow = lane & 15;
    const int lcol = (lane >> 4) * 8;

    auto cp_chunk = [&](int ch, int st) {
        uint32_t sb = smb + st * STAGE_B;
#pragma unroll
        for (int it = 0; it < 8; it++) {
            int idx = tid + it * 256;
            int tile = idx >> 10;
            int slot = idx & 1023;
            int row = slot >> 3;
            int c16 = slot & 7;
            uint32_t dst = sb + tile * TILE_B + row * (SMS * 2) + c16 * 16;
            if (tile == 0) {
                int gr = bm + row;
                cp16(dst, A + (size_t)gr * GK + ch * 64 + c16 * 8, gr < M ? 16 : 0);
            } else {
                cp16(dst, B + (size_t)(bn + row) * GK + ch * 64 + c16 * 8, 16);
            }
        }
        CP_COMMIT();
    };

    cp_chunk(0, 0);

    for (int ch = 0; ch < GK / 64; ch++) {
        int st = ch & 1;
        CP_WAIT0();
        __syncthreads();
        if (ch < GK / 64 - 1) cp_chunk(ch + 1, st ^ 1);

        uint32_t a_b = smb + st * STAGE_B;
        uint32_t b_b = a_b + TILE_B;

#pragma unroll
        for (int kk = 0; kk < 4; kk++) {
            uint32_t af[4][4], bf[2][4];
#pragma unroll
            for (int mt = 0; mt < 4; mt++) {
                uint32_t off = ((wm + mt * 16 + lrow) * SMS + kk * 16 + lcol) * 2;
                ldm_x4(af[mt], a_b + off);
            }
#pragma unroll
            for (int g = 0; g < 2; g++) {
                uint32_t off = ((wn + g * 16 + lrow) * SMS + kk * 16 + lcol) * 2;
                ldm_x4(bf[g], b_b + off);
            }
#pragma unroll
            for (int mt = 0; mt < 4; mt++) {
#pragma unroll
                for (int nt = 0; nt < 4; nt++) {
                    int g = nt >> 1, s = nt & 1;
                    mma_h(c[mt][nt], af[mt], bf[g][s], bf[g][s + 2]);
                }
            }
        }
    }

    const int gid = lane >> 2;
    const int tig = lane & 3;
#pragma unroll
    for (int mt = 0; mt < 4; mt++) {
#pragma unroll
        for (int nt = 0; nt < 4; nt++) {
            int n = bn + wn + nt * 8 + tig * 2;
            float bx = bias[n], by = bias[n + 1];
            int m0 = bm + wm + mt * 16 + gid;
#pragma unroll
            for (int half = 0; half < 2; half++) {
                int m = m0 + half * 8;
                if (m >= M) continue;
                float vx = c[mt][nt][half * 2 + 0] + bx;
                float vy = c[mt][nt][half * 2 + 1] + by;
                if (MODE == 0) {
                    *(float2*)&C[(size_t)m * Ntot + n] = make_float2(vx, vy);
                } else {
                    int sel = n >> 9, h = (n >> 6) & 7, d = n & 63;
                    if (sel < 2 && m >= NUM_CLS) {
                        float2 cs = g_rtab[(size_t)(m - NUM_CLS) * 32 + (d >> 1)];
                        float rx = vx * cs.x - vy * cs.y;
                        float ry = vy * cs.x + vx * cs.y;
                        vx = rx; vy = ry;
                    }
                    *(float2*)&g_qkv[(((size_t)(sel * 8 + h) * S_TOT) + m) * 64 + d] =
                        make_float2(vx, vy);
                }
            }
        }
    }
}

// ---------------------------------------------------------------------------
// CLS attention split-K (16 chunks) + wide combine writing fp16
// ---------------------------------------------------------------------------
#define NCHUNK 16
#define CCHUNK 513
#define SCBW 516

__launch_bounds__(256)
__global__ void cls_part_kernel() {
    __shared__ float qs[4 * 64];
    __shared__ float scb[4 * SCBW];
    __shared__ float red[4][8];
    __shared__ float gm[4], gs[4];
    __shared__ float osum[8][4][64];

    int h = blockIdx.x;
    int chunk = blockIdx.y;
    int k0 = chunk * CCHUNK;
    int k1 = min(S_TOT, k0 + CCHUNK);
    int nk = k1 - k0;
    int tid = threadIdx.x;
    int lane = tid & 31, w = tid >> 5;

    const float* Kb = &g_qkv[(size_t)(8 + h) * S_TOT * 64];
    const float* Vb = &g_qkv[(size_t)(16 + h) * S_TOT * 64];

    {
        int ci = tid >> 6, d = tid & 63;
        qs[tid] = g_qkv[(((size_t)h * S_TOT) + ci) * 64 + d];
    }
    __syncthreads();

    float lmax[4] = {-INFINITY, -INFINITY, -INFINITY, -INFINITY};
    for (int s = tid; s < nk; s += 256) {
        const float4* kr = (const float4*)(Kb + (size_t)(k0 + s) * 64);
        float a[4] = {0.f, 0.f, 0.f, 0.f};
#pragma unroll
        for (int i = 0; i < 16; i++) {
            float4 kv = kr[i];
#pragma unroll
            for (int ci = 0; ci < 4; ci++) {
                float4 qv = *(float4*)&qs[ci * 64 + i * 4];
                a[ci] += kv.x * qv.x + kv.y * qv.y + kv.z * qv.z + kv.w * qv.w;
            }
        }
#pragma unroll
        for (int ci = 0; ci < 4; ci++) {
            float sa = a[ci] * 0.125f;
            scb[ci * SCBW + s] = sa;
            lmax[ci] = fmaxf(lmax[ci], sa);
        }
    }
#pragma unroll
    for (int ci = 0; ci < 4; ci++) {
#pragma unroll
        for (int o = 16; o > 0; o >>= 1)
            lmax[ci] = fmaxf(lmax[ci], __shfl_xor_sync(0xffffffffu, lmax[ci], o));
        if (lane == 0) red[ci][w] = lmax[ci];
    }
    __syncthreads();
    float gmaxv[4];
#pragma unroll
    for (int ci = 0; ci < 4; ci++) {
        float m = red[ci][0];
#pragma unroll
        for (int i = 1; i < 8; i++) m = fmaxf(m, red[ci][i]);
        gmaxv[ci] = m;
    }
    __syncthreads();

    float lsum[4] = {0.f, 0.f, 0.f, 0.f};
    for (int s = tid; s < nk; s += 256) {
#pragma unroll
        for (int ci = 0; ci < 4; ci++) {
            float p = __expf(scb[ci * SCBW + s] - gmaxv[ci]);
            scb[ci * SCBW + s] = p;
            lsum[ci] += p;
        }
    }
#pragma unroll
    for (int ci = 0; ci < 4; ci++) {
#pragma unroll
        for (int o = 16; o > 0; o >>= 1)
            lsum[ci] += __shfl_xor_sync(0xffffffffu, lsum[ci], o);
        if (lane == 0) red[ci][w] = lsum[ci];
    }
    __syncthreads();
    if (tid < 4) {
        float ssum = 0.f;
#pragma unroll
        for (int i = 0; i < 8; i++) ssum += red[tid][i];
        gs[tid] = ssum;
        gm[tid] = gmaxv[tid];
    }

    int sl = tid >> 2, dcc = tid & 3, dof = dcc * 16;
    float acc[4][16];
#pragma unroll
    for (int ci = 0; ci < 4; ci++)
#pragma unroll
        for (int dd = 0; dd < 16; dd++) acc[ci][dd] = 0.f;

    for (int s = sl; s < nk; s += 64) {
        float p[4];
#pragma unroll
        for (int ci = 0; ci < 4; ci++) p[ci] = scb[ci * SCBW + s];
        const float* vr = Vb + (size_t)(k0 + s) * 64 + dof;
        float vf[16];
#pragma unroll
        for (int i = 0; i < 4; i++) *(float4*)&vf[i * 4] = *(const float4*)&vr[i * 4];
#pragma unroll
        for (int dd = 0; dd < 16; dd++) {
            float vv = vf[dd];
            acc[0][dd] = fmaf(p[0], vv, acc[0][dd]);
            acc[1][dd] = fmaf(p[1], vv, acc[1][dd]);
            acc[2][dd] = fmaf(p[2], vv, acc[2][dd]);
            acc[3][dd] = fmaf(p[3], vv, acc[3][dd]);
        }
    }
#pragma unroll
    for (int o = 4; o <= 16; o <<= 1)
#pragma unroll
        for (int ci = 0; ci < 4; ci++)
#pragma unroll
            for (int dd = 0; dd < 16; dd++)
                acc[ci][dd] += __shfl_xor_sync(0xffffffffu, acc[ci][dd], o);

    if ((lane & 28) == 0) {
#pragma unroll
        for (int ci = 0; ci < 4; ci++)
#pragma unroll
            for (int dd = 0; dd < 16; dd++)
                osum[w][ci][dof + dd] = acc[ci][dd];
    }
    __syncthreads();

    {
        int ci = tid >> 6, d = tid & 63;
        float v = 0.f;
#pragma unroll
        for (int i = 0; i < 8; i++) v += osum[i][ci][d];
        float* dst = &g_clsp[((size_t)(h * 4 + ci) * NCHUNK + chunk) * 66];
        dst[2 + d] = v;
        if (d == 0) { dst[0] = gm[ci]; dst[1] = gs[ci]; }
    }
}

__global__ void cls_combine_kernel() {    // grid 8 x 256: one thread per (hc, d)
    int idx = blockIdx.x * 256 + threadIdx.x;
    int hc = idx >> 6;
    int h = hc >> 2, ci = hc & 3;
    int d = idx & 63;
    const float* base = &g_clsp[(size_t)hc * NCHUNK * 66];
    float M = -INFINITY;
#pragma unroll
    for (int c = 0; c < NCHUNK; c++) M = fmaxf(M, base[c * 66]);
    float S = 0.f, A = 0.f;
#pragma unroll
    for (int c = 0; c < NCHUNK; c++) {
        float w = __expf(base[c * 66] - M);
        S = fmaf(base[c * 66 + 1], w, S);
        A = fmaf(base[c * 66 + 2 + d], w, A);
    }
    g_af[(size_t)ci * 512 + h * 64 + d] = __float2half(A / S);
}

// ---------------------------------------------------------------------------
// Patch attention on tensor cores, band-reduced: per m-tile only 6 k-tiles
// (5 window tiles rows wm..wm+79 + 1 cls tile). 8 warps = 4 m-tiles x 2 halves
// (wh=0: window tiles 0-2; wh=1: window tiles 3-4 + cls tile).
// ---------------------------------------------------------------------------
#define PST 72
#define SQ_E (64 * PST)
#define SK_E (144 * PST)
#define PATCH_SMEM ((SQ_E + 2 * SK_E) * 2 + 128 * 4 + 128 * 4 + 4 * 16 * 66 * 4)

__launch_bounds__(256)
__global__ void patch_attn_kernel() {
    __half* sQ = (__half*)dynsm;
    __half* sK = sQ + SQ_E;
    __half* sV = sK + SK_E;
    float* hm = (float*)(dynsm + (SQ_E + 2 * SK_E) * 2);
    float* hs = hm + 128;
    float* redb = hs + 128;

    int h = blockIdx.y;
    int l0 = blockIdx.x * 64;
    int tid = threadIdx.x;

    const float* Qb = &g_qkv[(size_t)h * S_TOT * 64];
    const float* Kb = &g_qkv[(size_t)(8 + h) * S_TOT * 64];
    const float* Vb = &g_qkv[(size_t)(16 + h) * S_TOT * 64];

    for (int i = tid; i < 64 * 8; i += 256) {
        int r = i >> 3, c8 = (i & 7) * 8;
        const float* src = &Qb[(size_t)(NUM_CLS + l0 + r) * 64 + c8];
        float4 a = *(const float4*)src;
        float4 b = *(const float4*)(src + 4);
        uint4 pk = make_uint4(packf16(a.x * 0.125f, a.y * 0.125f),
                              packf16(a.z * 0.125f, a.w * 0.125f),
                              packf16(b.x * 0.125f, b.y * 0.125f),
                              packf16(b.z * 0.125f, b.w * 0.125f));
        *(uint4*)&sQ[r * PST + c8] = pk;
    }
    // slab: rows 0..127 window, 128..131 cls, 132..143 zero
    for (int i = tid; i < 144 * 8; i += 256) {
        int r = i >> 3, c8 = (i & 7) * 8;
        float4 ka = make_float4(0.f, 0.f, 0.f, 0.f), kb = ka, va = ka, vb = ka;
        if (r < 128) {
            int kp = l0 - WIN + r;
            if (kp >= 0 && kp < L_PAT) {
                const float* ks = &Kb[(size_t)(NUM_CLS + kp) * 64 + c8];
                const float* vs = &Vb[(size_t)(NUM_CLS + kp) * 64 + c8];
                ka = *(const float4*)ks; kb = *(const float4*)(ks + 4);
                va = *(const float4*)vs; vb = *(const float4*)(vs + 4);
            }
        } else if (r < 132) {
            const float* ks = &Kb[(size_t)(r - 128) * 64 + c8];
            const float* vs = &Vb[(size_t)(r - 128) * 64 + c8];
            ka = *(const float4*)ks; kb = *(const float4*)(ks + 4);
            va = *(const float4*)vs; vb = *(const float4*)(vs + 4);
        }
        *(uint4*)&sK[r * PST + c8] = make_uint4(packf16(ka.x, ka.y), packf16(ka.z, ka.w),
                                                packf16(kb.x, kb.y), packf16(kb.z, kb.w));
        *(uint4*)&sV[r * PST + c8] = make_uint4(packf16(va.x, va.y), packf16(va.z, va.w),
                                                packf16(vb.x, vb.y), packf16(vb.z, vb.w));
    }
    __syncthreads();

    const int wid = tid >> 5;
    const int lane = tid & 31;
    const int wm = (wid >> 1) * 16;       // m-tile base
    const int wh = wid & 1;               // tile-half
    const int lrow = lane & 15;
    const int lcol = (lane >> 4) * 8;
    const int gid = lane >> 2;
    const int tig = lane & 3;

    const uint32_t sQb = smem_u32(sQ);
    const uint32_t sKb = smem_u32(sK);
    const uint32_t sVb = smem_u32(sV);

    // per-warp tile ids: wh*3 + {0,1,2}; tile t<5 -> window rows wm+t*16; t==5 -> cls rows 128
    int rbase[3];
#pragma unroll
    for (int ti = 0; ti < 3; ti++) {
        int t = wh * 3 + ti;
        rbase[ti] = (t < 5) ? (wm + t * 16) : 128;
    }

    // ---- QK^T ----
    float sf[3][2][4];
#pragma unroll
    for (int g = 0; g < 3; g++)
#pragma unroll
        for (int s = 0; s < 2; s++)
#pragma unroll
            for (int r = 0; r < 4; r++) sf[g][s][r] = 0.f;

#pragma unroll
    for (int kt = 0; kt < 4; kt++) {
        uint32_t af[4];
        ldm_x4(af, sQb + ((wm + lrow) * PST + kt * 16 + lcol) * 2);
#pragma unroll
        for (int g = 0; g < 3; g++) {
            uint32_t bf[4];
            ldm_x4(bf, sKb + ((rbase[g] + lrow) * PST + kt * 16 + lcol) * 2);
            mma_h(sf[g][0], af, bf[0], bf[2]);
            mma_h(sf[g][1], af, bf[1], bf[3]);
        }
    }

    // ---- mask + softmax on fragments ----
    const int row0 = wm + gid;
    const int row1 = row0 + 8;
    float mx0 = -INFINITY, mx1 = -INFINITY;
#pragma unroll
    for (int g = 0; g < 3; g++) {
        int t = wh * 3 + g;
#pragma unroll
        for (int s = 0; s < 2; s++)
#pragma unroll
            for (int j = 0; j < 2; j++) {
                int cc = s * 8 + tig * 2 + j;
                bool v0, v1;
                if (t < 5) {
                    int r = wm + t * 16 + cc;          // window row
                    int pos = l0 - WIN + r;
                    bool bok = (pos >= 0) && (pos < L_PAT);
                    v0 = bok && (r >= row0) && (r <= row0 + 64);
                    v1 = bok && (r >= row1) && (r <= row1 + 64);
                } else {
                    v0 = v1 = (cc < 4);
                }
                float a0 = v0 ? sf[g][s][j] : -1e30f;
                float a1 = v1 ? sf[g][s][j + 2] : -1e30f;
                sf[g][s][j] = a0;
                sf[g][s][j + 2] = a1;
                mx0 = fmaxf(mx0, a0);
                mx1 = fmaxf(mx1, a1);
            }
    }
    mx0 = fmaxf(mx0, __shfl_xor_sync(0xffffffffu, mx0, 1));
    mx0 = fmaxf(mx0, __shfl_xor_sync(0xffffffffu, mx0, 2));
    mx1 = fmaxf(mx1, __shfl_xor_sync(0xffffffffu, mx1, 1));
    mx1 = fmaxf(mx1, __shfl_xor_sync(0xffffffffu, mx1, 2));
    if (tig == 0) {
        hm[row0 * 2 + wh] = mx0;
        hm[row1 * 2 + wh] = mx1;
    }
    __syncthreads();
    float M0 = fmaxf(hm[row0 * 2], hm[row0 * 2 + 1]);
    float M1 = fmaxf(hm[row1 * 2], hm[row1 * 2 + 1]);

    float sum0 = 0.f, sum1 = 0.f;
#pragma unroll
    for (int g = 0; g < 3; g++)
#pragma unroll
        for (int s = 0; s < 2; s++) {
            float p0 = fexp(sf[g][s][0] - M0);
            float p1 = fexp(sf[g][s][1] - M0);
            float p2 = fexp(sf[g][s][2] - M1);
            float p3 = fexp(sf[g][s][3] - M1);
            sf[g][s][0] = p0; sf[g][s][1] = p1;
            sf[g][s][2] = p2; sf[g][s][3] = p3;
            sum0 += p0 + p1;
            sum1 += p2 + p3;
        }
    sum0 += __shfl_xor_sync(0xffffffffu, sum0, 1);
    sum0 += __shfl_xor_sync(0xffffffffu, sum0, 2);
    sum1 += __shfl_xor_sync(0xffffffffu, sum1, 1);
    sum1 += __shfl_xor_sync(0xffffffffu, sum1, 2);
    if (tig == 0) {
        hs[row0 * 2 + wh] = sum0;
        hs[row1 * 2 + wh] = sum1;
    }
    __syncthreads();
    float inv0 = 1.0f / (hs[row0 * 2] + hs[row0 * 2 + 1]);
    float inv1 = 1.0f / (hs[row1 * 2] + hs[row1 * 2 + 1]);

    // ---- P fp16 A-fragments ----
    uint32_t PhA[3][4];
#pragma unroll
    for (int kt = 0; kt < 3; kt++) {
#pragma unroll
        for (int s = 0; s < 2; s++) {
            PhA[kt][0 + s * 2] = packf16(sf[kt][s][0] * inv0, sf[kt][s][1] * inv0);
            PhA[kt][1 + s * 2] = packf16(sf[kt][s][2] * inv1, sf[kt][s][3] * inv1);
        }
    }

    // ---- PV ----
    float of[8][4];
#pragma unroll
    for (int i = 0; i < 8; i++)
#pragma unroll
        for (int r = 0; r < 4; r++) of[i][r] = 0.f;

#pragma unroll
    for (int dt2 = 0; dt2 < 4; dt2++) {
#pragma unroll
        for (int kt = 0; kt < 3; kt++) {
            uint32_t vb[4];
            ldm_x4t(vb, sVb + ((rbase[kt] + lrow) * PST + dt2 * 16 + lcol) * 2);
            mma_h(of[2 * dt2 + 0], PhA[kt], vb[0], vb[1]);
            mma_h(of[2 * dt2 + 1], PhA[kt], vb[2], vb[3]);
        }
    }

    // ---- cross-half reduce + write fp16 ----
    float* rb = redb + (wm >> 4) * 16 * 66;
    if (wh == 1) {
#pragma unroll
        for (int dt = 0; dt < 8; dt++) {
            int d = dt * 8 + tig * 2;
            *(float2*)&rb[gid * 66 + d] = make_float2(of[dt][0], of[dt][1]);
            *(float2*)&rb[(gid + 8) * 66 + d] = make_float2(of[dt][2], of[dt][3]);
        }
    }
    __syncthreads();
    if (wh == 0) {
#pragma unroll
        for (int dt = 0; dt < 8; dt++) {
            int d = dt * 8 + tig * 2;
            float2 r0 = *(float2*)&rb[gid * 66 + d];
            float2 r1 = *(float2*)&rb[(gid + 8) * 66 + d];
            int grow0 = NUM_CLS + l0 + row0;
            int grow1 = NUM_CLS + l0 + row1;
            *(uint32_t*)&g_af[(size_t)grow0 * 512 + h * 64 + d] =
                packf16(of[dt][0] + r0.x, of[dt][1] + r0.y);
            *(uint32_t*)&g_af[(size_t)grow1 * 512 + h * 64 + d] =
                packf16(of[dt][2] + r1.x, of[dt][3] + r1.y);
        }
    }
}

// ---------------------------------------------------------------------------
extern "C" void kernel_launch(void* const* d_in, const int* in_sizes, int n_in,
                              void* d_out, int out_size) {
    const float* x      = (const float*)d_in[0];
    const float* coords = (const float*)d_in[1];
    const float* w_qkv  = (const float*)d_in[2];
    const float* b_qkv  = (const float*)d_in[3];
    const float* w_out  = (const float*)d_in[4];
    const float* b_out  = (const float*)d_in[5];
    float* out = (float*)d_out;

    __half *xf, *af, *wqf, *wof;
    cudaGetSymbolAddress((void**)&xf, g_xf);
    cudaGetSymbolAddress((void**)&af, g_af);
    cudaGetSymbolAddress((void**)&wqf, g_wqf);
    cudaGetSymbolAddress((void**)&wof, g_wof);

    cudaFuncSetAttribute(gemm_f16<0>, cudaFuncAttributeMaxDynamicSharedMemorySize, GEMM_SMEM);
    cudaFuncSetAttribute(gemm_f16<1>, cudaFuncAttributeMaxDynamicSharedMemorySize, GEMM_SMEM);
    cudaFuncSetAttribute(patch_attn_kernel, cudaFuncAttributeMaxDynamicSharedMemorySize, PATCH_SMEM);

    // 1. fused prep (converts + rope table)
    prep_kernel<<<NB_PREP, 256>>>(x, w_qkv, w_out, coords);

    // 2. QKV GEMM (rope fused) -> g_qkv scatter
    {
        dim3 grid(1536 / 128, (S_TOT + 127) / 128);
        gemm_f16<1><<<grid, 256, GEMM_SMEM>>>(xf, wqf, b_qkv, nullptr, S_TOT, 0);
    }
    // 3. CLS attention + combine
    {
        dim3 grid(8, NCHUNK);
        cls_part_kernel<<<grid, 256>>>();
        cls_combine_kernel<<<8, 256>>>();
    }
    // 4. Patch attention (band-reduced)
    {
        dim3 grid(L_PAT / 64, H_NUM);
        patch_attn_kernel<<<grid, 256, PATCH_SMEM>>>();
    }
    // 5. out projection
    {
        dim3 grid(512 / 128, (S_TOT + 127) / 128);
        gemm_f16<0><<<grid, 256, GEMM_SMEM>>>(af, wof, b_out, out, S_TOT, 512);
    }
}